// round 7
// baseline (speedup 1.0000x reference)
#include <cuda_runtime.h>
#include <cstddef>
#include <cstdint>

// ----------------------------------------------------------------------------
// Problem constants
// ----------------------------------------------------------------------------
#define NB 1024            // batch
#define R 116              // ROIs
#define RR (R * R)         // 13456
#define LAYERS 4
#define FEAT 2320          // R*4*(L+1)
#define HID 1024
#define EPS 1e-5f

#define STR 124            // smem tile row stride (floats)
#define REGF 15872         // floats per 128xSTR tile region

// down-sample partial slot layout
#define DP_E0 0            // edge l=0: 29696 slots
#define DP_E4 29696        // edge l=4: 29696 slots
#define DP_EF 59392        // edge l=1..3: 1024 slots each
#define DP_N0 62464        // node l=0: 928 slots
#define DP_N4 63392        // node l=4: 928 slots
#define DP_NF 64320        // node l=1..3: 1024 slots each
#define DPTOT 67392

// ----------------------------------------------------------------------------
// Device scratch (static allocation only)
// ----------------------------------------------------------------------------
__device__ __align__(16) float g_Z  [(size_t)NB * RR];
__device__ __align__(16) float g_Z1 [(size_t)NB * RR];
__device__ __align__(16) float g_X  [NB * R * 3];
__device__ __align__(16) float g_X1 [NB * R * 3];
__device__ __align__(16) float g_XZ [(size_t)NB * FEAT];
__device__ __align__(16) float g_H  [(size_t)NB * HID];
__device__ float g_ps [R * NB];     // edge BN partials
__device__ float g_pq [R * NB];
__device__ float g_psN[R * NB];     // node BN partials
__device__ float g_pqN[R * NB];
__device__ float g_scale [R],  g_shift [R];   // edge BN affine
__device__ float g_scaleN[R],  g_shiftN[R];   // node BN affine
__device__ float g_dpS[DPTOT], g_dpQ[DPTOT];  // down-sample partials
__device__ float g_dssArr[20];                // 10 segments x (scale, shift)

__device__ __forceinline__ float wsum(float v) {
#pragma unroll
    for (int o = 16; o; o >>= 1) v += __shfl_xor_sync(0xffffffffu, v, o);
    return v;
}

__device__ __forceinline__ float to_tf32(float x) {
    float y;
    asm("cvt.rna.tf32.f32 %0, %1;" : "=f"(y) : "f"(x));
    return y;
}

// mma.sync m16n8k8 tf32: d += a (16x8, row) * b (8x8, col)
__device__ __forceinline__ void mma8(float* d, const uint32_t* a, const uint32_t* b) {
    asm volatile(
        "mma.sync.aligned.m16n8k8.row.col.f32.tf32.tf32.f32 "
        "{%0,%1,%2,%3},{%4,%5,%6,%7},{%8,%9},{%0,%1,%2,%3};"
        : "+f"(d[0]), "+f"(d[1]), "+f"(d[2]), "+f"(d[3])
        : "r"(a[0]), "r"(a[1]), "r"(a[2]), "r"(a[3]), "r"(b[0]), "r"(b[1]));
}

// 128x128x120 NT GEMM over whole smem tiles, 16 warps, warp tile 32x32.
__device__ __forceinline__ void mm_loop(const float* __restrict__ sA,
                                        const float* __restrict__ sB,
                                        float (&acc)[2][4][4],
                                        int wm, int wn, int g, int tig) {
#pragma unroll
    for (int ks = 0; ks < 15; ks++) {
        const int k0 = ks * 8;
        uint32_t af[2][4], bf[4][2];
#pragma unroll
        for (int mt = 0; mt < 2; mt++) {
            const float* p0 = sA + (wm * 32 + mt * 16 + g) * STR + k0 + tig;
            af[mt][0] = __float_as_uint(p0[0]);
            af[mt][1] = __float_as_uint(p0[8 * STR]);
            af[mt][2] = __float_as_uint(p0[4]);
            af[mt][3] = __float_as_uint(p0[8 * STR + 4]);
        }
#pragma unroll
        for (int nt = 0; nt < 4; nt++) {
            const float* p0 = sB + (wn * 32 + nt * 8 + g) * STR + k0 + tig;
            bf[nt][0] = __float_as_uint(p0[0]);
            bf[nt][1] = __float_as_uint(p0[4]);
        }
#pragma unroll
        for (int mt = 0; mt < 2; mt++)
#pragma unroll
            for (int nt = 0; nt < 4; nt++)
                mma8(acc[mt][nt], af[mt], bf[nt]);
    }
}

// ----------------------------------------------------------------------------
// Mega layer kernel: one CTA per batch, 512 threads (16 warps, 4x4 grid).
// apply=1 (layers 1..3): prologue also does Z += relu(bn(Z1)),
// X += relu(bn(X1)), and emits down-edge/down-node features + partials.
// ----------------------------------------------------------------------------
#define SM_B1  (3 * REGF)          // ab2 (128)
#define SM_B2  (SM_B1 + 128)       // eb (128)
#define SM_KS  (SM_B2 + 128)       // Ks (352)
#define SM_XS  (SM_KS + 352)       // X rows (352)
#define SM_PS  (SM_XS + 352)       // stat partials (512)
#define SM_PQ  (SM_PS + 512)
#define SM_PA  (SM_PQ + 512)       // node partials 3 x 512
#define SM_TOTF (SM_PA + 1536)
#define SM_TOTB (SM_TOTF * 4)      // ~204 KB

#define LT 512                     // threads in k_layer

__global__ void __launch_bounds__(LT, 1)
k_layer(const float* __restrict__ aw2, const float* __restrict__ ab2,
        const float* __restrict__ aw1, const float* __restrict__ ab1,
        const float* __restrict__ ew,  const float* __restrict__ eb,
        const float* __restrict__ nw,  const float* __restrict__ nb_,
        const float* __restrict__ dew, const float* __restrict__ deb,
        const float* __restrict__ dnw, const float* __restrict__ dnb,
        int offE, int offN, int dpE, int dpN, int apply)
{
    extern __shared__ float sm[];
    float* sZ = sm;
    float* sM = sm + REGF;
    float* sW = sm + 2 * REGF;
    float* sb1 = sm + SM_B1;
    float* sb2 = sm + SM_B2;
    float* sKs = sm + SM_KS;
    float* sXs = sm + SM_XS;
    float* pS  = sm + SM_PS;
    float* pQ  = sm + SM_PQ;
    float* pA  = sm + SM_PA;

    const int tid = threadIdx.x;
    const int b = blockIdx.x;
    const int wid = tid >> 5, lane = tid & 31;
    const int wm = wid >> 2, wn = wid & 3;
    const int g = lane >> 2, tig = lane & 3;
    const float4 z4 = make_float4(0.f, 0.f, 0.f, 0.f);

    // ---- phase 0 ----
    if (tid < 128) {
        sb1[tid] = (tid < R) ? ab2[tid] : 0.f;
        sb2[tid] = (tid < R) ? eb[tid] : 0.f;
    }
    // zero pads: rows 116..127 (31 f4) + col 116 f4 (rows 0..115) for all 3 regions
    for (int idx = tid; idx < 3 * 372; idx += LT) {
        const int t = idx / 372, i2 = idx - t * 372;
        const int r = 116 + i2 / 31, c = (i2 - (i2 / 31) * 31) * 4;
        *(float4*)(sm + t * REGF + r * STR + c) = z4;
    }
    for (int idx = tid; idx < 3 * 116; idx += LT) {
        const int t = idx / 116, r = idx - t * 116;
        *(float4*)(sm + t * REGF + r * STR + 116) = z4;
    }
    // aw2 -> sW (tf32)
    for (int idx = tid; idx < 116 * 29; idx += LT) {
        const int r = idx / 29;
        const int c = (idx - r * 29) << 2;
        const float4 vw = *(const float4*)(aw2 + r * R + c);
        float* dw = sW + r * STR + c;
        dw[0] = to_tf32(vw.x); dw[1] = to_tf32(vw.y);
        dw[2] = to_tf32(vw.z); dw[3] = to_tf32(vw.w);
    }
    // Z -> sZ (tf32); if apply, also Z_new = Z + relu(bn(Z1)) -> gmem + sM fp32
    if (apply) {
        for (int idx = tid; idx < 116 * 29; idx += LT) {
            const int r = idx / 29;
            const int c = (idx - r * 29) << 2;
            const size_t go = ((size_t)b * R + r) * R + c;
            float4 v = *(const float4*)(g_Z + go);
            const float4 u = *(const float4*)(g_Z1 + go);
            const float sc = g_scale[r], sf = g_shift[r];
            v.x += fmaxf(fmaf(u.x, sc, sf), 0.f);
            v.y += fmaxf(fmaf(u.y, sc, sf), 0.f);
            v.z += fmaxf(fmaf(u.z, sc, sf), 0.f);
            v.w += fmaxf(fmaf(u.w, sc, sf), 0.f);
            *(float4*)(g_Z + go) = v;
            *(float4*)(sM + r * STR + c) = v;        // fp32 copy for the conv
            float* dz = sZ + r * STR + c;
            dz[0] = to_tf32(v.x); dz[1] = to_tf32(v.y);
            dz[2] = to_tf32(v.z); dz[3] = to_tf32(v.w);
        }
    } else {
        const float* Zb = g_Z + (size_t)b * RR;
        for (int idx = tid; idx < 116 * 29; idx += LT) {
            const int r = idx / 29;
            const int c = (idx - r * 29) << 2;
            const float4 vz = *(const float4*)(Zb + r * R + c);
            float* dz = sZ + r * STR + c;
            dz[0] = to_tf32(vz.x); dz[1] = to_tf32(vz.y);
            dz[2] = to_tf32(vz.z); dz[3] = to_tf32(vz.w);
        }
    }
    // node path update + Ks
    if (tid < R) {
        float y0, y1, y2;
        float* xp = g_X + (size_t)b * (R * 3) + tid * 3;
        if (apply) {
            const float scn = g_scaleN[tid], sfn = g_shiftN[tid];
            const float* up = g_X1 + (size_t)b * (R * 3) + tid * 3;
            y0 = xp[0] + fmaxf(fmaf(up[0], scn, sfn), 0.f);
            y1 = xp[1] + fmaxf(fmaf(up[1], scn, sfn), 0.f);
            y2 = xp[2] + fmaxf(fmaf(up[2], scn, sfn), 0.f);
            xp[0] = y0; xp[1] = y1; xp[2] = y2;
            const float f = fmaxf(fmaf(y0, dnw[0],
                             fmaf(y1, dnw[1], fmaf(y2, dnw[2], dnb[0]))), 0.f);
            g_XZ[(size_t)b * FEAT + offN + tid] = f;
            pA[tid] = f;
        } else {
            y0 = xp[0]; y1 = xp[1]; y2 = xp[2];
        }
        sXs[tid * 3 + 0] = y0; sXs[tid * 3 + 1] = y1; sXs[tid * 3 + 2] = y2;
#pragma unroll
        for (int o = 0; o < 3; o++)
            sKs[tid * 3 + o] = fmaf(aw1[o * 3 + 0], y0,
                                fmaf(aw1[o * 3 + 1], y1,
                                fmaf(aw1[o * 3 + 2], y2, ab1[o])));
    }
    __syncthreads();

    if (apply) {
        // down-edge conv from fp32 Z_new in sM: warp per row
        float w0[4], w1[4], w2[4];
#pragma unroll
        for (int d = 0; d < 4; d++) {
            const int e = 4 * lane + d;
            w1[d] = (e < 78) ? dew[e] : 0.f;
            w0[d] = (e < 39) ? dew[39 + e] : 0.f;
            w2[d] = (e >= 39 && e < 116) ? dew[e - 39] : 0.f;
        }
        const float debv = deb[0];
        for (int r = wid; r < R; r += 16) {
            float4 v = z4;
            if (lane < 29) v = *(const float4*)(sM + r * STR + 4 * lane);
            const float vv[4] = {v.x, v.y, v.z, v.w};
            float f0 = 0.f, f1 = 0.f, f2 = 0.f;
#pragma unroll
            for (int d = 0; d < 4; d++) {
                f1 = fmaf(vv[d], w1[d], f1);
                f0 = fmaf(vv[d], w0[d], f0);
                f2 = fmaf(vv[d], w2[d], f2);
            }
            f0 = wsum(f0); f1 = wsum(f1); f2 = wsum(f2);
            if (lane == 0) {
                f0 = fmaxf(f0 + debv, 0.f);
                f1 = fmaxf(f1 + debv, 0.f);
                f2 = fmaxf(f2 + debv, 0.f);
                float* dst = g_XZ + (size_t)b * FEAT + offE + r * 3;
                dst[0] = f1; dst[1] = f0; dst[2] = f2;   // order fixed below
                // NOTE: original ordering is (f0_win0, f1_win1, f2_win2) with
                // win0 = w[39..78) over z[0..39), win1 = w[0..78) over z[0..78),
                // win2 = w[0..77) over z[39..116). Keep reference order:
                dst[0] = f0; dst[1] = f1; dst[2] = f2;
                pS[r] = f0 + f1 + f2;
                pQ[r] = f0 * f0 + f1 * f1 + f2 * f2;
            }
        }
        __syncthreads();
        if (wid == 0) {
            float s = 0.f, q = 0.f;
            for (int r = lane; r < R; r += 32) { s += pS[r]; q += pQ[r]; }
            s = wsum(s); q = wsum(q);
            if (lane == 0) { g_dpS[dpE + b] = s; g_dpQ[dpE + b] = q; }
        } else if (wid == 1) {
            float s = 0.f, q = 0.f;
            for (int r = lane; r < R; r += 32) {
                const float f = pA[r];
                s += f; q = fmaf(f, f, q);
            }
            s = wsum(s); q = wsum(q);
            if (lane == 0) { g_dpS[dpN + b] = s; g_dpQ[dpN + b] = q; }
        }
    }

    float acc[2][4][4];
#pragma unroll
    for (int mt = 0; mt < 2; mt++)
#pragma unroll
        for (int nt = 0; nt < 4; nt++)
#pragma unroll
            for (int i = 0; i < 4; i++) acc[mt][nt][i] = 0.f;

    // ---- GEMM1: Mid1 = Z @ aw2^T ----
    mm_loop(sZ, sW, acc, wm, wn, g, tig);
    __syncthreads();

    // ---- intermediate 1: Mid1+ab2 -> sW ; att -> sM ----
#pragma unroll
    for (int mt = 0; mt < 2; mt++)
#pragma unroll
        for (int h = 0; h < 2; h++) {
            const int row = wm * 32 + mt * 16 + g + 8 * h;
#pragma unroll
            for (int nt = 0; nt < 4; nt++) {
                const int col = wn * 32 + nt * 8 + 2 * tig;
                if (col < 120) {
                    sW[row * STR + col]     = to_tf32(acc[mt][nt][2 * h] + sb1[col]);
                    sW[row * STR + col + 1] = to_tf32(acc[mt][nt][2 * h + 1] + sb1[col + 1]);
                }
            }
        }
    // attention rows: one warp per row n
    for (int n = wid; n < R; n += 16) {
        const float k0 = sKs[n * 3], k1 = sKs[n * 3 + 1], k2 = sKs[n * 3 + 2];
        float s[4];
        float mx = -3.0e38f;
#pragma unroll
        for (int it = 0; it < 4; it++) {
            const int m = it * 32 + lane;
            float v = -3.0e38f;
            if (m < R) v = k0 * sKs[m * 3] + k1 * sKs[m * 3 + 1] + k2 * sKs[m * 3 + 2];
            s[it] = v;
            mx = fmaxf(mx, v);
        }
#pragma unroll
        for (int o = 16; o; o >>= 1) mx = fmaxf(mx, __shfl_xor_sync(0xffffffffu, mx, o));
        float sum = 0.f, e[4];
#pragma unroll
        for (int it = 0; it < 4; it++) {
            const int m = it * 32 + lane;
            e[it] = (m < R) ? __expf(s[it] - mx) : 0.f;
            sum += e[it];
        }
        sum = wsum(sum);
        const float inv = 1.f / sum;
#pragma unroll
        for (int it = 0; it < 4; it++) {
            const int m = it * 32 + lane;
            if (m < R) sM[n * STR + m] = to_tf32(e[it] * inv);
        }
    }
    // re-zero sM pad cols 116..119 (fp32 Z copy may have left values there
    // only in pad area? cols 116..119 of sM were zeroed in phase 0 and the
    // fp32 copy wrote only cols < 116; attention wrote cols < 116. Safe.)
    __syncthreads();

#pragma unroll
    for (int mt = 0; mt < 2; mt++)
#pragma unroll
        for (int nt = 0; nt < 4; nt++)
#pragma unroll
            for (int i = 0; i < 4; i++) acc[mt][nt][i] = 0.f;

    // ---- GEMM2: S2 = Mid1 @ att^T ----
    mm_loop(sW, sM, acc, wm, wn, g, tig);
    __syncthreads();

    // ---- intermediate 2: S2 -> sM ; node partials ; Zt -> sW ; re-zero sW pads ----
#pragma unroll
    for (int mt = 0; mt < 2; mt++)
#pragma unroll
        for (int h = 0; h < 2; h++) {
            const int row = wm * 32 + mt * 16 + g + 8 * h;
            float a0 = 0.f, a1 = 0.f, a2 = 0.f;
#pragma unroll
            for (int nt = 0; nt < 4; nt++) {
                const int col = wn * 32 + nt * 8 + 2 * tig;
                const float v0 = acc[mt][nt][2 * h];
                const float v1 = acc[mt][nt][2 * h + 1];
                if (col < 120) {
                    sM[row * STR + col]     = to_tf32(v0);
                    sM[row * STR + col + 1] = to_tf32(v1);
                }
                if (row < R && col < R) {
                    a0 = fmaf(v0, sXs[col * 3 + 0], fmaf(v1, sXs[col * 3 + 3], a0));
                    a1 = fmaf(v0, sXs[col * 3 + 1], fmaf(v1, sXs[col * 3 + 4], a1));
                    a2 = fmaf(v0, sXs[col * 3 + 2], fmaf(v1, sXs[col * 3 + 5], a2));
                }
            }
            a0 += __shfl_xor_sync(0xffffffffu, a0, 1);
            a0 += __shfl_xor_sync(0xffffffffu, a0, 2);
            a1 += __shfl_xor_sync(0xffffffffu, a1, 1);
            a1 += __shfl_xor_sync(0xffffffffu, a1, 2);
            a2 += __shfl_xor_sync(0xffffffffu, a2, 1);
            a2 += __shfl_xor_sync(0xffffffffu, a2, 2);
            if (tig == 0) {
                pA[0 * 512 + wn * 128 + row] = a0;
                pA[1 * 512 + wn * 128 + row] = a1;
                pA[2 * 512 + wn * 128 + row] = a2;
            }
        }
    // Zt: transpose sZ -> sW (both already tf32)
    for (int idx = tid; idx < 116 * 29; idx += LT) {
        const int r = idx / 29;
        const int c = (idx - r * 29) << 2;
        const float4 v = *(const float4*)(sZ + r * STR + c);
        sW[(c + 0) * STR + r] = v.x;
        sW[(c + 1) * STR + r] = v.y;
        sW[(c + 2) * STR + r] = v.z;
        sW[(c + 3) * STR + r] = v.w;
    }
    // re-zero sW pads
    for (int idx = tid; idx < 372; idx += LT) {
        const int r = 116 + idx / 31, c = (idx - (idx / 31) * 31) * 4;
        *(float4*)(sW + r * STR + c) = z4;
    }
    for (int r = tid; r < 116; r += LT)
        *(float4*)(sW + r * STR + 116) = z4;
    __syncthreads();

#pragma unroll
    for (int mt = 0; mt < 2; mt++)
#pragma unroll
        for (int nt = 0; nt < 4; nt++)
#pragma unroll
            for (int i = 0; i < 4; i++) acc[mt][nt][i] = 0.f;

    // ---- GEMM3: T = S2 @ Zt^T ----
    mm_loop(sM, sW, acc, wm, wn, g, tig);
    __syncthreads();

    // ---- intermediate 3: T -> sM ; ew -> sW ----
#pragma unroll
    for (int mt = 0; mt < 2; mt++)
#pragma unroll
        for (int h = 0; h < 2; h++) {
            const int row = wm * 32 + mt * 16 + g + 8 * h;
#pragma unroll
            for (int nt = 0; nt < 4; nt++) {
                const int col = wn * 32 + nt * 8 + 2 * tig;
                if (col < 120) {
                    sM[row * STR + col]     = to_tf32(acc[mt][nt][2 * h]);
                    sM[row * STR + col + 1] = to_tf32(acc[mt][nt][2 * h + 1]);
                }
            }
        }
    for (int idx = tid; idx < 116 * 29; idx += LT) {
        const int r = idx / 29;
        const int c = (idx - r * 29) << 2;
        const float4 v = *(const float4*)(ew + r * R + c);
        float* d = sW + r * STR + c;
        d[0] = to_tf32(v.x); d[1] = to_tf32(v.y);
        d[2] = to_tf32(v.z); d[3] = to_tf32(v.w);
    }
    __syncthreads();

#pragma unroll
    for (int mt = 0; mt < 2; mt++)
#pragma unroll
        for (int nt = 0; nt < 4; nt++)
#pragma unroll
            for (int i = 0; i < 4; i++) acc[mt][nt][i] = 0.f;

    // ---- GEMM4: Z1 = T @ ew^T + eb ----
    mm_loop(sM, sW, acc, wm, wn, g, tig);

    // ---- epilogue: Z1 + edge stats ----
    float* Cb = g_Z1 + (size_t)b * RR;
#pragma unroll
    for (int mt = 0; mt < 2; mt++) {
#pragma unroll
        for (int h = 0; h < 2; h++) {
            const int row = wm * 32 + mt * 16 + g + 8 * h;
            float s = 0.f, q = 0.f;
#pragma unroll
            for (int nt = 0; nt < 4; nt++) {
                const int col = wn * 32 + nt * 8 + 2 * tig;
                if (col < R) {
                    const float v0 = acc[mt][nt][2 * h] + sb2[col];
                    const float v1 = acc[mt][nt][2 * h + 1] + sb2[col + 1];
                    if (row < R)
                        *(float2*)(Cb + (size_t)row * R + col) = make_float2(v0, v1);
                    s += v0 + v1;
                    q += v0 * v0 + v1 * v1;
                }
            }
            s += __shfl_xor_sync(0xffffffffu, s, 1);
            s += __shfl_xor_sync(0xffffffffu, s, 2);
            q += __shfl_xor_sync(0xffffffffu, q, 1);
            q += __shfl_xor_sync(0xffffffffu, q, 2);
            if (tig == 0) { pS[wn * 128 + row] = s; pQ[wn * 128 + row] = q; }
        }
    }
    __syncthreads();
    if (tid < R) {
        const float s = pS[tid] + pS[128 + tid] + pS[256 + tid] + pS[384 + tid];
        const float q = pQ[tid] + pQ[128 + tid] + pQ[256 + tid] + pQ[384 + tid];
        g_ps[tid * NB + b] = s;
        g_pq[tid * NB + b] = q;
    }
    // ---- node path finish: X1 = (S2 @ X) @ nw^T + nb, node stats ----
    if (tid < R) {
        const int n = tid;
        const float a0 = pA[0 * 512 + n] + pA[0 * 512 + 128 + n] +
                         pA[0 * 512 + 256 + n] + pA[0 * 512 + 384 + n];
        const float a1 = pA[1 * 512 + n] + pA[1 * 512 + 128 + n] +
                         pA[1 * 512 + 256 + n] + pA[1 * 512 + 384 + n];
        const float a2 = pA[2 * 512 + n] + pA[2 * 512 + 128 + n] +
                         pA[2 * 512 + 256 + n] + pA[2 * 512 + 384 + n];
        float ps = 0.f, pq = 0.f;
        float* dst = g_X1 + (size_t)b * (R * 3) + n * 3;
#pragma unroll
        for (int o = 0; o < 3; o++) {
            const float v = fmaf(nw[o * 3 + 0], a0,
                            fmaf(nw[o * 3 + 1], a1,
                            fmaf(nw[o * 3 + 2], a2, nb_[o])));
            dst[o] = v;
            ps += v;
            pq = fmaf(v, v, pq);
        }
        g_psN[n * NB + b] = ps;
        g_pqN[n * NB + b] = pq;
    }
}

// ----------------------------------------------------------------------------
// Both BN channel reductions in one launch. grid = 2R, block = 256.
// ----------------------------------------------------------------------------
__global__ void k_reduce_both(const float* __restrict__ geg, const float* __restrict__ geb,
                              const float* __restrict__ gng, const float* __restrict__ gnb) {
    const bool edge = blockIdx.x < R;
    const int n = edge ? blockIdx.x : blockIdx.x - R;
    const float* PS = edge ? g_ps : g_psN;
    const float* PQ = edge ? g_pq : g_pqN;
    float s = 0.f, q = 0.f;
    for (int b = threadIdx.x; b < NB; b += 256) {
        s += PS[n * NB + b];
        q += PQ[n * NB + b];
    }
    __shared__ float shs[8], shq[8];
    s = wsum(s); q = wsum(q);
    const int w = threadIdx.x >> 5, lane = threadIdx.x & 31;
    if (lane == 0) { shs[w] = s; shq[w] = q; }
    __syncthreads();
    if (w == 0) {
        s = (lane < 8) ? shs[lane] : 0.f;
        q = (lane < 8) ? shq[lane] : 0.f;
        s = wsum(s); q = wsum(q);
        if (lane == 0) {
            const float invcnt = edge ? (1.f / (float)(NB * R)) : (1.f / (float)(3 * NB));
            const float mean = s * invcnt;
            const float var = q * invcnt - mean * mean;
            const float rstd = rsqrtf(var + EPS);
            const float gg = edge ? geg[n] : gng[n];
            const float bb = edge ? geb[n] : gnb[n];
            const float sc = rstd * gg;
            if (edge) { g_scale[n] = sc;  g_shift[n] = bb - mean * sc; }
            else      { g_scaleN[n] = sc; g_shiftN[n] = bb - mean * sc; }
        }
    }
}

// ----------------------------------------------------------------------------
// Standalone apply+down: only l=0 (pass-through copy) and l=4 (final apply).
// grid = 29696 + 928, block = 128.
// ----------------------------------------------------------------------------
__global__ void k_apply_down(const float* __restrict__ dew, const float* __restrict__ deb,
                             const float* __restrict__ dnw, const float* __restrict__ dnb,
                             const float* __restrict__ srcZ, const float* __restrict__ srcX,
                             int offE, int offN, int dpE, int dpN, int apply) {
    __shared__ float sWt[78];
    __shared__ float sh[8];
    if (blockIdx.x < 29696) {
        // ---------------- edge ----------------
        if (threadIdx.x < 78) sWt[threadIdx.x] = dew[threadIdx.x];
        __syncthreads();
        const int wrp = threadIdx.x >> 5, lane = threadIdx.x & 31;
        const int rowid = blockIdx.x * 4 + wrp;
        const int b = rowid / R, n = rowid - b * R;
        float4 v = make_float4(0.f, 0.f, 0.f, 0.f);
        float* zrow = g_Z + (size_t)rowid * R;
        if (lane < 29) {
            if (apply) {
                v = *(float4*)(zrow + 4 * lane);
                const float4 u = *(const float4*)(g_Z1 + (size_t)rowid * R + 4 * lane);
                const float sc = g_scale[n], sf = g_shift[n];
                v.x += fmaxf(fmaf(u.x, sc, sf), 0.f);
                v.y += fmaxf(fmaf(u.y, sc, sf), 0.f);
                v.z += fmaxf(fmaf(u.z, sc, sf), 0.f);
                v.w += fmaxf(fmaf(u.w, sc, sf), 0.f);
                *(float4*)(zrow + 4 * lane) = v;
            } else {
                v = *(const float4*)(srcZ + (size_t)rowid * R + 4 * lane);
                *(float4*)(zrow + 4 * lane) = v;
            }
        }
        float f0 = 0.f, f1 = 0.f, f2 = 0.f;
        const float vv[4] = {v.x, v.y, v.z, v.w};
#pragma unroll
        for (int d = 0; d < 4; d++) {
            const int e = 4 * lane + d;
            if (e < 78) f1 = fmaf(vv[d], sWt[e], f1);
            if (e < 39) f0 = fmaf(vv[d], sWt[39 + e], f0);
            if (e >= 39 && e < 116) f2 = fmaf(vv[d], sWt[e - 39], f2);
        }
        f0 = wsum(f0); f1 = wsum(f1); f2 = wsum(f2);
        float s = 0.f, q = 0.f;
        if (lane == 0) {
            const float bb = deb[0];
            f0 = fmaxf(f0 + bb, 0.f);
            f1 = fmaxf(f1 + bb, 0.f);
            f2 = fmaxf(f2 + bb, 0.f);
            float* dst = g_XZ + (size_t)b * FEAT + offE + n * 3;
            dst[0] = f0; dst[1] = f1; dst[2] = f2;
            s = f0 + f1 + f2;
            q = f0 * f0 + f1 * f1 + f2 * f2;
            sh[wrp] = s; sh[4 + wrp] = q;
        }
        __syncthreads();
        if (threadIdx.x == 0) {
            g_dpS[dpE + blockIdx.x] = sh[0] + sh[1] + sh[2] + sh[3];
            g_dpQ[dpE + blockIdx.x] = sh[4] + sh[5] + sh[6] + sh[7];
        }
    } else {
        // ---------------- node ----------------
        const int bid = blockIdx.x - 29696;
        const int idx = bid * 128 + threadIdx.x;
        float* xp = g_X + (size_t)idx * 3;
        float x0, x1, x2;
        if (apply) {
            x0 = xp[0]; x1 = xp[1]; x2 = xp[2];
            const int n = idx % R;
            const float sc = g_scaleN[n], sf = g_shiftN[n];
            const float* up = g_X1 + (size_t)idx * 3;
            x0 += fmaxf(fmaf(up[0], sc, sf), 0.f);
            x1 += fmaxf(fmaf(up[1], sc, sf), 0.f);
            x2 += fmaxf(fmaf(up[2], sc, sf), 0.f);
            xp[0] = x0; xp[1] = x1; xp[2] = x2;
        } else {
            const float* sp = srcX + (size_t)idx * 3;
            x0 = sp[0]; x1 = sp[1]; x2 = sp[2];
            xp[0] = x0; xp[1] = x1; xp[2] = x2;
        }
        const float f = fmaxf(fmaf(x0, dnw[0], fmaf(x1, dnw[1], fmaf(x2, dnw[2], dnb[0]))), 0.f);
        const int b = idx / R, r = idx - (idx / R) * R;
        g_XZ[(size_t)b * FEAT + offN + r] = f;
        const float s = wsum(f);
        const float q = wsum(f * f);
        const int wr = threadIdx.x >> 5, lane = threadIdx.x & 31;
        if (lane == 0) { sh[wr] = s; sh[4 + wr] = q; }
        __syncthreads();
        if (threadIdx.x == 0) {
            g_dpS[dpN + bid] = sh[0] + sh[1] + sh[2] + sh[3];
            g_dpQ[dpN + bid] = sh[4] + sh[5] + sh[6] + sh[7];
        }
    }
}

// ----------------------------------------------------------------------------
// All 10 down-sample reductions at once. grid = 10, block = 1024.
// sgm 0..4 node l, 5..9 edge l-5.
// ----------------------------------------------------------------------------
__global__ void k_dreduce_all(const float* __restrict__ dng, const float* __restrict__ dnbe,
                              const float* __restrict__ deg, const float* __restrict__ debe) {
    const int sgm = blockIdx.x;
    const bool node = sgm < 5;
    const int l = node ? sgm : sgm - 5;
    int base, cnt;
    if (node) {
        if (l == 0)      { base = DP_N0; cnt = 928; }
        else if (l == 4) { base = DP_N4; cnt = 928; }
        else             { base = DP_NF + (l - 1) * 1024; cnt = 1024; }
    } else {
        if (l == 0)      { base = DP_E0; cnt = 29696; }
        else if (l == 4) { base = DP_E4; cnt = 29696; }
        else             { base = DP_EF + (l - 1) * 1024; cnt = 1024; }
    }
    const float invcnt = node ? (1.f / (float)(NB * R)) : (1.f / (float)(NB * R * 3));
    float s = 0.f, q = 0.f;
    for (int i = threadIdx.x; i < cnt; i += 1024) {
        s += g_dpS[base + i];
        q += g_dpQ[base + i];
    }
    __shared__ float shs[32], shq[32];
    s = wsum(s); q = wsum(q);
    const int w = threadIdx.x >> 5, lane = threadIdx.x & 31;
    if (lane == 0) { shs[w] = s; shq[w] = q; }
    __syncthreads();
    if (w == 0) {
        s = shs[lane]; q = shq[lane];
        s = wsum(s); q = wsum(q);
        if (lane == 0) {
            const float mean = s * invcnt;
            const float var = q * invcnt - mean * mean;
            const float rstd = rsqrtf(var + EPS);
            const float gg = node ? dng[l] : deg[l];
            const float bb = node ? dnbe[l] : debe[l];
            const float sc = rstd * gg;
            g_dssArr[2 * sgm]     = sc;
            g_dssArr[2 * sgm + 1] = bb - mean * sc;
        }
    }
}

// ----------------------------------------------------------------------------
// Classifier GEMM with slab normalization folded into the A-load.
// ----------------------------------------------------------------------------
__global__ void __launch_bounds__(256)
k_cls(const float* __restrict__ A, const float* __restrict__ Bm,
      const float* __restrict__ bias, float* __restrict__ C)
{
    __shared__ float sA[2][128 * 20];
    __shared__ float sB[2][64 * 20];
    __shared__ float sbc[64];
    const int tid = threadIdx.x;
    const int wid = tid >> 5, lane = tid & 31;
    const int wm = wid >> 1, wn = wid & 1;
    const int g = lane >> 2, tig = lane & 3;
    const int row0 = blockIdx.y * 128, col0 = blockIdx.x * 64;

    if (tid < 64) sbc[tid] = bias[col0 + tid];

    float4 pa0, pa1, pb;
    float fsc, fsh;
    const int ar0 = tid >> 2, ac0 = (tid & 3) << 2;
    const int ar1 = (tid + 256) >> 2, ac1 = ac0;
    const int br = tid >> 2, bc = (tid & 3) << 2;

    auto fetch = [&](int k0) {
        const int k = k0 + ac0;
        const int sgm = (k < 580) ? (k / 116) : (5 + (k - 580) / 348);
        fsc = g_dssArr[2 * sgm];
        fsh = g_dssArr[2 * sgm + 1];
        pa0 = *(const float4*)(A + (size_t)(row0 + ar0) * FEAT + k0 + ac0);
        pa1 = *(const float4*)(A + (size_t)(row0 + ar1) * FEAT + k0 + ac1);
        pb  = *(const float4*)(Bm + (size_t)(col0 + br) * FEAT + k0 + bc);
    };
    auto store = [&](int buf) {
        float* d0 = &sA[buf][ar0 * 20 + ac0];
        d0[0] = to_tf32(fmaf(pa0.x, fsc, fsh)); d0[1] = to_tf32(fmaf(pa0.y, fsc, fsh));
        d0[2] = to_tf32(fmaf(pa0.z, fsc, fsh)); d0[3] = to_tf32(fmaf(pa0.w, fsc, fsh));
        float* d1 = &sA[buf][ar1 * 20 + ac1];
        d1[0] = to_tf32(fmaf(pa1.x, fsc, fsh)); d1[1] = to_tf32(fmaf(pa1.y, fsc, fsh));
        d1[2] = to_tf32(fmaf(pa1.z, fsc, fsh)); d1[3] = to_tf32(fmaf(pa1.w, fsc, fsh));
        float* d2 = &sB[buf][br * 20 + bc];
        d2[0] = to_tf32(pb.x); d2[1] = to_tf32(pb.y);
        d2[2] = to_tf32(pb.z); d2[3] = to_tf32(pb.w);
    };

    float acc[2][4][4];
#pragma unroll
    for (int mt = 0; mt < 2; mt++)
#pragma unroll
        for (int nt = 0; nt < 4; nt++)
#pragma unroll
            for (int i = 0; i < 4; i++) acc[mt][nt][i] = 0.f;

    const int NS = FEAT / 16;
    fetch(0);
    store(0);
    __syncthreads();
    int buf = 0;
    for (int ks = 0; ks < NS; ks++) {
        if (ks + 1 < NS) fetch((ks + 1) * 16);
#pragma unroll
        for (int kk = 0; kk < 2; kk++) {
            const int k0 = kk * 8;
            uint32_t af[2][4], bf[4][2];
#pragma unroll
            for (int mt = 0; mt < 2; mt++) {
                const float* p0 = &sA[buf][(wm * 32 + mt * 16 + g) * 20 + k0 + tig];
                af[mt][0] = __float_as_uint(p0[0]);
                af[mt][1] = __float_as_uint(p0[8 * 20]);
                af[mt][2] = __float_as_uint(p0[4]);
                af[mt][3] = __float_as_uint(p0[8 * 20 + 4]);
            }
#pragma unroll
            for (int nt = 0; nt < 4; nt++) {
                const float* p0 = &sB[buf][(wn * 32 + nt * 8 + g) * 20 + k0 + tig];
                bf[nt][0] = __float_as_uint(p0[0]);
                bf[nt][1] = __float_as_uint(p0[4]);
            }
#pragma unroll
            for (int mt = 0; mt < 2; mt++)
#pragma unroll
                for (int nt = 0; nt < 4; nt++)
                    mma8(acc[mt][nt], af[mt], bf[nt]);
        }
        if (ks + 1 < NS) store(buf ^ 1);
        __syncthreads();
        buf ^= 1;
    }

#pragma unroll
    for (int mt = 0; mt < 2; mt++)
#pragma unroll
        for (int h = 0; h < 2; h++) {
            const int row = row0 + wm * 32 + mt * 16 + g + 8 * h;
#pragma unroll
            for (int nt = 0; nt < 4; nt++) {
                const int col = wn * 32 + nt * 8 + 2 * tig;
                const float v0 = fmaxf(acc[mt][nt][2 * h] + sbc[col], 0.f);
                const float v1 = fmaxf(acc[mt][nt][2 * h + 1] + sbc[col + 1], 0.f);
                *(float2*)(C + (size_t)row * HID + col0 + col) = make_float2(v0, v1);
            }
        }
}

__global__ void k_out(const float* __restrict__ cw2, const float* __restrict__ cb2,
                      float* __restrict__ out) {
    const int b = blockIdx.x;
    const float* h = g_H + (size_t)b * HID;
    float a0 = 0.f, a1 = 0.f;
    for (int j = threadIdx.x; j < HID; j += 128) {
        const float hv = h[j];
        a0 = fmaf(hv, cw2[j], a0);
        a1 = fmaf(hv, cw2[HID + j], a1);
    }
    a0 = wsum(a0);
    a1 = wsum(a1);
    __shared__ float sh[8];
    const int w = threadIdx.x >> 5, lane = threadIdx.x & 31;
    if (lane == 0) { sh[w] = a0; sh[4 + w] = a1; }
    __syncthreads();
    if (threadIdx.x == 0) {
        out[b * 2 + 0] = sh[0] + sh[1] + sh[2] + sh[3] + cb2[0];
        out[b * 2 + 1] = sh[4] + sh[5] + sh[6] + sh[7] + cb2[1];
    }
}

// ----------------------------------------------------------------------------
// Host orchestration (graph-capturable: kernel launches only)
// ----------------------------------------------------------------------------
extern "C" void kernel_launch(void* const* d_in, const int* in_sizes, int n_in,
                              void* d_out, int out_size) {
    const float* X_in  = (const float*)d_in[0];
    const float* Z_in  = (const float*)d_in[1];
    const float* aw1   = (const float*)d_in[2];
    const float* ab1   = (const float*)d_in[3];
    const float* aw2   = (const float*)d_in[4];
    const float* ab2   = (const float*)d_in[5];
    const float* nw    = (const float*)d_in[6];
    const float* nb    = (const float*)d_in[7];
    const float* ew    = (const float*)d_in[8];
    const float* eb    = (const float*)d_in[9];
    const float* gn_g  = (const float*)d_in[10];
    const float* gn_b  = (const float*)d_in[11];
    const float* ge_g  = (const float*)d_in[12];
    const float* ge_b  = (const float*)d_in[13];
    const float* dn_w  = (const float*)d_in[14];
    const float* dn_b  = (const float*)d_in[15];
    const float* dn_g  = (const float*)d_in[16];
    const float* dn_be = (const float*)d_in[17];
    const float* de_w  = (const float*)d_in[18];
    const float* de_b  = (const float*)d_in[19];
    const float* de_g  = (const float*)d_in[20];
    const float* de_be = (const float*)d_in[21];
    const float* cw1   = (const float*)d_in[22];
    const float* cb1   = (const float*)d_in[23];
    const float* cw2   = (const float*)d_in[24];
    const float* cb2   = (const float*)d_in[25];
    float* out = (float*)d_out;

    cudaFuncSetAttribute(k_layer, cudaFuncAttributeMaxDynamicSharedMemorySize, SM_TOTB);

    float *pXZ, *pH;
    cudaGetSymbolAddress((void**)&pXZ, g_XZ);
    cudaGetSymbolAddress((void**)&pH,  g_H);

    // layer-0 down-sample, fused with input pass-through copy
    k_apply_down<<<29696 + 928, 128>>>(de_w, de_b, dn_w, dn_b,
                                       Z_in, X_in,
                                       580, 0, DP_E0, DP_N0, 0);

    for (int i = 0; i < LAYERS; i++) {
        const int ap = (i > 0) ? 1 : 0;
        const int dpE = ap ? (DP_EF + (i - 1) * 1024) : 0;
        const int dpN = ap ? (DP_NF + (i - 1) * 1024) : 0;
        k_layer<<<NB, LT, SM_TOTB>>>(aw2 + (size_t)i * RR, ab2 + i * R,
                                     aw1 + 9 * i, ab1 + 3 * i,
                                     ew + (size_t)i * RR, eb + i * R,
                                     nw + 9 * i, nb + 3 * i,
                                     de_w + 78 * i, de_b + i,
                                     dn_w + 3 * i, dn_b + i,
                                     580 + i * 348, i * R, dpE, dpN, ap);
        k_reduce_both<<<2 * R, 256>>>(ge_g + i * R, ge_b + i * R,
                                      gn_g + i * R, gn_b + i * R);
    }

    // final apply + down-sample for l = 4
    k_apply_down<<<29696 + 928, 128>>>(de_w + 78 * 4, de_b + 4,
                                       dn_w + 3 * 4, dn_b + 4,
                                       nullptr, nullptr,
                                       580 + 4 * 348, 4 * R, DP_E4, DP_N4, 1);

    k_dreduce_all<<<10, 1024>>>(dn_g, dn_be, de_g, de_be);
    k_cls<<<dim3(HID / 64, NB / 128), 256>>>(pXZ, cw1, cb1, pH);
    k_out<<<NB, 128>>>(cw2, cb2, out);
}

// round 8
// speedup vs baseline: 1.0936x; 1.0936x over previous
#include <cuda_runtime.h>
#include <cstddef>
#include <cstdint>

// ----------------------------------------------------------------------------
// Problem constants
// ----------------------------------------------------------------------------
#define NB 1024            // batch
#define R 116              // ROIs
#define RR (R * R)         // 13456
#define LAYERS 4
#define FEAT 2320          // R*4*(L+1)
#define HID 1024
#define EPS 1e-5f

#define STR 120            // smem tile row stride (floats) — conflict-free LDS.64
#define REGF 15360         // floats per 128xSTR tile region

// down-sample partial slot layout (R6 scheme)
#define EDGET 148480       // 5 * 29696 edge partial slots
#define DPTOT 153120       // + 5 * 928 node slots

// ----------------------------------------------------------------------------
// Device scratch (static allocation only)
// ----------------------------------------------------------------------------
__device__ __align__(16) float g_Z  [(size_t)NB * RR];
__device__ __align__(16) float g_Z1 [(size_t)NB * RR];
__device__ __align__(16) float g_X  [NB * R * 3];
__device__ __align__(16) float g_X1 [NB * R * 3];
__device__ __align__(16) float g_XZ [(size_t)NB * FEAT];
__device__ __align__(16) float g_H  [(size_t)NB * HID];
__device__ float g_ps [R * NB];     // edge BN partials
__device__ float g_pq [R * NB];
__device__ float g_psN[R * NB];     // node BN partials
__device__ float g_pqN[R * NB];
__device__ float g_scale [R],  g_shift [R];   // edge BN affine
__device__ float g_scaleN[R],  g_shiftN[R];   // node BN affine
__device__ float g_dpS[DPTOT], g_dpQ[DPTOT];  // down-sample partials
__device__ float g_dssArr[20];                // 10 segments x (scale, shift)

__device__ __forceinline__ float wsum(float v) {
#pragma unroll
    for (int o = 16; o; o >>= 1) v += __shfl_xor_sync(0xffffffffu, v, o);
    return v;
}

__device__ __forceinline__ float to_tf32(float x) {
    float y;
    asm("cvt.rna.tf32.f32 %0, %1;" : "=f"(y) : "f"(x));
    return y;
}

// K-dimension permutation: logical k -> physical column.
// Within each 8-block: (0,1,2,3,4,5,6,7) -> (0,2,4,6,1,3,5,7).
// Fragment pair (k0+tig, k0+4+tig) lands at (k0+2*tig, k0+2*tig+1): one LDS.64.
__device__ __forceinline__ int pcol(int c) {
    return (c & ~7) | ((c & 3) << 1) | ((c >> 2) & 1);
}

// mma.sync m16n8k8 tf32: d += a (16x8, row) * b (8x8, col)
__device__ __forceinline__ void mma8(float* d, const uint32_t* a, const uint32_t* b) {
    asm volatile(
        "mma.sync.aligned.m16n8k8.row.col.f32.tf32.tf32.f32 "
        "{%0,%1,%2,%3},{%4,%5,%6,%7},{%8,%9},{%0,%1,%2,%3};"
        : "+f"(d[0]), "+f"(d[1]), "+f"(d[2]), "+f"(d[3])
        : "r"(a[0]), "r"(a[1]), "r"(a[2]), "r"(a[3]), "r"(b[0]), "r"(b[1]));
}

// 128x128x120 NT GEMM over whole permuted smem tiles, 16 warps, warp tile 32x32.
// All fragment loads are 64-bit (conflict-free with STR=120).
__device__ __forceinline__ void mm_loop(const float* __restrict__ sA,
                                        const float* __restrict__ sB,
                                        float (&acc)[2][4][4],
                                        int wm, int wn, int g, int tig) {
#pragma unroll
    for (int ks = 0; ks < 15; ks++) {
        const int k0 = ks * 8 + 2 * tig;
        uint32_t af[2][4], bf[4][2];
#pragma unroll
        for (int mt = 0; mt < 2; mt++) {
            const float2 v0 = *(const float2*)(sA + (wm * 32 + mt * 16 + g) * STR + k0);
            const float2 v1 = *(const float2*)(sA + (wm * 32 + mt * 16 + g + 8) * STR + k0);
            af[mt][0] = __float_as_uint(v0.x);
            af[mt][1] = __float_as_uint(v1.x);
            af[mt][2] = __float_as_uint(v0.y);
            af[mt][3] = __float_as_uint(v1.y);
        }
#pragma unroll
        for (int nt = 0; nt < 4; nt++) {
            const float2 v = *(const float2*)(sB + (wn * 32 + nt * 8 + g) * STR + k0);
            bf[nt][0] = __float_as_uint(v.x);
            bf[nt][1] = __float_as_uint(v.y);
        }
#pragma unroll
        for (int mt = 0; mt < 2; mt++)
#pragma unroll
            for (int nt = 0; nt < 4; nt++)
                mma8(acc[mt][nt], af[mt], bf[nt]);
    }
}

// ----------------------------------------------------------------------------
// Mega layer kernel: one CTA per batch, 512 threads (16 warps, 4x4 grid).
//   Mid1 = Z @ aw2^T + ab2 ; att = softmax(K^T K) (phase 0) ;
//   S2   = Mid1 @ att^T  (+ fused node path partials) ;
//   Et   = ew @ Z^T      (replaces T = S2 @ Zt — no smem transpose) ;
//   Z1   = S2 @ Et^T + eb (gmem, + edge-BN stats)
// Regions: R1 = Z -> Et ; R2 = aw2 -> Mid1 -> ew ; R3 = att -> S2.
// ----------------------------------------------------------------------------
#define SM_B1  (3 * REGF)          // ab2 (128)
#define SM_B2  (SM_B1 + 128)       // eb (128)
#define SM_KS  (SM_B2 + 128)       // Ks (352)
#define SM_XS  (SM_KS + 352)       // X rows (352)
#define SM_PS  (SM_XS + 352)       // stat partials (512)
#define SM_PQ  (SM_PS + 512)
#define SM_PA  (SM_PQ + 512)       // node partials 3 x 512
#define SM_TOTF (SM_PA + 1536)
#define SM_TOTB (SM_TOTF * 4)      // ~194 KB

#define LT 512                     // threads in k_layer

__global__ void __launch_bounds__(LT, 1)
k_layer(const float* __restrict__ aw2, const float* __restrict__ ab2,
        const float* __restrict__ aw1, const float* __restrict__ ab1,
        const float* __restrict__ ew,  const float* __restrict__ eb,
        const float* __restrict__ nw,  const float* __restrict__ nb_)
{
    extern __shared__ float sm[];
    float* sR1 = sm;                 // Z -> Et
    float* sR2 = sm + REGF;          // aw2 -> Mid1 -> ew
    float* sR3 = sm + 2 * REGF;      // att -> S2
    float* sb1 = sm + SM_B1;
    float* sb2 = sm + SM_B2;
    float* sKs = sm + SM_KS;
    float* sXs = sm + SM_XS;
    float* pS  = sm + SM_PS;
    float* pQ  = sm + SM_PQ;
    float* pA  = sm + SM_PA;

    const int tid = threadIdx.x;
    const int b = blockIdx.x;
    const int wid = tid >> 5, lane = tid & 31;
    const int wm = wid >> 2, wn = wid & 3;
    const int g = lane >> 2, tig = lane & 3;
    const float4 z4 = make_float4(0.f, 0.f, 0.f, 0.f);

    // ---- phase 0: biases, X/Ks, pads, Z & aw2 loads (permuted, tf32) ----
    if (tid < 128) {
        sb1[tid] = (tid < R) ? ab2[tid] : 0.f;
        sb2[tid] = (tid < R) ? eb[tid] : 0.f;
    }
    if (tid < R) {
        const float* xp = g_X + (size_t)b * (R * 3) + tid * 3;
        const float y0 = xp[0], y1 = xp[1], y2 = xp[2];
        sXs[tid * 3 + 0] = y0; sXs[tid * 3 + 1] = y1; sXs[tid * 3 + 2] = y2;
#pragma unroll
        for (int o = 0; o < 3; o++)
            sKs[tid * 3 + o] = fmaf(aw1[o * 3 + 0], y0,
                                fmaf(aw1[o * 3 + 1], y1,
                                fmaf(aw1[o * 3 + 2], y2, ab1[o])));
    }
    // zero pad rows 116..127 (30 f4 per row) for all 3 regions
    for (int idx = tid; idx < 3 * 12 * 30; idx += LT) {
        const int t = idx / 360, i2 = idx - t * 360;
        const int r = 116 + i2 / 30, c = (i2 - (i2 / 30) * 30) * 4;
        *(float4*)(sm + t * REGF + r * STR + c) = z4;
    }
    // zero pad logical cols 116..119 (phys 113,115,117,119) rows 0..115, all regions
    for (int idx = tid; idx < 3 * 116; idx += LT) {
        const int t = idx / 116, r = idx - t * 116;
        float* base = sm + t * REGF + r * STR;
        base[113] = 0.f; base[115] = 0.f; base[117] = 0.f; base[119] = 0.f;
    }
    // Z -> R1, aw2 -> R2 (permuted K, tf32)
    {
        const float* Zb = g_Z + (size_t)b * RR;
        for (int idx = tid; idx < 116 * 29; idx += LT) {
            const int r = idx / 29;
            const int c = (idx - r * 29) << 2;            // multiple of 4
            const int pb = (c & ~7) + ((c >> 2) & 1);     // phys base (step 2)
            const float4 vz = *(const float4*)(Zb + r * R + c);
            float* dz = sR1 + r * STR + pb;
            dz[0] = to_tf32(vz.x); dz[2] = to_tf32(vz.y);
            dz[4] = to_tf32(vz.z); dz[6] = to_tf32(vz.w);
            const float4 vw = *(const float4*)(aw2 + r * R + c);
            float* dw = sR2 + r * STR + pb;
            dw[0] = to_tf32(vw.x); dw[2] = to_tf32(vw.y);
            dw[4] = to_tf32(vw.z); dw[6] = to_tf32(vw.w);
        }
    }
    __syncthreads();

    // ---- attention -> R3 (permuted). No barrier needed before GEMM1. ----
    for (int n = wid; n < R; n += 16) {
        const float k0 = sKs[n * 3], k1 = sKs[n * 3 + 1], k2 = sKs[n * 3 + 2];
        float s[4];
        float mx = -3.0e38f;
#pragma unroll
        for (int it = 0; it < 4; it++) {
            const int m = it * 32 + lane;
            float v = -3.0e38f;
            if (m < R) v = k0 * sKs[m * 3] + k1 * sKs[m * 3 + 1] + k2 * sKs[m * 3 + 2];
            s[it] = v;
            mx = fmaxf(mx, v);
        }
#pragma unroll
        for (int o = 16; o; o >>= 1) mx = fmaxf(mx, __shfl_xor_sync(0xffffffffu, mx, o));
        float sum = 0.f, e[4];
#pragma unroll
        for (int it = 0; it < 4; it++) {
            const int m = it * 32 + lane;
            e[it] = (m < R) ? __expf(s[it] - mx) : 0.f;
            sum += e[it];
        }
        sum = wsum(sum);
        const float inv = 1.f / sum;
#pragma unroll
        for (int it = 0; it < 4; it++) {
            const int m = it * 32 + lane;
            if (m < R) sR3[n * STR + pcol(m)] = to_tf32(e[it] * inv);
        }
    }

    float acc[2][4][4];
#pragma unroll
    for (int mt = 0; mt < 2; mt++)
#pragma unroll
        for (int nt = 0; nt < 4; nt++)
#pragma unroll
            for (int i = 0; i < 4; i++) acc[mt][nt][i] = 0.f;

    // ---- GEMM1: Mid1 = Z @ aw2^T ----
    mm_loop(sR1, sR2, acc, wm, wn, g, tig);
    __syncthreads();

    // ---- Mid1 + ab2 -> R2 (permuted) ----
#pragma unroll
    for (int mt = 0; mt < 2; mt++)
#pragma unroll
        for (int h = 0; h < 2; h++) {
            const int row = wm * 32 + mt * 16 + g + 8 * h;
#pragma unroll
            for (int nt = 0; nt < 4; nt++) {
                const int col = wn * 32 + nt * 8 + 2 * tig;
                if (col < 120) {
                    sR2[row * STR + pcol(col)]     = to_tf32(acc[mt][nt][2 * h] + sb1[col]);
                    sR2[row * STR + pcol(col + 1)] = to_tf32(acc[mt][nt][2 * h + 1] + sb1[col + 1]);
                }
            }
        }
#pragma unroll
    for (int mt = 0; mt < 2; mt++)
#pragma unroll
        for (int nt = 0; nt < 4; nt++)
#pragma unroll
            for (int i = 0; i < 4; i++) acc[mt][nt][i] = 0.f;
    __syncthreads();

    // ---- GEMM3: S2 = Mid1 @ att^T ----
    mm_loop(sR2, sR3, acc, wm, wn, g, tig);
    __syncthreads();

    // ---- S2 -> R3 (permuted) + node partials ; ew -> R2 (permuted) ----
#pragma unroll
    for (int mt = 0; mt < 2; mt++)
#pragma unroll
        for (int h = 0; h < 2; h++) {
            const int row = wm * 32 + mt * 16 + g + 8 * h;
            float a0 = 0.f, a1 = 0.f, a2 = 0.f;
#pragma unroll
            for (int nt = 0; nt < 4; nt++) {
                const int col = wn * 32 + nt * 8 + 2 * tig;
                const float v0 = acc[mt][nt][2 * h];
                const float v1 = acc[mt][nt][2 * h + 1];
                if (col < 120) {
                    sR3[row * STR + pcol(col)]     = to_tf32(v0);
                    sR3[row * STR + pcol(col + 1)] = to_tf32(v1);
                }
                if (row < R && col < R) {
                    a0 = fmaf(v0, sXs[col * 3 + 0], fmaf(v1, sXs[col * 3 + 3], a0));
                    a1 = fmaf(v0, sXs[col * 3 + 1], fmaf(v1, sXs[col * 3 + 4], a1));
                    a2 = fmaf(v0, sXs[col * 3 + 2], fmaf(v1, sXs[col * 3 + 5], a2));
                }
            }
            a0 += __shfl_xor_sync(0xffffffffu, a0, 1);
            a0 += __shfl_xor_sync(0xffffffffu, a0, 2);
            a1 += __shfl_xor_sync(0xffffffffu, a1, 1);
            a1 += __shfl_xor_sync(0xffffffffu, a1, 2);
            a2 += __shfl_xor_sync(0xffffffffu, a2, 1);
            a2 += __shfl_xor_sync(0xffffffffu, a2, 2);
            if (tig == 0) {
                pA[0 * 512 + wn * 128 + row] = a0;
                pA[1 * 512 + wn * 128 + row] = a1;
                pA[2 * 512 + wn * 128 + row] = a2;
            }
        }
    for (int idx = tid; idx < 116 * 29; idx += LT) {
        const int r = idx / 29;
        const int c = (idx - r * 29) << 2;
        const int pb = (c & ~7) + ((c >> 2) & 1);
        const float4 v = *(const float4*)(ew + r * R + c);
        float* d = sR2 + r * STR + pb;
        d[0] = to_tf32(v.x); d[2] = to_tf32(v.y);
        d[4] = to_tf32(v.z); d[6] = to_tf32(v.w);
    }
#pragma unroll
    for (int mt = 0; mt < 2; mt++)
#pragma unroll
        for (int nt = 0; nt < 4; nt++)
#pragma unroll
            for (int i = 0; i < 4; i++) acc[mt][nt][i] = 0.f;
    __syncthreads();

    // ---- GEMM2: Et = ew @ Z^T ----
    mm_loop(sR2, sR1, acc, wm, wn, g, tig);
    __syncthreads();

    // ---- Et -> R1 (permuted) ----
#pragma unroll
    for (int mt = 0; mt < 2; mt++)
#pragma unroll
        for (int h = 0; h < 2; h++) {
            const int row = wm * 32 + mt * 16 + g + 8 * h;
#pragma unroll
            for (int nt = 0; nt < 4; nt++) {
                const int col = wn * 32 + nt * 8 + 2 * tig;
                if (col < 120) {
                    sR1[row * STR + pcol(col)]     = to_tf32(acc[mt][nt][2 * h]);
                    sR1[row * STR + pcol(col + 1)] = to_tf32(acc[mt][nt][2 * h + 1]);
                }
            }
        }
#pragma unroll
    for (int mt = 0; mt < 2; mt++)
#pragma unroll
        for (int nt = 0; nt < 4; nt++)
#pragma unroll
            for (int i = 0; i < 4; i++) acc[mt][nt][i] = 0.f;
    __syncthreads();

    // ---- GEMM4: Z1 = S2 @ Et^T + eb ----
    mm_loop(sR3, sR1, acc, wm, wn, g, tig);

    // ---- epilogue: Z1 + edge stats ----
    float* Cb = g_Z1 + (size_t)b * RR;
#pragma unroll
    for (int mt = 0; mt < 2; mt++) {
#pragma unroll
        for (int h = 0; h < 2; h++) {
            const int row = wm * 32 + mt * 16 + g + 8 * h;
            float s = 0.f, q = 0.f;
#pragma unroll
            for (int nt = 0; nt < 4; nt++) {
                const int col = wn * 32 + nt * 8 + 2 * tig;
                if (col < R) {
                    const float v0 = acc[mt][nt][2 * h] + sb2[col];
                    const float v1 = acc[mt][nt][2 * h + 1] + sb2[col + 1];
                    if (row < R)
                        *(float2*)(Cb + (size_t)row * R + col) = make_float2(v0, v1);
                    s += v0 + v1;
                    q += v0 * v0 + v1 * v1;
                }
            }
            s += __shfl_xor_sync(0xffffffffu, s, 1);
            s += __shfl_xor_sync(0xffffffffu, s, 2);
            q += __shfl_xor_sync(0xffffffffu, q, 1);
            q += __shfl_xor_sync(0xffffffffu, q, 2);
            if (tig == 0) { pS[wn * 128 + row] = s; pQ[wn * 128 + row] = q; }
        }
    }
    __syncthreads();
    if (tid < R) {
        const float s = pS[tid] + pS[128 + tid] + pS[256 + tid] + pS[384 + tid];
        const float q = pQ[tid] + pQ[128 + tid] + pQ[256 + tid] + pQ[384 + tid];
        g_ps[tid * NB + b] = s;
        g_pq[tid * NB + b] = q;
    }
    // ---- node path finish: X1 = (S2 @ X) @ nw^T + nb, node stats ----
    if (tid < R) {
        const int n = tid;
        const float a0 = pA[0 * 512 + n] + pA[0 * 512 + 128 + n] +
                         pA[0 * 512 + 256 + n] + pA[0 * 512 + 384 + n];
        const float a1 = pA[1 * 512 + n] + pA[1 * 512 + 128 + n] +
                         pA[1 * 512 + 256 + n] + pA[1 * 512 + 384 + n];
        const float a2 = pA[2 * 512 + n] + pA[2 * 512 + 128 + n] +
                         pA[2 * 512 + 256 + n] + pA[2 * 512 + 384 + n];
        float ps = 0.f, pq = 0.f;
        float* dst = g_X1 + (size_t)b * (R * 3) + n * 3;
#pragma unroll
        for (int o = 0; o < 3; o++) {
            const float v = fmaf(nw[o * 3 + 0], a0,
                            fmaf(nw[o * 3 + 1], a1,
                            fmaf(nw[o * 3 + 2], a2, nb_[o])));
            dst[o] = v;
            ps += v;
            pq = fmaf(v, v, pq);
        }
        g_psN[n * NB + b] = ps;
        g_pqN[n * NB + b] = pq;
    }
}

// ----------------------------------------------------------------------------
// Both BN channel reductions in one launch. grid = 2R, block = 256.
// ----------------------------------------------------------------------------
__global__ void k_reduce_both(const float* __restrict__ geg, const float* __restrict__ geb,
                              const float* __restrict__ gng, const float* __restrict__ gnb) {
    const bool edge = blockIdx.x < R;
    const int n = edge ? blockIdx.x : blockIdx.x - R;
    const float* PS = edge ? g_ps : g_psN;
    const float* PQ = edge ? g_pq : g_pqN;
    float s = 0.f, q = 0.f;
    for (int b = threadIdx.x; b < NB; b += 256) {
        s += PS[n * NB + b];
        q += PQ[n * NB + b];
    }
    __shared__ float shs[8], shq[8];
    s = wsum(s); q = wsum(q);
    const int w = threadIdx.x >> 5, lane = threadIdx.x & 31;
    if (lane == 0) { shs[w] = s; shq[w] = q; }
    __syncthreads();
    if (w == 0) {
        s = (lane < 8) ? shs[lane] : 0.f;
        q = (lane < 8) ? shq[lane] : 0.f;
        s = wsum(s); q = wsum(q);
        if (lane == 0) {
            const float invcnt = edge ? (1.f / (float)(NB * R)) : (1.f / (float)(3 * NB));
            const float mean = s * invcnt;
            const float var = q * invcnt - mean * mean;
            const float rstd = rsqrtf(var + EPS);
            const float gg = edge ? geg[n] : gng[n];
            const float bb = edge ? geb[n] : gnb[n];
            const float sc = rstd * gg;
            if (edge) { g_scale[n] = sc;  g_shift[n] = bb - mean * sc; }
            else      { g_scaleN[n] = sc; g_shiftN[n] = bb - mean * sc; }
        }
    }
}

// ----------------------------------------------------------------------------
// Combined: Z+=relu(bn(Z1)) & down-edge  /  X+=relu(bn(X1)) & down-node.
// apply==0: pass-through copy from srcZ/srcX into g_Z/g_X (layer 0).
// grid = 29696 + 928, block = 128.
// ----------------------------------------------------------------------------
__global__ void k_apply_down(const float* __restrict__ dew, const float* __restrict__ deb,
                             const float* __restrict__ dnw, const float* __restrict__ dnb,
                             const float* __restrict__ srcZ, const float* __restrict__ srcX,
                             int offE, int offN, int dpE, int dpN, int apply) {
    __shared__ float sWt[78];
    __shared__ float sh[8];
    if (blockIdx.x < 29696) {
        // ---------------- edge ----------------
        if (threadIdx.x < 78) sWt[threadIdx.x] = dew[threadIdx.x];
        __syncthreads();
        const int wrp = threadIdx.x >> 5, lane = threadIdx.x & 31;
        const int rowid = blockIdx.x * 4 + wrp;
        const int b = rowid / R, n = rowid - b * R;
        float4 v = make_float4(0.f, 0.f, 0.f, 0.f);
        float* zrow = g_Z + (size_t)rowid * R;
        if (lane < 29) {
            if (apply) {
                v = *(float4*)(zrow + 4 * lane);
                const float4 u = *(const float4*)(g_Z1 + (size_t)rowid * R + 4 * lane);
                const float sc = g_scale[n], sf = g_shift[n];
                v.x += fmaxf(fmaf(u.x, sc, sf), 0.f);
                v.y += fmaxf(fmaf(u.y, sc, sf), 0.f);
                v.z += fmaxf(fmaf(u.z, sc, sf), 0.f);
                v.w += fmaxf(fmaf(u.w, sc, sf), 0.f);
                *(float4*)(zrow + 4 * lane) = v;
            } else {
                v = *(const float4*)(srcZ + (size_t)rowid * R + 4 * lane);
                *(float4*)(zrow + 4 * lane) = v;
            }
        }
        float f0 = 0.f, f1 = 0.f, f2 = 0.f;
        const float vv[4] = {v.x, v.y, v.z, v.w};
#pragma unroll
        for (int d = 0; d < 4; d++) {
            const int e = 4 * lane + d;
            if (e < 78) f1 = fmaf(vv[d], sWt[e], f1);
            if (e < 39) f0 = fmaf(vv[d], sWt[39 + e], f0);
            if (e >= 39 && e < 116) f2 = fmaf(vv[d], sWt[e - 39], f2);
        }
        f0 = wsum(f0); f1 = wsum(f1); f2 = wsum(f2);
        float s = 0.f, q = 0.f;
        if (lane == 0) {
            const float bb = deb[0];
            f0 = fmaxf(f0 + bb, 0.f);
            f1 = fmaxf(f1 + bb, 0.f);
            f2 = fmaxf(f2 + bb, 0.f);
            float* dst = g_XZ + (size_t)b * FEAT + offE + n * 3;
            dst[0] = f0; dst[1] = f1; dst[2] = f2;
            s = f0 + f1 + f2;
            q = f0 * f0 + f1 * f1 + f2 * f2;
            sh[wrp] = s; sh[4 + wrp] = q;
        }
        __syncthreads();
        if (threadIdx.x == 0) {
            g_dpS[dpE + blockIdx.x] = sh[0] + sh[1] + sh[2] + sh[3];
            g_dpQ[dpE + blockIdx.x] = sh[4] + sh[5] + sh[6] + sh[7];
        }
    } else {
        // ---------------- node ----------------
        const int bid = blockIdx.x - 29696;
        const int idx = bid * 128 + threadIdx.x;
        float* xp = g_X + (size_t)idx * 3;
        float x0, x1, x2;
        if (apply) {
            x0 = xp[0]; x1 = xp[1]; x2 = xp[2];
            const int n = idx % R;
            const float sc = g_scaleN[n], sf = g_shiftN[n];
            const float* up = g_X1 + (size_t)idx * 3;
            x0 += fmaxf(fmaf(up[0], sc, sf), 0.f);
            x1 += fmaxf(fmaf(up[1], sc, sf), 0.f);
            x2 += fmaxf(fmaf(up[2], sc, sf), 0.f);
            xp[0] = x0; xp[1] = x1; xp[2] = x2;
        } else {
            const float* sp = srcX + (size_t)idx * 3;
            x0 = sp[0]; x1 = sp[1]; x2 = sp[2];
            xp[0] = x0; xp[1] = x1; xp[2] = x2;
        }
        const float f = fmaxf(fmaf(x0, dnw[0], fmaf(x1, dnw[1], fmaf(x2, dnw[2], dnb[0]))), 0.f);
        const int b = idx / R, r = idx - (idx / R) * R;
        g_XZ[(size_t)b * FEAT + offN + r] = f;
        const float s = wsum(f);
        const float q = wsum(f * f);
        const int wr = threadIdx.x >> 5, lane = threadIdx.x & 31;
        if (lane == 0) { sh[wr] = s; sh[4 + wr] = q; }
        __syncthreads();
        if (threadIdx.x == 0) {
            g_dpS[dpN + bid] = sh[0] + sh[1] + sh[2] + sh[3];
            g_dpQ[dpN + bid] = sh[4] + sh[5] + sh[6] + sh[7];
        }
    }
}

// ----------------------------------------------------------------------------
// All 10 down-sample reductions at once. grid = 10, block = 1024.
// ----------------------------------------------------------------------------
__global__ void k_dreduce_all(const float* __restrict__ dng, const float* __restrict__ dnbe,
                              const float* __restrict__ deg, const float* __restrict__ debe) {
    const int sgm = blockIdx.x;
    const bool node = sgm < 5;
    const int l = node ? sgm : sgm - 5;
    const int base = node ? (EDGET + l * 928) : (l * 29696);
    const int cnt = node ? 928 : 29696;
    const float invcnt = node ? (1.f / (float)(NB * R)) : (1.f / (float)(NB * R * 3));
    float s = 0.f, q = 0.f;
    for (int i = threadIdx.x; i < cnt; i += 1024) {
        s += g_dpS[base + i];
        q += g_dpQ[base + i];
    }
    __shared__ float shs[32], shq[32];
    s = wsum(s); q = wsum(q);
    const int w = threadIdx.x >> 5, lane = threadIdx.x & 31;
    if (lane == 0) { shs[w] = s; shq[w] = q; }
    __syncthreads();
    if (w == 0) {
        s = shs[lane]; q = shq[lane];
        s = wsum(s); q = wsum(q);
        if (lane == 0) {
            const float mean = s * invcnt;
            const float var = q * invcnt - mean * mean;
            const float rstd = rsqrtf(var + EPS);
            const float gg = node ? dng[l] : deg[l];
            const float bb = node ? dnbe[l] : debe[l];
            const float sc = rstd * gg;
            g_dssArr[2 * sgm]     = sc;
            g_dssArr[2 * sgm + 1] = bb - mean * sc;
        }
    }
}

// ----------------------------------------------------------------------------
// Classifier GEMM with slab normalization folded into the A-load.
// ----------------------------------------------------------------------------
__global__ void __launch_bounds__(256)
k_cls(const float* __restrict__ A, const float* __restrict__ Bm,
      const float* __restrict__ bias, float* __restrict__ C)
{
    __shared__ float sA[2][128 * 20];
    __shared__ float sB[2][64 * 20];
    __shared__ float sbc[64];
    const int tid = threadIdx.x;
    const int wid = tid >> 5, lane = tid & 31;
    const int wm = wid >> 1, wn = wid & 1;
    const int g = lane >> 2, tig = lane & 3;
    const int row0 = blockIdx.y * 128, col0 = blockIdx.x * 64;

    if (tid < 64) sbc[tid] = bias[col0 + tid];

    float4 pa0, pa1, pb;
    float fsc, fsh;
    const int ar0 = tid >> 2, ac0 = (tid & 3) << 2;
    const int ar1 = (tid + 256) >> 2, ac1 = ac0;
    const int br = tid >> 2, bc = (tid & 3) << 2;

    auto fetch = [&](int k0) {
        const int k = k0 + ac0;
        const int sgm = (k < 580) ? (k / 116) : (5 + (k - 580) / 348);
        fsc = g_dssArr[2 * sgm];
        fsh = g_dssArr[2 * sgm + 1];
        pa0 = *(const float4*)(A + (size_t)(row0 + ar0) * FEAT + k0 + ac0);
        pa1 = *(const float4*)(A + (size_t)(row0 + ar1) * FEAT + k0 + ac1);
        pb  = *(const float4*)(Bm + (size_t)(col0 + br) * FEAT + k0 + bc);
    };
    auto store = [&](int buf) {
        float* d0 = &sA[buf][ar0 * 20 + ac0];
        d0[0] = to_tf32(fmaf(pa0.x, fsc, fsh)); d0[1] = to_tf32(fmaf(pa0.y, fsc, fsh));
        d0[2] = to_tf32(fmaf(pa0.z, fsc, fsh)); d0[3] = to_tf32(fmaf(pa0.w, fsc, fsh));
        float* d1 = &sA[buf][ar1 * 20 + ac1];
        d1[0] = to_tf32(fmaf(pa1.x, fsc, fsh)); d1[1] = to_tf32(fmaf(pa1.y, fsc, fsh));
        d1[2] = to_tf32(fmaf(pa1.z, fsc, fsh)); d1[3] = to_tf32(fmaf(pa1.w, fsc, fsh));
        float* d2 = &sB[buf][br * 20 + bc];
        d2[0] = to_tf32(pb.x); d2[1] = to_tf32(pb.y);
        d2[2] = to_tf32(pb.z); d2[3] = to_tf32(pb.w);
    };

    float acc[2][4][4];
#pragma unroll
    for (int mt = 0; mt < 2; mt++)
#pragma unroll
        for (int nt = 0; nt < 4; nt++)
#pragma unroll
            for (int i = 0; i < 4; i++) acc[mt][nt][i] = 0.f;

    const int NS = FEAT / 16;
    fetch(0);
    store(0);
    __syncthreads();
    int buf = 0;
    for (int ks = 0; ks < NS; ks++) {
        if (ks + 1 < NS) fetch((ks + 1) * 16);
#pragma unroll
        for (int kk = 0; kk < 2; kk++) {
            const int k0 = kk * 8;
            uint32_t af[2][4], bf[4][2];
#pragma unroll
            for (int mt = 0; mt < 2; mt++) {
                const float* p0 = &sA[buf][(wm * 32 + mt * 16 + g) * 20 + k0 + tig];
                af[mt][0] = __float_as_uint(p0[0]);
                af[mt][1] = __float_as_uint(p0[8 * 20]);
                af[mt][2] = __float_as_uint(p0[4]);
                af[mt][3] = __float_as_uint(p0[8 * 20 + 4]);
            }
#pragma unroll
            for (int nt = 0; nt < 4; nt++) {
                const float* p0 = &sB[buf][(wn * 32 + nt * 8 + g) * 20 + k0 + tig];
                bf[nt][0] = __float_as_uint(p0[0]);
                bf[nt][1] = __float_as_uint(p0[4]);
            }
#pragma unroll
            for (int mt = 0; mt < 2; mt++)
#pragma unroll
                for (int nt = 0; nt < 4; nt++)
                    mma8(acc[mt][nt], af[mt], bf[nt]);
        }
        if (ks + 1 < NS) store(buf ^ 1);
        __syncthreads();
        buf ^= 1;
    }

#pragma unroll
    for (int mt = 0; mt < 2; mt++)
#pragma unroll
        for (int h = 0; h < 2; h++) {
            const int row = row0 + wm * 32 + mt * 16 + g + 8 * h;
#pragma unroll
            for (int nt = 0; nt < 4; nt++) {
                const int col = wn * 32 + nt * 8 + 2 * tig;
                const float v0 = fmaxf(acc[mt][nt][2 * h] + sbc[col], 0.f);
                const float v1 = fmaxf(acc[mt][nt][2 * h + 1] + sbc[col + 1], 0.f);
                *(float2*)(C + (size_t)row * HID + col0 + col) = make_float2(v0, v1);
            }
        }
}

__global__ void k_out(const float* __restrict__ cw2, const float* __restrict__ cb2,
                      float* __restrict__ out) {
    const int b = blockIdx.x;
    const float* h = g_H + (size_t)b * HID;
    float a0 = 0.f, a1 = 0.f;
    for (int j = threadIdx.x; j < HID; j += 128) {
        const float hv = h[j];
        a0 = fmaf(hv, cw2[j], a0);
        a1 = fmaf(hv, cw2[HID + j], a1);
    }
    a0 = wsum(a0);
    a1 = wsum(a1);
    __shared__ float sh[8];
    const int w = threadIdx.x >> 5, lane = threadIdx.x & 31;
    if (lane == 0) { sh[w] = a0; sh[4 + w] = a1; }
    __syncthreads();
    if (threadIdx.x == 0) {
        out[b * 2 + 0] = sh[0] + sh[1] + sh[2] + sh[3] + cb2[0];
        out[b * 2 + 1] = sh[4] + sh[5] + sh[6] + sh[7] + cb2[1];
    }
}

// ----------------------------------------------------------------------------
// Host orchestration (graph-capturable: kernel launches only)
// ----------------------------------------------------------------------------
extern "C" void kernel_launch(void* const* d_in, const int* in_sizes, int n_in,
                              void* d_out, int out_size) {
    const float* X_in  = (const float*)d_in[0];
    const float* Z_in  = (const float*)d_in[1];
    const float* aw1   = (const float*)d_in[2];
    const float* ab1   = (const float*)d_in[3];
    const float* aw2   = (const float*)d_in[4];
    const float* ab2   = (const float*)d_in[5];
    const float* nw    = (const float*)d_in[6];
    const float* nb    = (const float*)d_in[7];
    const float* ew    = (const float*)d_in[8];
    const float* eb    = (const float*)d_in[9];
    const float* gn_g  = (const float*)d_in[10];
    const float* gn_b  = (const float*)d_in[11];
    const float* ge_g  = (const float*)d_in[12];
    const float* ge_b  = (const float*)d_in[13];
    const float* dn_w  = (const float*)d_in[14];
    const float* dn_b  = (const float*)d_in[15];
    const float* dn_g  = (const float*)d_in[16];
    const float* dn_be = (const float*)d_in[17];
    const float* de_w  = (const float*)d_in[18];
    const float* de_b  = (const float*)d_in[19];
    const float* de_g  = (const float*)d_in[20];
    const float* de_be = (const float*)d_in[21];
    const float* cw1   = (const float*)d_in[22];
    const float* cb1   = (const float*)d_in[23];
    const float* cw2   = (const float*)d_in[24];
    const float* cb2   = (const float*)d_in[25];
    float* out = (float*)d_out;

    cudaFuncSetAttribute(k_layer, cudaFuncAttributeMaxDynamicSharedMemorySize, SM_TOTB);

    float *pXZ, *pH;
    cudaGetSymbolAddress((void**)&pXZ, g_XZ);
    cudaGetSymbolAddress((void**)&pH,  g_H);

    // layer-0 down-sample, fused with input pass-through copy
    k_apply_down<<<29696 + 928, 128>>>(de_w, de_b, dn_w, dn_b,
                                       Z_in, X_in,
                                       580, 0, 0, EDGET, 0);

    for (int i = 0; i < LAYERS; i++) {
        k_layer<<<NB, LT, SM_TOTB>>>(aw2 + (size_t)i * RR, ab2 + i * R,
                                     aw1 + 9 * i, ab1 + 3 * i,
                                     ew + (size_t)i * RR, eb + i * R,
                                     nw + 9 * i, nb + 3 * i);
        k_reduce_both<<<2 * R, 256>>>(ge_g + i * R, ge_b + i * R,
                                      gn_g + i * R, gn_b + i * R);
        const int l = i + 1;
        k_apply_down<<<29696 + 928, 128>>>(de_w + 78 * l, de_b + l,
                                           dn_w + 3 * l, dn_b + l,
                                           nullptr, nullptr,
                                           580 + l * 348, l * R,
                                           l * 29696, EDGET + l * 928, 1);
    }

    k_dreduce_all<<<10, 1024>>>(dn_g, dn_be, de_g, de_be);
    k_cls<<<dim3(HID / 64, NB / 128), 256>>>(pXZ, cw1, cb1, pH);
    k_out<<<NB, 128>>>(cw2, cb2, out);
}

// round 9
// speedup vs baseline: 1.1269x; 1.0305x over previous
#include <cuda_runtime.h>
#include <cstddef>
#include <cstdint>

// ----------------------------------------------------------------------------
// Problem constants
// ----------------------------------------------------------------------------
#define NB 1024            // batch
#define R 116              // ROIs
#define RR (R * R)         // 13456
#define LAYERS 4
#define FEAT 2320          // R*4*(L+1)
#define HID 1024
#define EPS 1e-5f

#define STR 132            // smem tile row stride (floats) — LDSM conflict-free
#define REGF 16896         // floats per 128xSTR tile region

// down-sample partial slot layout
#define EDGET 148480       // 5 * 29696 edge partial slots
#define DPTOT 153120       // + 5 * 928 node slots

// ----------------------------------------------------------------------------
// Device scratch (static allocation only)
// ----------------------------------------------------------------------------
__device__ __align__(16) float g_Z  [(size_t)NB * RR];
__device__ __align__(16) float g_Z1 [(size_t)NB * RR];
__device__ __align__(16) float g_X  [NB * R * 3];
__device__ __align__(16) float g_X1 [NB * R * 3];
__device__ __align__(16) float g_XZ [(size_t)NB * FEAT];
__device__ __align__(16) float g_H  [(size_t)NB * HID];
__device__ float g_ps [R * NB];     // edge BN partials
__device__ float g_pq [R * NB];
__device__ float g_psN[R * NB];     // node BN partials
__device__ float g_pqN[R * NB];
__device__ float g_scale [R],  g_shift [R];   // edge BN affine
__device__ float g_scaleN[R],  g_shiftN[R];   // node BN affine
__device__ float g_dpS[DPTOT], g_dpQ[DPTOT];  // down-sample partials
__device__ float g_dssArr[20];                // 10 segments x (scale, shift)

__device__ __forceinline__ float wsum(float v) {
#pragma unroll
    for (int o = 16; o; o >>= 1) v += __shfl_xor_sync(0xffffffffu, v, o);
    return v;
}

__device__ __forceinline__ float to_tf32(float x) {
    float y;
    asm("cvt.rna.tf32.f32 %0, %1;" : "=f"(y) : "f"(x));
    return y;
}

__device__ __forceinline__ uint32_t sptr(const void* p) {
    return (uint32_t)__cvta_generic_to_shared(p);
}

// ldmatrix x4: loads 4 8x8 b16 tiles (= tf32 fragments) from per-lane row addrs.
#define LDSM4(r0, r1, r2, r3, addr) \
    asm volatile("ldmatrix.sync.aligned.m8n8.x4.shared.b16 {%0,%1,%2,%3}, [%4];" \
                 : "=r"(r0), "=r"(r1), "=r"(r2), "=r"(r3) : "r"(addr))

// mma.sync m16n8k8 tf32: d += a (16x8, row) * b (8x8, col)
__device__ __forceinline__ void mma8(float* d, const uint32_t* a, const uint32_t* b) {
    asm volatile(
        "mma.sync.aligned.m16n8k8.row.col.f32.tf32.tf32.f32 "
        "{%0,%1,%2,%3},{%4,%5,%6,%7},{%8,%9},{%0,%1,%2,%3};"
        : "+f"(d[0]), "+f"(d[1]), "+f"(d[2]), "+f"(d[3])
        : "r"(a[0]), "r"(a[1]), "r"(a[2]), "r"(a[3]), "r"(b[0]), "r"(b[1]));
}

// 128x128x120 NT GEMM over whole smem tiles (stride STR), 16 warps, tile 32x32.
// Fragment loads via ldmatrix.x4: 4 LDSM + 8 MMA per k-step.
// aOff/bOff: per-lane byte offsets (precomputed in the caller):
//   aOff = ((lane&15)*STR + 4*(lane>>4)) * 4
//   bOff = ((8*(lane>>4) + (lane&7))*STR + 4*((lane>>3)&1)) * 4
__device__ __forceinline__ void mm_loop(const float* __restrict__ sA,
                                        const float* __restrict__ sB,
                                        float (&acc)[2][4][4],
                                        int wm, int wn,
                                        uint32_t aOff, uint32_t bOff) {
    const uint32_t a0b = sptr(sA) + (uint32_t)(wm * 32 * STR * 4) + aOff;
    const uint32_t a1b = a0b + 16 * STR * 4;
    const uint32_t b0b = sptr(sB) + (uint32_t)(wn * 32 * STR * 4) + bOff;
    const uint32_t b1b = b0b + 16 * STR * 4;
#pragma unroll
    for (int ks = 0; ks < 15; ks++) {
        const uint32_t off = ks * 32;       // 8 floats = 32 bytes per k-step
        uint32_t af[2][4], bf[4][2];
        LDSM4(af[0][0], af[0][1], af[0][2], af[0][3], a0b + off);
        LDSM4(af[1][0], af[1][1], af[1][2], af[1][3], a1b + off);
        LDSM4(bf[0][0], bf[0][1], bf[1][0], bf[1][1], b0b + off);
        LDSM4(bf[2][0], bf[2][1], bf[3][0], bf[3][1], b1b + off);
#pragma unroll
        for (int mt = 0; mt < 2; mt++)
#pragma unroll
            for (int nt = 0; nt < 4; nt++)
                mma8(acc[mt][nt], af[mt], bf[nt]);
    }
}

// ----------------------------------------------------------------------------
// Mega layer kernel: one CTA per batch, 512 threads (16 warps, 4x4 grid).
//   Mid1 = Z @ aw2^T + ab2 ; att = softmax(K^T K) (phase 0) ;
//   S2   = Mid1 @ att^T  (+ fused node path partials) ;
//   Et   = ew @ Z^T ;
//   Z1   = S2 @ Et^T + eb (gmem, + edge-BN stats)
// Regions: R1 = Z -> Et ; R2 = aw2 -> Mid1 -> ew ; R3 = att -> S2.
// ----------------------------------------------------------------------------
#define SM_B1  (3 * REGF)          // ab2 (128)
#define SM_B2  (SM_B1 + 128)       // eb (128)
#define SM_KS  (SM_B2 + 128)       // Ks (352)
#define SM_XS  (SM_KS + 352)       // X rows (352)
#define SM_PS  (SM_XS + 352)       // stat partials (512)
#define SM_PQ  (SM_PS + 512)
#define SM_PA  (SM_PQ + 512)       // node partials 3 x 512
#define SM_TOTF (SM_PA + 1536)
#define SM_TOTB (SM_TOTF * 4)      // ~212 KB

#define LT 512                     // threads in k_layer

__global__ void __launch_bounds__(LT, 1)
k_layer(const float* __restrict__ aw2, const float* __restrict__ ab2,
        const float* __restrict__ aw1, const float* __restrict__ ab1,
        const float* __restrict__ ew,  const float* __restrict__ eb,
        const float* __restrict__ nw,  const float* __restrict__ nb_)
{
    extern __shared__ float sm[];
    float* sR1 = sm;                 // Z -> Et
    float* sR2 = sm + REGF;          // aw2 -> Mid1 -> ew
    float* sR3 = sm + 2 * REGF;      // att -> S2
    float* sb1 = sm + SM_B1;
    float* sb2 = sm + SM_B2;
    float* sKs = sm + SM_KS;
    float* sXs = sm + SM_XS;
    float* pS  = sm + SM_PS;
    float* pQ  = sm + SM_PQ;
    float* pA  = sm + SM_PA;

    const int tid = threadIdx.x;
    const int b = blockIdx.x;
    const int wid = tid >> 5, lane = tid & 31;
    const int wm = wid >> 2, wn = wid & 3;
    const int g = lane >> 2, tig = lane & 3;
    const float4 z4 = make_float4(0.f, 0.f, 0.f, 0.f);

    // ldmatrix per-lane offsets (bytes)
    const uint32_t aOff = (uint32_t)((((lane & 15) * STR) + 4 * (lane >> 4)) * 4);
    const uint32_t bOff = (uint32_t)(((8 * (lane >> 4) + (lane & 7)) * STR +
                                      4 * ((lane >> 3) & 1)) * 4);

    // ---- phase 0: biases, X/Ks, pads, Z & aw2 loads (tf32) ----
    if (tid < 128) {
        sb1[tid] = (tid < R) ? ab2[tid] : 0.f;
        sb2[tid] = (tid < R) ? eb[tid] : 0.f;
    }
    if (tid < R) {
        const float* xp = g_X + (size_t)b * (R * 3) + tid * 3;
        const float y0 = xp[0], y1 = xp[1], y2 = xp[2];
        sXs[tid * 3 + 0] = y0; sXs[tid * 3 + 1] = y1; sXs[tid * 3 + 2] = y2;
#pragma unroll
        for (int o = 0; o < 3; o++)
            sKs[tid * 3 + o] = fmaf(aw1[o * 3 + 0], y0,
                                fmaf(aw1[o * 3 + 1], y1,
                                fmaf(aw1[o * 3 + 2], y2, ab1[o])));
    }
    // zero pad rows 116..127 (cols 0..119 = 30 f4) for all 3 regions
    for (int idx = tid; idx < 3 * 12 * 30; idx += LT) {
        const int t = idx / 360, i2 = idx - t * 360;
        const int r = 116 + i2 / 30, c = (i2 - (i2 / 30) * 30) * 4;
        *(float4*)(sm + t * REGF + r * STR + c) = z4;
    }
    // zero pad cols 116..119 (one f4) rows 0..115, all regions
    for (int idx = tid; idx < 3 * 116; idx += LT) {
        const int t = idx / 116, r = idx - t * 116;
        *(float4*)(sm + t * REGF + r * STR + 116) = z4;
    }
    // Z -> R1, aw2 -> R2 (tf32)
    {
        const float* Zb = g_Z + (size_t)b * RR;
        for (int idx = tid; idx < 116 * 29; idx += LT) {
            const int r = idx / 29;
            const int c = (idx - r * 29) << 2;
            const float4 vz = *(const float4*)(Zb + r * R + c);
            *(float4*)(sR1 + r * STR + c) =
                make_float4(to_tf32(vz.x), to_tf32(vz.y), to_tf32(vz.z), to_tf32(vz.w));
            const float4 vw = *(const float4*)(aw2 + r * R + c);
            *(float4*)(sR2 + r * STR + c) =
                make_float4(to_tf32(vw.x), to_tf32(vw.y), to_tf32(vw.z), to_tf32(vw.w));
        }
    }
    __syncthreads();

    // ---- attention -> R3. No barrier needed before GEMM1. ----
    for (int n = wid; n < R; n += 16) {
        const float k0 = sKs[n * 3], k1 = sKs[n * 3 + 1], k2 = sKs[n * 3 + 2];
        float s[4];
        float mx = -3.0e38f;
#pragma unroll
        for (int it = 0; it < 4; it++) {
            const int m = it * 32 + lane;
            float v = -3.0e38f;
            if (m < R) v = k0 * sKs[m * 3] + k1 * sKs[m * 3 + 1] + k2 * sKs[m * 3 + 2];
            s[it] = v;
            mx = fmaxf(mx, v);
        }
#pragma unroll
        for (int o = 16; o; o >>= 1) mx = fmaxf(mx, __shfl_xor_sync(0xffffffffu, mx, o));
        float sum = 0.f, e[4];
#pragma unroll
        for (int it = 0; it < 4; it++) {
            const int m = it * 32 + lane;
            e[it] = (m < R) ? __expf(s[it] - mx) : 0.f;
            sum += e[it];
        }
        sum = wsum(sum);
        const float inv = 1.f / sum;
#pragma unroll
        for (int it = 0; it < 4; it++) {
            const int m = it * 32 + lane;
            if (m < R) sR3[n * STR + m] = to_tf32(e[it] * inv);
        }
    }

    float acc[2][4][4];
#pragma unroll
    for (int mt = 0; mt < 2; mt++)
#pragma unroll
        for (int nt = 0; nt < 4; nt++)
#pragma unroll
            for (int i = 0; i < 4; i++) acc[mt][nt][i] = 0.f;

    // ---- GEMM1: Mid1 = Z @ aw2^T ----
    mm_loop(sR1, sR2, acc, wm, wn, aOff, bOff);
    __syncthreads();

    // ---- Mid1 + ab2 -> R2 ----
#pragma unroll
    for (int mt = 0; mt < 2; mt++)
#pragma unroll
        for (int h = 0; h < 2; h++) {
            const int row = wm * 32 + mt * 16 + g + 8 * h;
#pragma unroll
            for (int nt = 0; nt < 4; nt++) {
                const int col = wn * 32 + nt * 8 + 2 * tig;
                if (col < 120)
                    *(float2*)(sR2 + row * STR + col) =
                        make_float2(to_tf32(acc[mt][nt][2 * h] + sb1[col]),
                                    to_tf32(acc[mt][nt][2 * h + 1] + sb1[col + 1]));
            }
        }
#pragma unroll
    for (int mt = 0; mt < 2; mt++)
#pragma unroll
        for (int nt = 0; nt < 4; nt++)
#pragma unroll
            for (int i = 0; i < 4; i++) acc[mt][nt][i] = 0.f;
    __syncthreads();

    // ---- GEMM3: S2 = Mid1 @ att^T ----
    mm_loop(sR2, sR3, acc, wm, wn, aOff, bOff);
    __syncthreads();

    // ---- S2 -> R3 + node partials ; ew -> R2 ----
#pragma unroll
    for (int mt = 0; mt < 2; mt++)
#pragma unroll
        for (int h = 0; h < 2; h++) {
            const int row = wm * 32 + mt * 16 + g + 8 * h;
            float a0 = 0.f, a1 = 0.f, a2 = 0.f;
#pragma unroll
            for (int nt = 0; nt < 4; nt++) {
                const int col = wn * 32 + nt * 8 + 2 * tig;
                const float v0 = acc[mt][nt][2 * h];
                const float v1 = acc[mt][nt][2 * h + 1];
                if (col < 120)
                    *(float2*)(sR3 + row * STR + col) =
                        make_float2(to_tf32(v0), to_tf32(v1));
                if (row < R && col < R) {
                    a0 = fmaf(v0, sXs[col * 3 + 0], fmaf(v1, sXs[col * 3 + 3], a0));
                    a1 = fmaf(v0, sXs[col * 3 + 1], fmaf(v1, sXs[col * 3 + 4], a1));
                    a2 = fmaf(v0, sXs[col * 3 + 2], fmaf(v1, sXs[col * 3 + 5], a2));
                }
            }
            a0 += __shfl_xor_sync(0xffffffffu, a0, 1);
            a0 += __shfl_xor_sync(0xffffffffu, a0, 2);
            a1 += __shfl_xor_sync(0xffffffffu, a1, 1);
            a1 += __shfl_xor_sync(0xffffffffu, a1, 2);
            a2 += __shfl_xor_sync(0xffffffffu, a2, 1);
            a2 += __shfl_xor_sync(0xffffffffu, a2, 2);
            if (tig == 0) {
                pA[0 * 512 + wn * 128 + row] = a0;
                pA[1 * 512 + wn * 128 + row] = a1;
                pA[2 * 512 + wn * 128 + row] = a2;
            }
        }
    for (int idx = tid; idx < 116 * 29; idx += LT) {
        const int r = idx / 29;
        const int c = (idx - r * 29) << 2;
        const float4 v = *(const float4*)(ew + r * R + c);
        *(float4*)(sR2 + r * STR + c) =
            make_float4(to_tf32(v.x), to_tf32(v.y), to_tf32(v.z), to_tf32(v.w));
    }
#pragma unroll
    for (int mt = 0; mt < 2; mt++)
#pragma unroll
        for (int nt = 0; nt < 4; nt++)
#pragma unroll
            for (int i = 0; i < 4; i++) acc[mt][nt][i] = 0.f;
    __syncthreads();

    // ---- GEMM2: Et = ew @ Z^T ----
    mm_loop(sR2, sR1, acc, wm, wn, aOff, bOff);
    __syncthreads();

    // ---- Et -> R1 ----
#pragma unroll
    for (int mt = 0; mt < 2; mt++)
#pragma unroll
        for (int h = 0; h < 2; h++) {
            const int row = wm * 32 + mt * 16 + g + 8 * h;
#pragma unroll
            for (int nt = 0; nt < 4; nt++) {
                const int col = wn * 32 + nt * 8 + 2 * tig;
                if (col < 120)
                    *(float2*)(sR1 + row * STR + col) =
                        make_float2(to_tf32(acc[mt][nt][2 * h]),
                                    to_tf32(acc[mt][nt][2 * h + 1]));
            }
        }
#pragma unroll
    for (int mt = 0; mt < 2; mt++)
#pragma unroll
        for (int nt = 0; nt < 4; nt++)
#pragma unroll
            for (int i = 0; i < 4; i++) acc[mt][nt][i] = 0.f;
    __syncthreads();

    // ---- GEMM4: Z1 = S2 @ Et^T + eb ----
    mm_loop(sR3, sR1, acc, wm, wn, aOff, bOff);

    // ---- epilogue: Z1 + edge stats ----
    float* Cb = g_Z1 + (size_t)b * RR;
#pragma unroll
    for (int mt = 0; mt < 2; mt++) {
#pragma unroll
        for (int h = 0; h < 2; h++) {
            const int row = wm * 32 + mt * 16 + g + 8 * h;
            float s = 0.f, q = 0.f;
#pragma unroll
            for (int nt = 0; nt < 4; nt++) {
                const int col = wn * 32 + nt * 8 + 2 * tig;
                if (col < R) {
                    const float v0 = acc[mt][nt][2 * h] + sb2[col];
                    const float v1 = acc[mt][nt][2 * h + 1] + sb2[col + 1];
                    if (row < R)
                        *(float2*)(Cb + (size_t)row * R + col) = make_float2(v0, v1);
                    s += v0 + v1;
                    q += v0 * v0 + v1 * v1;
                }
            }
            s += __shfl_xor_sync(0xffffffffu, s, 1);
            s += __shfl_xor_sync(0xffffffffu, s, 2);
            q += __shfl_xor_sync(0xffffffffu, q, 1);
            q += __shfl_xor_sync(0xffffffffu, q, 2);
            if (tig == 0) { pS[wn * 128 + row] = s; pQ[wn * 128 + row] = q; }
        }
    }
    __syncthreads();
    if (tid < R) {
        const float s = pS[tid] + pS[128 + tid] + pS[256 + tid] + pS[384 + tid];
        const float q = pQ[tid] + pQ[128 + tid] + pQ[256 + tid] + pQ[384 + tid];
        g_ps[tid * NB + b] = s;
        g_pq[tid * NB + b] = q;
    }
    // ---- node path finish: X1 = (S2 @ X) @ nw^T + nb, node stats ----
    if (tid < R) {
        const int n = tid;
        const float a0 = pA[0 * 512 + n] + pA[0 * 512 + 128 + n] +
                         pA[0 * 512 + 256 + n] + pA[0 * 512 + 384 + n];
        const float a1 = pA[1 * 512 + n] + pA[1 * 512 + 128 + n] +
                         pA[1 * 512 + 256 + n] + pA[1 * 512 + 384 + n];
        const float a2 = pA[2 * 512 + n] + pA[2 * 512 + 128 + n] +
                         pA[2 * 512 + 256 + n] + pA[2 * 512 + 384 + n];
        float ps = 0.f, pq = 0.f;
        float* dst = g_X1 + (size_t)b * (R * 3) + n * 3;
#pragma unroll
        for (int o = 0; o < 3; o++) {
            const float v = fmaf(nw[o * 3 + 0], a0,
                            fmaf(nw[o * 3 + 1], a1,
                            fmaf(nw[o * 3 + 2], a2, nb_[o])));
            dst[o] = v;
            ps += v;
            pq = fmaf(v, v, pq);
        }
        g_psN[n * NB + b] = ps;
        g_pqN[n * NB + b] = pq;
    }
}

// ----------------------------------------------------------------------------
// Both BN channel reductions in one launch. grid = 2R, block = 256.
// ----------------------------------------------------------------------------
__global__ void k_reduce_both(const float* __restrict__ geg, const float* __restrict__ geb,
                              const float* __restrict__ gng, const float* __restrict__ gnb) {
    const bool edge = blockIdx.x < R;
    const int n = edge ? blockIdx.x : blockIdx.x - R;
    const float* PS = edge ? g_ps : g_psN;
    const float* PQ = edge ? g_pq : g_pqN;
    float s = 0.f, q = 0.f;
    for (int b = threadIdx.x; b < NB; b += 256) {
        s += PS[n * NB + b];
        q += PQ[n * NB + b];
    }
    __shared__ float shs[8], shq[8];
    s = wsum(s); q = wsum(q);
    const int w = threadIdx.x >> 5, lane = threadIdx.x & 31;
    if (lane == 0) { shs[w] = s; shq[w] = q; }
    __syncthreads();
    if (w == 0) {
        s = (lane < 8) ? shs[lane] : 0.f;
        q = (lane < 8) ? shq[lane] : 0.f;
        s = wsum(s); q = wsum(q);
        if (lane == 0) {
            const float invcnt = edge ? (1.f / (float)(NB * R)) : (1.f / (float)(3 * NB));
            const float mean = s * invcnt;
            const float var = q * invcnt - mean * mean;
            const float rstd = rsqrtf(var + EPS);
            const float gg = edge ? geg[n] : gng[n];
            const float bb = edge ? geb[n] : gnb[n];
            const float sc = rstd * gg;
            if (edge) { g_scale[n] = sc;  g_shift[n] = bb - mean * sc; }
            else      { g_scaleN[n] = sc; g_shiftN[n] = bb - mean * sc; }
        }
    }
}

// ----------------------------------------------------------------------------
// Combined: Z+=relu(bn(Z1)) & down-edge  /  X+=relu(bn(X1)) & down-node.
// apply==0: pass-through copy from srcZ/srcX into g_Z/g_X (layer 0).
// grid = 29696 + 928, block = 128.
// ----------------------------------------------------------------------------
__global__ void k_apply_down(const float* __restrict__ dew, const float* __restrict__ deb,
                             const float* __restrict__ dnw, const float* __restrict__ dnb,
                             const float* __restrict__ srcZ, const float* __restrict__ srcX,
                             int offE, int offN, int dpE, int dpN, int apply) {
    __shared__ float sWt[78];
    __shared__ float sh[8];
    if (blockIdx.x < 29696) {
        // ---------------- edge ----------------
        if (threadIdx.x < 78) sWt[threadIdx.x] = dew[threadIdx.x];
        __syncthreads();
        const int wrp = threadIdx.x >> 5, lane = threadIdx.x & 31;
        const int rowid = blockIdx.x * 4 + wrp;
        const int b = rowid / R, n = rowid - b * R;
        float4 v = make_float4(0.f, 0.f, 0.f, 0.f);
        float* zrow = g_Z + (size_t)rowid * R;
        if (lane < 29) {
            if (apply) {
                v = *(float4*)(zrow + 4 * lane);
                const float4 u = *(const float4*)(g_Z1 + (size_t)rowid * R + 4 * lane);
                const float sc = g_scale[n], sf = g_shift[n];
                v.x += fmaxf(fmaf(u.x, sc, sf), 0.f);
                v.y += fmaxf(fmaf(u.y, sc, sf), 0.f);
                v.z += fmaxf(fmaf(u.z, sc, sf), 0.f);
                v.w += fmaxf(fmaf(u.w, sc, sf), 0.f);
                *(float4*)(zrow + 4 * lane) = v;
            } else {
                v = *(const float4*)(srcZ + (size_t)rowid * R + 4 * lane);
                *(float4*)(zrow + 4 * lane) = v;
            }
        }
        float f0 = 0.f, f1 = 0.f, f2 = 0.f;
        const float vv[4] = {v.x, v.y, v.z, v.w};
#pragma unroll
        for (int d = 0; d < 4; d++) {
            const int e = 4 * lane + d;
            if (e < 78) f1 = fmaf(vv[d], sWt[e], f1);
            if (e < 39) f0 = fmaf(vv[d], sWt[39 + e], f0);
            if (e >= 39 && e < 116) f2 = fmaf(vv[d], sWt[e - 39], f2);
        }
        f0 = wsum(f0); f1 = wsum(f1); f2 = wsum(f2);
        float s = 0.f, q = 0.f;
        if (lane == 0) {
            const float bb = deb[0];
            f0 = fmaxf(f0 + bb, 0.f);
            f1 = fmaxf(f1 + bb, 0.f);
            f2 = fmaxf(f2 + bb, 0.f);
            float* dst = g_XZ + (size_t)b * FEAT + offE + n * 3;
            dst[0] = f0; dst[1] = f1; dst[2] = f2;
            s = f0 + f1 + f2;
            q = f0 * f0 + f1 * f1 + f2 * f2;
            sh[wrp] = s; sh[4 + wrp] = q;
        }
        __syncthreads();
        if (threadIdx.x == 0) {
            g_dpS[dpE + blockIdx.x] = sh[0] + sh[1] + sh[2] + sh[3];
            g_dpQ[dpE + blockIdx.x] = sh[4] + sh[5] + sh[6] + sh[7];
        }
    } else {
        // ---------------- node ----------------
        const int bid = blockIdx.x - 29696;
        const int idx = bid * 128 + threadIdx.x;
        float* xp = g_X + (size_t)idx * 3;
        float x0, x1, x2;
        if (apply) {
            x0 = xp[0]; x1 = xp[1]; x2 = xp[2];
            const int n = idx % R;
            const float sc = g_scaleN[n], sf = g_shiftN[n];
            const float* up = g_X1 + (size_t)idx * 3;
            x0 += fmaxf(fmaf(up[0], sc, sf), 0.f);
            x1 += fmaxf(fmaf(up[1], sc, sf), 0.f);
            x2 += fmaxf(fmaf(up[2], sc, sf), 0.f);
            xp[0] = x0; xp[1] = x1; xp[2] = x2;
        } else {
            const float* sp = srcX + (size_t)idx * 3;
            x0 = sp[0]; x1 = sp[1]; x2 = sp[2];
            xp[0] = x0; xp[1] = x1; xp[2] = x2;
        }
        const float f = fmaxf(fmaf(x0, dnw[0], fmaf(x1, dnw[1], fmaf(x2, dnw[2], dnb[0]))), 0.f);
        const int b = idx / R, r = idx - (idx / R) * R;
        g_XZ[(size_t)b * FEAT + offN + r] = f;
        const float s = wsum(f);
        const float q = wsum(f * f);
        const int wr = threadIdx.x >> 5, lane = threadIdx.x & 31;
        if (lane == 0) { sh[wr] = s; sh[4 + wr] = q; }
        __syncthreads();
        if (threadIdx.x == 0) {
            g_dpS[dpN + bid] = sh[0] + sh[1] + sh[2] + sh[3];
            g_dpQ[dpN + bid] = sh[4] + sh[5] + sh[6] + sh[7];
        }
    }
}

// ----------------------------------------------------------------------------
// All 10 down-sample reductions at once. grid = 10, block = 1024.
// ----------------------------------------------------------------------------
__global__ void k_dreduce_all(const float* __restrict__ dng, const float* __restrict__ dnbe,
                              const float* __restrict__ deg, const float* __restrict__ debe) {
    const int sgm = blockIdx.x;
    const bool node = sgm < 5;
    const int l = node ? sgm : sgm - 5;
    const int base = node ? (EDGET + l * 928) : (l * 29696);
    const int cnt = node ? 928 : 29696;
    const float invcnt = node ? (1.f / (float)(NB * R)) : (1.f / (float)(NB * R * 3));
    float s = 0.f, q = 0.f;
    for (int i = threadIdx.x; i < cnt; i += 1024) {
        s += g_dpS[base + i];
        q += g_dpQ[base + i];
    }
    __shared__ float shs[32], shq[32];
    s = wsum(s); q = wsum(q);
    const int w = threadIdx.x >> 5, lane = threadIdx.x & 31;
    if (lane == 0) { shs[w] = s; shq[w] = q; }
    __syncthreads();
    if (w == 0) {
        s = shs[lane]; q = shq[lane];
        s = wsum(s); q = wsum(q);
        if (lane == 0) {
            const float mean = s * invcnt;
            const float var = q * invcnt - mean * mean;
            const float rstd = rsqrtf(var + EPS);
            const float gg = node ? dng[l] : deg[l];
            const float bb = node ? dnbe[l] : debe[l];
            const float sc = rstd * gg;
            g_dssArr[2 * sgm]     = sc;
            g_dssArr[2 * sgm + 1] = bb - mean * sc;
        }
    }
}

// ----------------------------------------------------------------------------
// Classifier GEMM with slab normalization folded into the A-load.
// ----------------------------------------------------------------------------
__global__ void __launch_bounds__(256)
k_cls(const float* __restrict__ A, const float* __restrict__ Bm,
      const float* __restrict__ bias, float* __restrict__ C)
{
    __shared__ float sA[2][128 * 20];
    __shared__ float sB[2][64 * 20];
    __shared__ float sbc[64];
    const int tid = threadIdx.x;
    const int wid = tid >> 5, lane = tid & 31;
    const int wm = wid >> 1, wn = wid & 1;
    const int g = lane >> 2, tig = lane & 3;
    const int row0 = blockIdx.y * 128, col0 = blockIdx.x * 64;

    if (tid < 64) sbc[tid] = bias[col0 + tid];

    float4 pa0, pa1, pb;
    float fsc, fsh;
    const int ar0 = tid >> 2, ac0 = (tid & 3) << 2;
    const int ar1 = (tid + 256) >> 2, ac1 = ac0;
    const int br = tid >> 2, bc = (tid & 3) << 2;

    auto fetch = [&](int k0) {
        const int k = k0 + ac0;
        const int sgm = (k < 580) ? (k / 116) : (5 + (k - 580) / 348);
        fsc = g_dssArr[2 * sgm];
        fsh = g_dssArr[2 * sgm + 1];
        pa0 = *(const float4*)(A + (size_t)(row0 + ar0) * FEAT + k0 + ac0);
        pa1 = *(const float4*)(A + (size_t)(row0 + ar1) * FEAT + k0 + ac1);
        pb  = *(const float4*)(Bm + (size_t)(col0 + br) * FEAT + k0 + bc);
    };
    auto store = [&](int buf) {
        float* d0 = &sA[buf][ar0 * 20 + ac0];
        d0[0] = to_tf32(fmaf(pa0.x, fsc, fsh)); d0[1] = to_tf32(fmaf(pa0.y, fsc, fsh));
        d0[2] = to_tf32(fmaf(pa0.z, fsc, fsh)); d0[3] = to_tf32(fmaf(pa0.w, fsc, fsh));
        float* d1 = &sA[buf][ar1 * 20 + ac1];
        d1[0] = to_tf32(fmaf(pa1.x, fsc, fsh)); d1[1] = to_tf32(fmaf(pa1.y, fsc, fsh));
        d1[2] = to_tf32(fmaf(pa1.z, fsc, fsh)); d1[3] = to_tf32(fmaf(pa1.w, fsc, fsh));
        float* d2 = &sB[buf][br * 20 + bc];
        d2[0] = to_tf32(pb.x); d2[1] = to_tf32(pb.y);
        d2[2] = to_tf32(pb.z); d2[3] = to_tf32(pb.w);
    };

    float acc[2][4][4];
#pragma unroll
    for (int mt = 0; mt < 2; mt++)
#pragma unroll
        for (int nt = 0; nt < 4; nt++)
#pragma unroll
            for (int i = 0; i < 4; i++) acc[mt][nt][i] = 0.f;

    const int NS = FEAT / 16;
    fetch(0);
    store(0);
    __syncthreads();
    int buf = 0;
    for (int ks = 0; ks < NS; ks++) {
        if (ks + 1 < NS) fetch((ks + 1) * 16);
#pragma unroll
        for (int kk = 0; kk < 2; kk++) {
            const int k0 = kk * 8;
            uint32_t af[2][4], bf[4][2];
#pragma unroll
            for (int mt = 0; mt < 2; mt++) {
                const float* p0 = &sA[buf][(wm * 32 + mt * 16 + g) * 20 + k0 + tig];
                af[mt][0] = __float_as_uint(p0[0]);
                af[mt][1] = __float_as_uint(p0[8 * 20]);
                af[mt][2] = __float_as_uint(p0[4]);
                af[mt][3] = __float_as_uint(p0[8 * 20 + 4]);
            }
#pragma unroll
            for (int nt = 0; nt < 4; nt++) {
                const float* p0 = &sB[buf][(wn * 32 + nt * 8 + g) * 20 + k0 + tig];
                bf[nt][0] = __float_as_uint(p0[0]);
                bf[nt][1] = __float_as_uint(p0[4]);
            }
#pragma unroll
            for (int mt = 0; mt < 2; mt++)
#pragma unroll
                for (int nt = 0; nt < 4; nt++)
                    mma8(acc[mt][nt], af[mt], bf[nt]);
        }
        if (ks + 1 < NS) store(buf ^ 1);
        __syncthreads();
        buf ^= 1;
    }

#pragma unroll
    for (int mt = 0; mt < 2; mt++)
#pragma unroll
        for (int h = 0; h < 2; h++) {
            const int row = row0 + wm * 32 + mt * 16 + g + 8 * h;
#pragma unroll
            for (int nt = 0; nt < 4; nt++) {
                const int col = wn * 32 + nt * 8 + 2 * tig;
                const float v0 = fmaxf(acc[mt][nt][2 * h] + sbc[col], 0.f);
                const float v1 = fmaxf(acc[mt][nt][2 * h + 1] + sbc[col + 1], 0.f);
                *(float2*)(C + (size_t)row * HID + col0 + col) = make_float2(v0, v1);
            }
        }
}

__global__ void k_out(const float* __restrict__ cw2, const float* __restrict__ cb2,
                      float* __restrict__ out) {
    const int b = blockIdx.x;
    const float* h = g_H + (size_t)b * HID;
    float a0 = 0.f, a1 = 0.f;
    for (int j = threadIdx.x; j < HID; j += 128) {
        const float hv = h[j];
        a0 = fmaf(hv, cw2[j], a0);
        a1 = fmaf(hv, cw2[HID + j], a1);
    }
    a0 = wsum(a0);
    a1 = wsum(a1);
    __shared__ float sh[8];
    const int w = threadIdx.x >> 5, lane = threadIdx.x & 31;
    if (lane == 0) { sh[w] = a0; sh[4 + w] = a1; }
    __syncthreads();
    if (threadIdx.x == 0) {
        out[b * 2 + 0] = sh[0] + sh[1] + sh[2] + sh[3] + cb2[0];
        out[b * 2 + 1] = sh[4] + sh[5] + sh[6] + sh[7] + cb2[1];
    }
}

// ----------------------------------------------------------------------------
// Host orchestration (graph-capturable: kernel launches only)
// ----------------------------------------------------------------------------
extern "C" void kernel_launch(void* const* d_in, const int* in_sizes, int n_in,
                              void* d_out, int out_size) {
    const float* X_in  = (const float*)d_in[0];
    const float* Z_in  = (const float*)d_in[1];
    const float* aw1   = (const float*)d_in[2];
    const float* ab1   = (const float*)d_in[3];
    const float* aw2   = (const float*)d_in[4];
    const float* ab2   = (const float*)d_in[5];
    const float* nw    = (const float*)d_in[6];
    const float* nb    = (const float*)d_in[7];
    const float* ew    = (const float*)d_in[8];
    const float* eb    = (const float*)d_in[9];
    const float* gn_g  = (const float*)d_in[10];
    const float* gn_b  = (const float*)d_in[11];
    const float* ge_g  = (const float*)d_in[12];
    const float* ge_b  = (const float*)d_in[13];
    const float* dn_w  = (const float*)d_in[14];
    const float* dn_b  = (const float*)d_in[15];
    const float* dn_g  = (const float*)d_in[16];
    const float* dn_be = (const float*)d_in[17];
    const float* de_w  = (const float*)d_in[18];
    const float* de_b  = (const float*)d_in[19];
    const float* de_g  = (const float*)d_in[20];
    const float* de_be = (const float*)d_in[21];
    const float* cw1   = (const float*)d_in[22];
    const float* cb1   = (const float*)d_in[23];
    const float* cw2   = (const float*)d_in[24];
    const float* cb2   = (const float*)d_in[25];
    float* out = (float*)d_out;

    cudaFuncSetAttribute(k_layer, cudaFuncAttributeMaxDynamicSharedMemorySize, SM_TOTB);

    float *pXZ, *pH;
    cudaGetSymbolAddress((void**)&pXZ, g_XZ);
    cudaGetSymbolAddress((void**)&pH,  g_H);

    // layer-0 down-sample, fused with input pass-through copy
    k_apply_down<<<29696 + 928, 128>>>(de_w, de_b, dn_w, dn_b,
                                       Z_in, X_in,
                                       580, 0, 0, EDGET, 0);

    for (int i = 0; i < LAYERS; i++) {
        k_layer<<<NB, LT, SM_TOTB>>>(aw2 + (size_t)i * RR, ab2 + i * R,
                                     aw1 + 9 * i, ab1 + 3 * i,
                                     ew + (size_t)i * RR, eb + i * R,
                                     nw + 9 * i, nb + 3 * i);
        k_reduce_both<<<2 * R, 256>>>(ge_g + i * R, ge_b + i * R,
                                      gn_g + i * R, gn_b + i * R);
        const int l = i + 1;
        k_apply_down<<<29696 + 928, 128>>>(de_w + 78 * l, de_b + l,
                                           dn_w + 3 * l, dn_b + l,
                                           nullptr, nullptr,
                                           580 + l * 348, l * R,
                                           l * 29696, EDGET + l * 928, 1);
    }

    k_dreduce_all<<<10, 1024>>>(dn_g, dn_be, de_g, de_be);
    k_cls<<<dim3(HID / 64, NB / 128), 256>>>(pXZ, cw1, cb1, pH);
    k_out<<<NB, 128>>>(cw2, cb2, out);
}

// round 10
// speedup vs baseline: 1.3480x; 1.1962x over previous
#include <cuda_runtime.h>
#include <cuda_fp16.h>
#include <cstddef>
#include <cstdint>

// ----------------------------------------------------------------------------
// Problem constants
// ----------------------------------------------------------------------------
#define NB 1024            // batch
#define R 116              // ROIs
#define RR (R * R)         // 13456
#define LAYERS 4
#define FEAT 2320          // R*4*(L+1)
#define HID 1024
#define EPS 1e-5f

#define SH 136             // smem tile row stride (halves) — LDSM conflict-free
#define REGH (128 * SH)    // halves per region (17408)

// down-sample partial slot layout
#define EDGET 148480       // 5 * 29696 edge partial slots
#define DPTOT 153120       // + 5 * 928 node slots

// ----------------------------------------------------------------------------
// Device scratch (static allocation only)
// ----------------------------------------------------------------------------
__device__ __align__(16) float g_Z  [(size_t)NB * RR];
__device__ __align__(16) float g_Z1 [(size_t)NB * RR];
__device__ __align__(16) float g_X  [NB * R * 3];
__device__ __align__(16) float g_X1 [NB * R * 3];
__device__ __align__(16) float g_XZ [(size_t)NB * FEAT];
__device__ __align__(16) float g_H  [(size_t)NB * HID];
__device__ float g_ps [R * NB];     // edge BN partials
__device__ float g_pq [R * NB];
__device__ float g_psN[R * NB];     // node BN partials
__device__ float g_pqN[R * NB];
__device__ float g_scale [R],  g_shift [R];   // edge BN affine
__device__ float g_scaleN[R],  g_shiftN[R];   // node BN affine
__device__ float g_dpS[DPTOT], g_dpQ[DPTOT];  // down-sample partials
__device__ float g_dssArr[20];                // 10 segments x (scale, shift)

__device__ __forceinline__ float wsum(float v) {
#pragma unroll
    for (int o = 16; o; o >>= 1) v += __shfl_xor_sync(0xffffffffu, v, o);
    return v;
}

__device__ __forceinline__ float to_tf32(float x) {
    float y;
    asm("cvt.rna.tf32.f32 %0, %1;" : "=f"(y) : "f"(x));
    return y;
}

__device__ __forceinline__ uint32_t sptr(const void* p) {
    return (uint32_t)__cvta_generic_to_shared(p);
}

// ldmatrix x4: loads 4 8x8 b16 tiles.
#define LDSM4(r0, r1, r2, r3, addr) \
    asm volatile("ldmatrix.sync.aligned.m8n8.x4.shared.b16 {%0,%1,%2,%3}, [%4];" \
                 : "=r"(r0), "=r"(r1), "=r"(r2), "=r"(r3) : "r"(addr))

// mma.sync m16n8k16 fp16 inputs, fp32 accumulate
__device__ __forceinline__ void mma16(float* d, const uint32_t* a, const uint32_t* b) {
    asm volatile(
        "mma.sync.aligned.m16n8k16.row.col.f32.f16.f16.f32 "
        "{%0,%1,%2,%3},{%4,%5,%6,%7},{%8,%9},{%0,%1,%2,%3};"
        : "+f"(d[0]), "+f"(d[1]), "+f"(d[2]), "+f"(d[3])
        : "r"(a[0]), "r"(a[1]), "r"(a[2]), "r"(a[3]), "r"(b[0]), "r"(b[1]));
}

// mma.sync m16n8k8 tf32 (classifier only)
__device__ __forceinline__ void mma8(float* d, const uint32_t* a, const uint32_t* b) {
    asm volatile(
        "mma.sync.aligned.m16n8k8.row.col.f32.tf32.tf32.f32 "
        "{%0,%1,%2,%3},{%4,%5,%6,%7},{%8,%9},{%0,%1,%2,%3};"
        : "+f"(d[0]), "+f"(d[1]), "+f"(d[2]), "+f"(d[3])
        : "r"(a[0]), "r"(a[1]), "r"(a[2]), "r"(a[3]), "r"(b[0]), "r"(b[1]));
}

// 128x128x128 NT GEMM over fp16 smem tiles (stride SH halves), 16 warps,
// warp tile 32x32, 8 k-steps of K=16. 4 LDSM.x4 + 8 MMA per k-step.
//   aOff = (lane&15)*SH*2 + 16*(lane>>4)
//   bOff = ((lane&7) + 8*(lane>>4))*SH*2 + 16*((lane>>3)&1)
__device__ __forceinline__ void mm_loop(const __half* __restrict__ sA,
                                        const __half* __restrict__ sB,
                                        float (&acc)[2][4][4],
                                        int wm, int wn,
                                        uint32_t aOff, uint32_t bOff) {
    const uint32_t a0b = sptr(sA) + (uint32_t)(wm * 32 * SH * 2) + aOff;
    const uint32_t a1b = a0b + 16 * SH * 2;
    const uint32_t b0b = sptr(sB) + (uint32_t)(wn * 32 * SH * 2) + bOff;
    const uint32_t b1b = b0b + 16 * SH * 2;
#pragma unroll
    for (int ks = 0; ks < 8; ks++) {
        const uint32_t off = ks * 32;       // 16 halves = 32 bytes per k-step
        uint32_t af[2][4], bf[4][2];
        LDSM4(af[0][0], af[0][1], af[0][2], af[0][3], a0b + off);
        LDSM4(af[1][0], af[1][1], af[1][2], af[1][3], a1b + off);
        LDSM4(bf[0][0], bf[0][1], bf[1][0], bf[1][1], b0b + off);
        LDSM4(bf[2][0], bf[2][1], bf[3][0], bf[3][1], b1b + off);
#pragma unroll
        for (int mt = 0; mt < 2; mt++)
#pragma unroll
            for (int nt = 0; nt < 4; nt++)
                mma16(acc[mt][nt], af[mt], bf[nt]);
    }
}

// ----------------------------------------------------------------------------
// Mega layer kernel (fp16 tiles): one CTA per batch, 512 threads (16 warps).
//   Mid1 = Z @ aw2^T + ab2 ; att = softmax(K^T K) ;
//   S2   = Mid1 @ att^T  (+ fused node path partials) ;
//   Et   = ew @ Z^T ;  Z1 = S2 @ Et^T + eb (gmem, + edge-BN stats)
// Regions (halves): R1 = Z -> Et ; R2 = aw2 -> Mid1 -> ew ; R3 = att -> S2.
// Float extras follow the 3 half regions.
// ----------------------------------------------------------------------------
#define HBYTES (3 * REGH * 2)      // 104448
#define EXT_B1 0
#define EXT_B2 128
#define EXT_KS 256                 // 352
#define EXT_XS 608                 // 352
#define EXT_PS 960                 // 512
#define EXT_PQ 1472                // 512
#define EXT_PA 1984                // 1536
#define EXT_TOT 3520
#define SM_TOTB (HBYTES + EXT_TOT * 4)   // 118528

#define LT 512

__global__ void __launch_bounds__(LT, 1)
k_layer(const float* __restrict__ aw2, const float* __restrict__ ab2,
        const float* __restrict__ aw1, const float* __restrict__ ab1,
        const float* __restrict__ ew,  const float* __restrict__ eb,
        const float* __restrict__ nw,  const float* __restrict__ nb_)
{
    extern __shared__ __align__(16) char smraw[];
    __half* hR1 = (__half*)smraw;            // Z -> Et
    __half* hR2 = hR1 + REGH;                // aw2 -> Mid1 -> ew
    __half* hR3 = hR2 + REGH;                // att -> S2
    float* fext = (float*)(smraw + HBYTES);
    float* sb1 = fext + EXT_B1;
    float* sb2 = fext + EXT_B2;
    float* sKs = fext + EXT_KS;
    float* sXs = fext + EXT_XS;
    float* pS  = fext + EXT_PS;
    float* pQ  = fext + EXT_PQ;
    float* pA  = fext + EXT_PA;

    const int tid = threadIdx.x;
    const int b = blockIdx.x;
    const int wid = tid >> 5, lane = tid & 31;
    const int wm = wid >> 2, wn = wid & 3;
    const int g = lane >> 2, tig = lane & 3;

    // ldmatrix per-lane byte offsets
    const uint32_t aOff = (uint32_t)((lane & 15) * SH * 2 + 16 * (lane >> 4));
    const uint32_t bOff = (uint32_t)(((lane & 7) + 8 * (lane >> 4)) * SH * 2 +
                                     16 * ((lane >> 3) & 1));

    // ---- phase 0: biases, X/Ks, pads, Z & aw2 loads (fp16) ----
    if (tid < 128) {
        sb1[tid] = (tid < R) ? ab2[tid] : 0.f;
        sb2[tid] = (tid < R) ? eb[tid] : 0.f;
    }
    if (tid < R) {
        const float* xp = g_X + (size_t)b * (R * 3) + tid * 3;
        const float y0 = xp[0], y1 = xp[1], y2 = xp[2];
        sXs[tid * 3 + 0] = y0; sXs[tid * 3 + 1] = y1; sXs[tid * 3 + 2] = y2;
#pragma unroll
        for (int o = 0; o < 3; o++)
            sKs[tid * 3 + o] = fmaf(aw1[o * 3 + 0], y0,
                                fmaf(aw1[o * 3 + 1], y1,
                                fmaf(aw1[o * 3 + 2], y2, ab1[o])));
    }
    // zero pad rows 116..127, cols 0..127: 12 rows x 16 uint4 per region
    {
        const uint4 z4u = make_uint4(0, 0, 0, 0);
        for (int idx = tid; idx < 3 * 192; idx += LT) {
            const int t = idx / 192, i2 = idx - t * 192;
            const int r = 116 + i2 / 16, c8 = (i2 & 15) * 8;
            *(uint4*)(hR1 + (size_t)t * REGH + r * SH + c8) = z4u;
        }
    }
    // zero pad cols 116..127 rows 0..115: 3 uint2 per row per region
    {
        const uint2 z2u = make_uint2(0, 0);
        for (int idx = tid; idx < 3 * 116; idx += LT) {
            const int t = idx / 116, r = idx - t * 116;
            uint2* p = (uint2*)(hR1 + (size_t)t * REGH + r * SH + 116);
            p[0] = z2u; p[1] = z2u; p[2] = z2u;
        }
    }
    // Z -> R1, aw2 -> R2 (fp16)
    {
        const float* Zb = g_Z + (size_t)b * RR;
        for (int idx = tid; idx < 116 * 29; idx += LT) {
            const int r = idx / 29;
            const int c = (idx - r * 29) << 2;
            const float4 vz = *(const float4*)(Zb + r * R + c);
            __half2* dz = (__half2*)(hR1 + r * SH + c);
            dz[0] = __floats2half2_rn(vz.x, vz.y);
            dz[1] = __floats2half2_rn(vz.z, vz.w);
            const float4 vw = *(const float4*)(aw2 + r * R + c);
            __half2* dw = (__half2*)(hR2 + r * SH + c);
            dw[0] = __floats2half2_rn(vw.x, vw.y);
            dw[1] = __floats2half2_rn(vw.z, vw.w);
        }
    }
    __syncthreads();

    // ---- attention -> R3 (fp16). No barrier needed before GEMM1. ----
    for (int n = wid; n < R; n += 16) {
        const float k0 = sKs[n * 3], k1 = sKs[n * 3 + 1], k2 = sKs[n * 3 + 2];
        float s[4];
        float mx = -3.0e38f;
#pragma unroll
        for (int it = 0; it < 4; it++) {
            const int m = it * 32 + lane;
            float v = -3.0e38f;
            if (m < R) v = k0 * sKs[m * 3] + k1 * sKs[m * 3 + 1] + k2 * sKs[m * 3 + 2];
            s[it] = v;
            mx = fmaxf(mx, v);
        }
#pragma unroll
        for (int o = 16; o; o >>= 1) mx = fmaxf(mx, __shfl_xor_sync(0xffffffffu, mx, o));
        float sum = 0.f, e[4];
#pragma unroll
        for (int it = 0; it < 4; it++) {
            const int m = it * 32 + lane;
            e[it] = (m < R) ? __expf(s[it] - mx) : 0.f;
            sum += e[it];
        }
        sum = wsum(sum);
        const float inv = 1.f / sum;
#pragma unroll
        for (int it = 0; it < 4; it++) {
            const int m = it * 32 + lane;
            if (m < R) hR3[n * SH + m] = __float2half_rn(e[it] * inv);
        }
    }

    float acc[2][4][4];
#pragma unroll
    for (int mt = 0; mt < 2; mt++)
#pragma unroll
        for (int nt = 0; nt < 4; nt++)
#pragma unroll
            for (int i = 0; i < 4; i++) acc[mt][nt][i] = 0.f;

    // ---- GEMM1: Mid1 = Z @ aw2^T ----
    mm_loop(hR1, hR2, acc, wm, wn, aOff, bOff);
    __syncthreads();

    // ---- Mid1 + ab2 -> R2 ----
#pragma unroll
    for (int mt = 0; mt < 2; mt++)
#pragma unroll
        for (int h = 0; h < 2; h++) {
            const int row = wm * 32 + mt * 16 + g + 8 * h;
#pragma unroll
            for (int nt = 0; nt < 4; nt++) {
                const int col = wn * 32 + nt * 8 + 2 * tig;
                if (col < 120)
                    *(__half2*)(hR2 + row * SH + col) =
                        __floats2half2_rn(acc[mt][nt][2 * h] + sb1[col],
                                          acc[mt][nt][2 * h + 1] + sb1[col + 1]);
            }
        }
#pragma unroll
    for (int mt = 0; mt < 2; mt++)
#pragma unroll
        for (int nt = 0; nt < 4; nt++)
#pragma unroll
            for (int i = 0; i < 4; i++) acc[mt][nt][i] = 0.f;
    __syncthreads();

    // ---- GEMM3: S2 = Mid1 @ att^T ----
    mm_loop(hR2, hR3, acc, wm, wn, aOff, bOff);
    __syncthreads();

    // ---- S2 -> R3 + node partials ; ew -> R2 ----
#pragma unroll
    for (int mt = 0; mt < 2; mt++)
#pragma unroll
        for (int h = 0; h < 2; h++) {
            const int row = wm * 32 + mt * 16 + g + 8 * h;
            float a0 = 0.f, a1 = 0.f, a2 = 0.f;
#pragma unroll
            for (int nt = 0; nt < 4; nt++) {
                const int col = wn * 32 + nt * 8 + 2 * tig;
                const float v0 = acc[mt][nt][2 * h];
                const float v1 = acc[mt][nt][2 * h + 1];
                if (col < 120)
                    *(__half2*)(hR3 + row * SH + col) = __floats2half2_rn(v0, v1);
                if (row < R && col < R) {
                    a0 = fmaf(v0, sXs[col * 3 + 0], fmaf(v1, sXs[col * 3 + 3], a0));
                    a1 = fmaf(v0, sXs[col * 3 + 1], fmaf(v1, sXs[col * 3 + 4], a1));
                    a2 = fmaf(v0, sXs[col * 3 + 2], fmaf(v1, sXs[col * 3 + 5], a2));
                }
            }
            a0 += __shfl_xor_sync(0xffffffffu, a0, 1);
            a0 += __shfl_xor_sync(0xffffffffu, a0, 2);
            a1 += __shfl_xor_sync(0xffffffffu, a1, 1);
            a1 += __shfl_xor_sync(0xffffffffu, a1, 2);
            a2 += __shfl_xor_sync(0xffffffffu, a2, 1);
            a2 += __shfl_xor_sync(0xffffffffu, a2, 2);
            if (tig == 0) {
                pA[0 * 512 + wn * 128 + row] = a0;
                pA[1 * 512 + wn * 128 + row] = a1;
                pA[2 * 512 + wn * 128 + row] = a2;
            }
        }
    for (int idx = tid; idx < 116 * 29; idx += LT) {
        const int r = idx / 29;
        const int c = (idx - r * 29) << 2;
        const float4 v = *(const float4*)(ew + r * R + c);
        __half2* d = (__half2*)(hR2 + r * SH + c);
        d[0] = __floats2half2_rn(v.x, v.y);
        d[1] = __floats2half2_rn(v.z, v.w);
    }
#pragma unroll
    for (int mt = 0; mt < 2; mt++)
#pragma unroll
        for (int nt = 0; nt < 4; nt++)
#pragma unroll
            for (int i = 0; i < 4; i++) acc[mt][nt][i] = 0.f;
    __syncthreads();

    // ---- GEMM2: Et = ew @ Z^T ----
    mm_loop(hR2, hR1, acc, wm, wn, aOff, bOff);
    __syncthreads();

    // ---- Et -> R1 ----
#pragma unroll
    for (int mt = 0; mt < 2; mt++)
#pragma unroll
        for (int h = 0; h < 2; h++) {
            const int row = wm * 32 + mt * 16 + g + 8 * h;
#pragma unroll
            for (int nt = 0; nt < 4; nt++) {
                const int col = wn * 32 + nt * 8 + 2 * tig;
                if (col < 120)
                    *(__half2*)(hR1 + row * SH + col) =
                        __floats2half2_rn(acc[mt][nt][2 * h], acc[mt][nt][2 * h + 1]);
            }
        }
#pragma unroll
    for (int mt = 0; mt < 2; mt++)
#pragma unroll
        for (int nt = 0; nt < 4; nt++)
#pragma unroll
            for (int i = 0; i < 4; i++) acc[mt][nt][i] = 0.f;
    __syncthreads();

    // ---- GEMM4: Z1 = S2 @ Et^T + eb ----
    mm_loop(hR3, hR1, acc, wm, wn, aOff, bOff);

    // ---- epilogue: Z1 + edge stats ----
    float* Cb = g_Z1 + (size_t)b * RR;
#pragma unroll
    for (int mt = 0; mt < 2; mt++) {
#pragma unroll
        for (int h = 0; h < 2; h++) {
            const int row = wm * 32 + mt * 16 + g + 8 * h;
            float s = 0.f, q = 0.f;
#pragma unroll
            for (int nt = 0; nt < 4; nt++) {
                const int col = wn * 32 + nt * 8 + 2 * tig;
                if (col < R) {
                    const float v0 = acc[mt][nt][2 * h] + sb2[col];
                    const float v1 = acc[mt][nt][2 * h + 1] + sb2[col + 1];
                    if (row < R)
                        *(float2*)(Cb + (size_t)row * R + col) = make_float2(v0, v1);
                    s += v0 + v1;
                    q += v0 * v0 + v1 * v1;
                }
            }
            s += __shfl_xor_sync(0xffffffffu, s, 1);
            s += __shfl_xor_sync(0xffffffffu, s, 2);
            q += __shfl_xor_sync(0xffffffffu, q, 1);
            q += __shfl_xor_sync(0xffffffffu, q, 2);
            if (tig == 0) { pS[wn * 128 + row] = s; pQ[wn * 128 + row] = q; }
        }
    }
    __syncthreads();
    if (tid < R) {
        const float s = pS[tid] + pS[128 + tid] + pS[256 + tid] + pS[384 + tid];
        const float q = pQ[tid] + pQ[128 + tid] + pQ[256 + tid] + pQ[384 + tid];
        g_ps[tid * NB + b] = s;
        g_pq[tid * NB + b] = q;
    }
    // ---- node path finish: X1 = (S2 @ X) @ nw^T + nb, node stats ----
    if (tid < R) {
        const int n = tid;
        const float a0 = pA[0 * 512 + n] + pA[0 * 512 + 128 + n] +
                         pA[0 * 512 + 256 + n] + pA[0 * 512 + 384 + n];
        const float a1 = pA[1 * 512 + n] + pA[1 * 512 + 128 + n] +
                         pA[1 * 512 + 256 + n] + pA[1 * 512 + 384 + n];
        const float a2 = pA[2 * 512 + n] + pA[2 * 512 + 128 + n] +
                         pA[2 * 512 + 256 + n] + pA[2 * 512 + 384 + n];
        float ps = 0.f, pq = 0.f;
        float* dst = g_X1 + (size_t)b * (R * 3) + n * 3;
#pragma unroll
        for (int o = 0; o < 3; o++) {
            const float v = fmaf(nw[o * 3 + 0], a0,
                            fmaf(nw[o * 3 + 1], a1,
                            fmaf(nw[o * 3 + 2], a2, nb_[o])));
            dst[o] = v;
            ps += v;
            pq = fmaf(v, v, pq);
        }
        g_psN[n * NB + b] = ps;
        g_pqN[n * NB + b] = pq;
    }
}

// ----------------------------------------------------------------------------
// Both BN channel reductions in one launch. grid = 2R, block = 256.
// ----------------------------------------------------------------------------
__global__ void k_reduce_both(const float* __restrict__ geg, const float* __restrict__ geb,
                              const float* __restrict__ gng, const float* __restrict__ gnb) {
    const bool edge = blockIdx.x < R;
    const int n = edge ? blockIdx.x : blockIdx.x - R;
    const float* PS = edge ? g_ps : g_psN;
    const float* PQ = edge ? g_pq : g_pqN;
    float s = 0.f, q = 0.f;
    for (int b = threadIdx.x; b < NB; b += 256) {
        s += PS[n * NB + b];
        q += PQ[n * NB + b];
    }
    __shared__ float shs[8], shq[8];
    s = wsum(s); q = wsum(q);
    const int w = threadIdx.x >> 5, lane = threadIdx.x & 31;
    if (lane == 0) { shs[w] = s; shq[w] = q; }
    __syncthreads();
    if (w == 0) {
        s = (lane < 8) ? shs[lane] : 0.f;
        q = (lane < 8) ? shq[lane] : 0.f;
        s = wsum(s); q = wsum(q);
        if (lane == 0) {
            const float invcnt = edge ? (1.f / (float)(NB * R)) : (1.f / (float)(3 * NB));
            const float mean = s * invcnt;
            const float var = q * invcnt - mean * mean;
            const float rstd = rsqrtf(var + EPS);
            const float gg = edge ? geg[n] : gng[n];
            const float bb = edge ? geb[n] : gnb[n];
            const float sc = rstd * gg;
            if (edge) { g_scale[n] = sc;  g_shift[n] = bb - mean * sc; }
            else      { g_scaleN[n] = sc; g_shiftN[n] = bb - mean * sc; }
        }
    }
}

// ----------------------------------------------------------------------------
// Combined: Z+=relu(bn(Z1)) & down-edge  /  X+=relu(bn(X1)) & down-node.
// apply==0: pass-through copy from srcZ/srcX into g_Z/g_X (layer 0).
// grid = 29696 + 928, block = 128.
// ----------------------------------------------------------------------------
__global__ void k_apply_down(const float* __restrict__ dew, const float* __restrict__ deb,
                             const float* __restrict__ dnw, const float* __restrict__ dnb,
                             const float* __restrict__ srcZ, const float* __restrict__ srcX,
                             int offE, int offN, int dpE, int dpN, int apply) {
    __shared__ float sWt[78];
    __shared__ float sh[8];
    if (blockIdx.x < 29696) {
        // ---------------- edge ----------------
        if (threadIdx.x < 78) sWt[threadIdx.x] = dew[threadIdx.x];
        __syncthreads();
        const int wrp = threadIdx.x >> 5, lane = threadIdx.x & 31;
        const int rowid = blockIdx.x * 4 + wrp;
        const int b = rowid / R, n = rowid - b * R;
        float4 v = make_float4(0.f, 0.f, 0.f, 0.f);
        float* zrow = g_Z + (size_t)rowid * R;
        if (lane < 29) {
            if (apply) {
                v = *(float4*)(zrow + 4 * lane);
                const float4 u = *(const float4*)(g_Z1 + (size_t)rowid * R + 4 * lane);
                const float sc = g_scale[n], sf = g_shift[n];
                v.x += fmaxf(fmaf(u.x, sc, sf), 0.f);
                v.y += fmaxf(fmaf(u.y, sc, sf), 0.f);
                v.z += fmaxf(fmaf(u.z, sc, sf), 0.f);
                v.w += fmaxf(fmaf(u.w, sc, sf), 0.f);
                *(float4*)(zrow + 4 * lane) = v;
            } else {
                v = *(const float4*)(srcZ + (size_t)rowid * R + 4 * lane);
                *(float4*)(zrow + 4 * lane) = v;
            }
        }
        float f0 = 0.f, f1 = 0.f, f2 = 0.f;
        const float vv[4] = {v.x, v.y, v.z, v.w};
#pragma unroll
        for (int d = 0; d < 4; d++) {
            const int e = 4 * lane + d;
            if (e < 78) f1 = fmaf(vv[d], sWt[e], f1);
            if (e < 39) f0 = fmaf(vv[d], sWt[39 + e], f0);
            if (e >= 39 && e < 116) f2 = fmaf(vv[d], sWt[e - 39], f2);
        }
        f0 = wsum(f0); f1 = wsum(f1); f2 = wsum(f2);
        float s = 0.f, q = 0.f;
        if (lane == 0) {
            const float bb = deb[0];
            f0 = fmaxf(f0 + bb, 0.f);
            f1 = fmaxf(f1 + bb, 0.f);
            f2 = fmaxf(f2 + bb, 0.f);
            float* dst = g_XZ + (size_t)b * FEAT + offE + n * 3;
            dst[0] = f0; dst[1] = f1; dst[2] = f2;
            s = f0 + f1 + f2;
            q = f0 * f0 + f1 * f1 + f2 * f2;
            sh[wrp] = s; sh[4 + wrp] = q;
        }
        __syncthreads();
        if (threadIdx.x == 0) {
            g_dpS[dpE + blockIdx.x] = sh[0] + sh[1] + sh[2] + sh[3];
            g_dpQ[dpE + blockIdx.x] = sh[4] + sh[5] + sh[6] + sh[7];
        }
    } else {
        // ---------------- node ----------------
        const int bid = blockIdx.x - 29696;
        const int idx = bid * 128 + threadIdx.x;
        float* xp = g_X + (size_t)idx * 3;
        float x0, x1, x2;
        if (apply) {
            x0 = xp[0]; x1 = xp[1]; x2 = xp[2];
            const int n = idx % R;
            const float sc = g_scaleN[n], sf = g_shiftN[n];
            const float* up = g_X1 + (size_t)idx * 3;
            x0 += fmaxf(fmaf(up[0], sc, sf), 0.f);
            x1 += fmaxf(fmaf(up[1], sc, sf), 0.f);
            x2 += fmaxf(fmaf(up[2], sc, sf), 0.f);
            xp[0] = x0; xp[1] = x1; xp[2] = x2;
        } else {
            const float* sp = srcX + (size_t)idx * 3;
            x0 = sp[0]; x1 = sp[1]; x2 = sp[2];
            xp[0] = x0; xp[1] = x1; xp[2] = x2;
        }
        const float f = fmaxf(fmaf(x0, dnw[0], fmaf(x1, dnw[1], fmaf(x2, dnw[2], dnb[0]))), 0.f);
        const int b = idx / R, r = idx - (idx / R) * R;
        g_XZ[(size_t)b * FEAT + offN + r] = f;
        const float s = wsum(f);
        const float q = wsum(f * f);
        const int wr = threadIdx.x >> 5, lane = threadIdx.x & 31;
        if (lane == 0) { sh[wr] = s; sh[4 + wr] = q; }
        __syncthreads();
        if (threadIdx.x == 0) {
            g_dpS[dpN + bid] = sh[0] + sh[1] + sh[2] + sh[3];
            g_dpQ[dpN + bid] = sh[4] + sh[5] + sh[6] + sh[7];
        }
    }
}

// ----------------------------------------------------------------------------
// All 10 down-sample reductions at once. grid = 10, block = 1024.
// ----------------------------------------------------------------------------
__global__ void k_dreduce_all(const float* __restrict__ dng, const float* __restrict__ dnbe,
                              const float* __restrict__ deg, const float* __restrict__ debe) {
    const int sgm = blockIdx.x;
    const bool node = sgm < 5;
    const int l = node ? sgm : sgm - 5;
    const int base = node ? (EDGET + l * 928) : (l * 29696);
    const int cnt = node ? 928 : 29696;
    const float invcnt = node ? (1.f / (float)(NB * R)) : (1.f / (float)(NB * R * 3));
    float s = 0.f, q = 0.f;
    for (int i = threadIdx.x; i < cnt; i += 1024) {
        s += g_dpS[base + i];
        q += g_dpQ[base + i];
    }
    __shared__ float shs[32], shq[32];
    s = wsum(s); q = wsum(q);
    const int w = threadIdx.x >> 5, lane = threadIdx.x & 31;
    if (lane == 0) { shs[w] = s; shq[w] = q; }
    __syncthreads();
    if (w == 0) {
        s = shs[lane]; q = shq[lane];
        s = wsum(s); q = wsum(q);
        if (lane == 0) {
            const float mean = s * invcnt;
            const float var = q * invcnt - mean * mean;
            const float rstd = rsqrtf(var + EPS);
            const float gg = node ? dng[l] : deg[l];
            const float bb = node ? dnbe[l] : debe[l];
            const float sc = rstd * gg;
            g_dssArr[2 * sgm]     = sc;
            g_dssArr[2 * sgm + 1] = bb - mean * sc;
        }
    }
}

// ----------------------------------------------------------------------------
// Classifier GEMM (tf32) with slab normalization folded into the A-load.
// ----------------------------------------------------------------------------
__global__ void __launch_bounds__(256)
k_cls(const float* __restrict__ A, const float* __restrict__ Bm,
      const float* __restrict__ bias, float* __restrict__ C)
{
    __shared__ float sA[2][128 * 20];
    __shared__ float sB[2][64 * 20];
    __shared__ float sbc[64];
    const int tid = threadIdx.x;
    const int wid = tid >> 5, lane = tid & 31;
    const int wm = wid >> 1, wn = wid & 1;
    const int g = lane >> 2, tig = lane & 3;
    const int row0 = blockIdx.y * 128, col0 = blockIdx.x * 64;

    if (tid < 64) sbc[tid] = bias[col0 + tid];

    float4 pa0, pa1, pb;
    float fsc, fsh;
    const int ar0 = tid >> 2, ac0 = (tid & 3) << 2;
    const int ar1 = (tid + 256) >> 2, ac1 = ac0;
    const int br = tid >> 2, bc = (tid & 3) << 2;

    auto fetch = [&](int k0) {
        const int k = k0 + ac0;
        const int sgm = (k < 580) ? (k / 116) : (5 + (k - 580) / 348);
        fsc = g_dssArr[2 * sgm];
        fsh = g_dssArr[2 * sgm + 1];
        pa0 = *(const float4*)(A + (size_t)(row0 + ar0) * FEAT + k0 + ac0);
        pa1 = *(const float4*)(A + (size_t)(row0 + ar1) * FEAT + k0 + ac1);
        pb  = *(const float4*)(Bm + (size_t)(col0 + br) * FEAT + k0 + bc);
    };
    auto store = [&](int buf) {
        float* d0 = &sA[buf][ar0 * 20 + ac0];
        d0[0] = to_tf32(fmaf(pa0.x, fsc, fsh)); d0[1] = to_tf32(fmaf(pa0.y, fsc, fsh));
        d0[2] = to_tf32(fmaf(pa0.z, fsc, fsh)); d0[3] = to_tf32(fmaf(pa0.w, fsc, fsh));
        float* d1 = &sA[buf][ar1 * 20 + ac1];
        d1[0] = to_tf32(fmaf(pa1.x, fsc, fsh)); d1[1] = to_tf32(fmaf(pa1.y, fsc, fsh));
        d1[2] = to_tf32(fmaf(pa1.z, fsc, fsh)); d1[3] = to_tf32(fmaf(pa1.w, fsc, fsh));
        float* d2 = &sB[buf][br * 20 + bc];
        d2[0] = to_tf32(pb.x); d2[1] = to_tf32(pb.y);
        d2[2] = to_tf32(pb.z); d2[3] = to_tf32(pb.w);
    };

    float acc[2][4][4];
#pragma unroll
    for (int mt = 0; mt < 2; mt++)
#pragma unroll
        for (int nt = 0; nt < 4; nt++)
#pragma unroll
            for (int i = 0; i < 4; i++) acc[mt][nt][i] = 0.f;

    const int NS = FEAT / 16;
    fetch(0);
    store(0);
    __syncthreads();
    int buf = 0;
    for (int ks = 0; ks < NS; ks++) {
        if (ks + 1 < NS) fetch((ks + 1) * 16);
#pragma unroll
        for (int kk = 0; kk < 2; kk++) {
            const int k0 = kk * 8;
            uint32_t af[2][4], bf[4][2];
#pragma unroll
            for (int mt = 0; mt < 2; mt++) {
                const float* p0 = &sA[buf][(wm * 32 + mt * 16 + g) * 20 + k0 + tig];
                af[mt][0] = __float_as_uint(p0[0]);
                af[mt][1] = __float_as_uint(p0[8 * 20]);
                af[mt][2] = __float_as_uint(p0[4]);
                af[mt][3] = __float_as_uint(p0[8 * 20 + 4]);
            }
#pragma unroll
            for (int nt = 0; nt < 4; nt++) {
                const float* p0 = &sB[buf][(wn * 32 + nt * 8 + g) * 20 + k0 + tig];
                bf[nt][0] = __float_as_uint(p0[0]);
                bf[nt][1] = __float_as_uint(p0[4]);
            }
#pragma unroll
            for (int mt = 0; mt < 2; mt++)
#pragma unroll
                for (int nt = 0; nt < 4; nt++)
                    mma8(acc[mt][nt], af[mt], bf[nt]);
        }
        if (ks + 1 < NS) store(buf ^ 1);
        __syncthreads();
        buf ^= 1;
    }

#pragma unroll
    for (int mt = 0; mt < 2; mt++)
#pragma unroll
        for (int h = 0; h < 2; h++) {
            const int row = row0 + wm * 32 + mt * 16 + g + 8 * h;
#pragma unroll
            for (int nt = 0; nt < 4; nt++) {
                const int col = wn * 32 + nt * 8 + 2 * tig;
                const float v0 = fmaxf(acc[mt][nt][2 * h] + sbc[col], 0.f);
                const float v1 = fmaxf(acc[mt][nt][2 * h + 1] + sbc[col + 1], 0.f);
                *(float2*)(C + (size_t)row * HID + col0 + col) = make_float2(v0, v1);
            }
        }
}

__global__ void k_out(const float* __restrict__ cw2, const float* __restrict__ cb2,
                      float* __restrict__ out) {
    const int b = blockIdx.x;
    const float* h = g_H + (size_t)b * HID;
    float a0 = 0.f, a1 = 0.f;
    for (int j = threadIdx.x; j < HID; j += 128) {
        const float hv = h[j];
        a0 = fmaf(hv, cw2[j], a0);
        a1 = fmaf(hv, cw2[HID + j], a1);
    }
    a0 = wsum(a0);
    a1 = wsum(a1);
    __shared__ float sh[8];
    const int w = threadIdx.x >> 5, lane = threadIdx.x & 31;
    if (lane == 0) { sh[w] = a0; sh[4 + w] = a1; }
    __syncthreads();
    if (threadIdx.x == 0) {
        out[b * 2 + 0] = sh[0] + sh[1] + sh[2] + sh[3] + cb2[0];
        out[b * 2 + 1] = sh[4] + sh[5] + sh[6] + sh[7] + cb2[1];
    }
}

// ----------------------------------------------------------------------------
// Host orchestration (graph-capturable: kernel launches only)
// ----------------------------------------------------------------------------
extern "C" void kernel_launch(void* const* d_in, const int* in_sizes, int n_in,
                              void* d_out, int out_size) {
    const float* X_in  = (const float*)d_in[0];
    const float* Z_in  = (const float*)d_in[1];
    const float* aw1   = (const float*)d_in[2];
    const float* ab1   = (const float*)d_in[3];
    const float* aw2   = (const float*)d_in[4];
    const float* ab2   = (const float*)d_in[5];
    const float* nw    = (const float*)d_in[6];
    const float* nb    = (const float*)d_in[7];
    const float* ew    = (const float*)d_in[8];
    const float* eb    = (const float*)d_in[9];
    const float* gn_g  = (const float*)d_in[10];
    const float* gn_b  = (const float*)d_in[11];
    const float* ge_g  = (const float*)d_in[12];
    const float* ge_b  = (const float*)d_in[13];
    const float* dn_w  = (const float*)d_in[14];
    const float* dn_b  = (const float*)d_in[15];
    const float* dn_g  = (const float*)d_in[16];
    const float* dn_be = (const float*)d_in[17];
    const float* de_w  = (const float*)d_in[18];
    const float* de_b  = (const float*)d_in[19];
    const float* de_g  = (const float*)d_in[20];
    const float* de_be = (const float*)d_in[21];
    const float* cw1   = (const float*)d_in[22];
    const float* cb1   = (const float*)d_in[23];
    const float* cw2   = (const float*)d_in[24];
    const float* cb2   = (const float*)d_in[25];
    float* out = (float*)d_out;

    cudaFuncSetAttribute(k_layer, cudaFuncAttributeMaxDynamicSharedMemorySize, SM_TOTB);

    float *pXZ, *pH;
    cudaGetSymbolAddress((void**)&pXZ, g_XZ);
    cudaGetSymbolAddress((void**)&pH,  g_H);

    // layer-0 down-sample, fused with input pass-through copy
    k_apply_down<<<29696 + 928, 128>>>(de_w, de_b, dn_w, dn_b,
                                       Z_in, X_in,
                                       580, 0, 0, EDGET, 0);

    for (int i = 0; i < LAYERS; i++) {
        k_layer<<<NB, LT, SM_TOTB>>>(aw2 + (size_t)i * RR, ab2 + i * R,
                                     aw1 + 9 * i, ab1 + 3 * i,
                                     ew + (size_t)i * RR, eb + i * R,
                                     nw + 9 * i, nb + 3 * i);
        k_reduce_both<<<2 * R, 256>>>(ge_g + i * R, ge_b + i * R,
                                      gn_g + i * R, gn_b + i * R);
        const int l = i + 1;
        k_apply_down<<<29696 + 928, 128>>>(de_w + 78 * l, de_b + l,
                                           dn_w + 3 * l, dn_b + l,
                                           nullptr, nullptr,
                                           580 + l * 348, l * R,
                                           l * 29696, EDGET + l * 928, 1);
    }

    k_dreduce_all<<<10, 1024>>>(dn_g, dn_be, de_g, de_be);
    k_cls<<<dim3(HID / 64, NB / 128), 256>>>(pXZ, cw1, cb1, pH);
    k_out<<<NB, 128>>>(cw2, cb2, out);
}

// round 11
// speedup vs baseline: 1.4947x; 1.1088x over previous
#include <cuda_runtime.h>
#include <cuda_fp16.h>
#include <cstddef>
#include <cstdint>

// ----------------------------------------------------------------------------
// Problem constants
// ----------------------------------------------------------------------------
#define NB 1024            // batch
#define R 116              // ROIs
#define RR (R * R)         // 13456
#define LAYERS 4
#define FEAT 2320          // R*4*(L+1)
#define HID 1024
#define EPS 1e-5f

#define SH 136             // smem tile row stride (halves) — LDSM conflict-free
#define REGH (128 * SH)    // halves per region (17408)

// down-sample partial slot layout
#define EDGET 148480       // 5 * 29696 edge partial slots
#define DPTOT 153120       // + 5 * 928 node slots

// ----------------------------------------------------------------------------
// Device scratch (static allocation only)
// ----------------------------------------------------------------------------
__device__ __align__(16) float  g_Z  [(size_t)NB * RR];
__device__ __align__(16) __half g_Z1h[(size_t)NB * RR];
__device__ __align__(16) float  g_X  [NB * R * 3];
__device__ __align__(16) float  g_X1 [NB * R * 3];
__device__ __align__(16) float  g_XZ [(size_t)NB * FEAT];
__device__ __align__(16) float  g_H  [(size_t)NB * HID];
__device__ float g_ps [R * NB];     // edge BN partials
__device__ float g_pq [R * NB];
__device__ float g_psN[R * NB];     // node BN partials
__device__ float g_pqN[R * NB];
__device__ float g_scale [R],  g_shift [R];   // edge BN affine
__device__ float g_scaleN[R],  g_shiftN[R];   // node BN affine
__device__ float g_dpS[DPTOT], g_dpQ[DPTOT];  // down-sample partials
__device__ float g_dssArr[20];                // 10 segments x (scale, shift)

__device__ __forceinline__ float wsum(float v) {
#pragma unroll
    for (int o = 16; o; o >>= 1) v += __shfl_xor_sync(0xffffffffu, v, o);
    return v;
}

__device__ __forceinline__ uint32_t sptr(const void* p) {
    return (uint32_t)__cvta_generic_to_shared(p);
}

// ldmatrix x4: loads 4 8x8 b16 tiles.
#define LDSM4(r0, r1, r2, r3, addr) \
    asm volatile("ldmatrix.sync.aligned.m8n8.x4.shared.b16 {%0,%1,%2,%3}, [%4];" \
                 : "=r"(r0), "=r"(r1), "=r"(r2), "=r"(r3) : "r"(addr))

// mma.sync m16n8k16 fp16 inputs, fp32 accumulate
__device__ __forceinline__ void mma16(float* d, const uint32_t* a, const uint32_t* b) {
    asm volatile(
        "mma.sync.aligned.m16n8k16.row.col.f32.f16.f16.f32 "
        "{%0,%1,%2,%3},{%4,%5,%6,%7},{%8,%9},{%0,%1,%2,%3};"
        : "+f"(d[0]), "+f"(d[1]), "+f"(d[2]), "+f"(d[3])
        : "r"(a[0]), "r"(a[1]), "r"(a[2]), "r"(a[3]), "r"(b[0]), "r"(b[1]));
}

// 128x128x128 NT GEMM over fp16 smem tiles (stride SH halves), 16 warps,
// warp tile 32x32, 8 k-steps of K=16. 4 LDSM.x4 + 8 MMA per k-step.
__device__ __forceinline__ void mm_loop(const __half* __restrict__ sA,
                                        const __half* __restrict__ sB,
                                        float (&acc)[2][4][4],
                                        int wm, int wn,
                                        uint32_t aOff, uint32_t bOff) {
    const uint32_t a0b = sptr(sA) + (uint32_t)(wm * 32 * SH * 2) + aOff;
    const uint32_t a1b = a0b + 16 * SH * 2;
    const uint32_t b0b = sptr(sB) + (uint32_t)(wn * 32 * SH * 2) + bOff;
    const uint32_t b1b = b0b + 16 * SH * 2;
#pragma unroll
    for (int ks = 0; ks < 8; ks++) {
        const uint32_t off = ks * 32;       // 16 halves = 32 bytes per k-step
        uint32_t af[2][4], bf[4][2];
        LDSM4(af[0][0], af[0][1], af[0][2], af[0][3], a0b + off);
        LDSM4(af[1][0], af[1][1], af[1][2], af[1][3], a1b + off);
        LDSM4(bf[0][0], bf[0][1], bf[1][0], bf[1][1], b0b + off);
        LDSM4(bf[2][0], bf[2][1], bf[3][0], bf[3][1], b1b + off);
#pragma unroll
        for (int mt = 0; mt < 2; mt++)
#pragma unroll
            for (int nt = 0; nt < 4; nt++)
                mma16(acc[mt][nt], af[mt], bf[nt]);
    }
}

// ----------------------------------------------------------------------------
// Mega layer kernel (fp16 tiles): one CTA per batch, 512 threads (16 warps).
// ----------------------------------------------------------------------------
#define HBYTES (3 * REGH * 2)      // 104448
#define EXT_B1 0
#define EXT_B2 128
#define EXT_KS 256                 // 352
#define EXT_XS 608                 // 352
#define EXT_PS 960                 // 512
#define EXT_PQ 1472                // 512
#define EXT_PA 1984                // 1536
#define EXT_TOT 3520
#define SM_TOTB (HBYTES + EXT_TOT * 4)   // 118528

#define LT 512

__global__ void __launch_bounds__(LT, 1)
k_layer(const float* __restrict__ aw2, const float* __restrict__ ab2,
        const float* __restrict__ aw1, const float* __restrict__ ab1,
        const float* __restrict__ ew,  const float* __restrict__ eb,
        const float* __restrict__ nw,  const float* __restrict__ nb_)
{
    extern __shared__ __align__(16) char smraw[];
    __half* hR1 = (__half*)smraw;            // Z -> Et
    __half* hR2 = hR1 + REGH;                // aw2 -> Mid1 -> ew
    __half* hR3 = hR2 + REGH;                // att -> S2
    float* fext = (float*)(smraw + HBYTES);
    float* sb1 = fext + EXT_B1;
    float* sb2 = fext + EXT_B2;
    float* sKs = fext + EXT_KS;
    float* sXs = fext + EXT_XS;
    float* pS  = fext + EXT_PS;
    float* pQ  = fext + EXT_PQ;
    float* pA  = fext + EXT_PA;

    const int tid = threadIdx.x;
    const int b = blockIdx.x;
    const int wid = tid >> 5, lane = tid & 31;
    const int wm = wid >> 2, wn = wid & 3;
    const int g = lane >> 2, tig = lane & 3;

    // ldmatrix per-lane byte offsets
    const uint32_t aOff = (uint32_t)((lane & 15) * SH * 2 + 16 * (lane >> 4));
    const uint32_t bOff = (uint32_t)(((lane & 7) + 8 * (lane >> 4)) * SH * 2 +
                                     16 * ((lane >> 3) & 1));

    // ---- phase 0: biases, X/Ks, pads, Z & aw2 loads (fp16) ----
    if (tid < 128) {
        sb1[tid] = (tid < R) ? ab2[tid] : 0.f;
        sb2[tid] = (tid < R) ? eb[tid] : 0.f;
    }
    if (tid < R) {
        const float* xp = g_X + (size_t)b * (R * 3) + tid * 3;
        const float y0 = xp[0], y1 = xp[1], y2 = xp[2];
        sXs[tid * 3 + 0] = y0; sXs[tid * 3 + 1] = y1; sXs[tid * 3 + 2] = y2;
#pragma unroll
        for (int o = 0; o < 3; o++)
            sKs[tid * 3 + o] = fmaf(aw1[o * 3 + 0], y0,
                                fmaf(aw1[o * 3 + 1], y1,
                                fmaf(aw1[o * 3 + 2], y2, ab1[o])));
    }
    // zero pad rows 116..127, cols 0..127: 12 rows x 16 uint4 per region
    {
        const uint4 z4u = make_uint4(0, 0, 0, 0);
        for (int idx = tid; idx < 3 * 192; idx += LT) {
            const int t = idx / 192, i2 = idx - t * 192;
            const int r = 116 + i2 / 16, c8 = (i2 & 15) * 8;
            *(uint4*)(hR1 + (size_t)t * REGH + r * SH + c8) = z4u;
        }
    }
    // zero pad cols 116..127 rows 0..115: 3 uint2 per row per region
    {
        const uint2 z2u = make_uint2(0, 0);
        for (int idx = tid; idx < 3 * 116; idx += LT) {
            const int t = idx / 116, r = idx - t * 116;
            uint2* p = (uint2*)(hR1 + (size_t)t * REGH + r * SH + 116);
            p[0] = z2u; p[1] = z2u; p[2] = z2u;
        }
    }
    // Z -> R1, aw2 -> R2 (fp16)
    {
        const float* Zb = g_Z + (size_t)b * RR;
        for (int idx = tid; idx < 116 * 29; idx += LT) {
            const int r = idx / 29;
            const int c = (idx - r * 29) << 2;
            const float4 vz = *(const float4*)(Zb + r * R + c);
            __half2* dz = (__half2*)(hR1 + r * SH + c);
            dz[0] = __floats2half2_rn(vz.x, vz.y);
            dz[1] = __floats2half2_rn(vz.z, vz.w);
            const float4 vw = *(const float4*)(aw2 + r * R + c);
            __half2* dw = (__half2*)(hR2 + r * SH + c);
            dw[0] = __floats2half2_rn(vw.x, vw.y);
            dw[1] = __floats2half2_rn(vw.z, vw.w);
        }
    }
    __syncthreads();

    // ---- attention -> R3 (fp16). No barrier needed before GEMM1. ----
    for (int n = wid; n < R; n += 16) {
        const float k0 = sKs[n * 3], k1 = sKs[n * 3 + 1], k2 = sKs[n * 3 + 2];
        float s[4];
        float mx = -3.0e38f;
#pragma unroll
        for (int it = 0; it < 4; it++) {
            const int m = it * 32 + lane;
            float v = -3.0e38f;
            if (m < R) v = k0 * sKs[m * 3] + k1 * sKs[m * 3 + 1] + k2 * sKs[m * 3 + 2];
            s[it] = v;
            mx = fmaxf(mx, v);
        }
#pragma unroll
        for (int o = 16; o; o >>= 1) mx = fmaxf(mx, __shfl_xor_sync(0xffffffffu, mx, o));
        float sum = 0.f, e[4];
#pragma unroll
        for (int it = 0; it < 4; it++) {
            const int m = it * 32 + lane;
            e[it] = (m < R) ? __expf(s[it] - mx) : 0.f;
            sum += e[it];
        }
        sum = wsum(sum);
        const float inv = 1.f / sum;
#pragma unroll
        for (int it = 0; it < 4; it++) {
            const int m = it * 32 + lane;
            if (m < R) hR3[n * SH + m] = __float2half_rn(e[it] * inv);
        }
    }

    float acc[2][4][4];
#pragma unroll
    for (int mt = 0; mt < 2; mt++)
#pragma unroll
        for (int nt = 0; nt < 4; nt++)
#pragma unroll
            for (int i = 0; i < 4; i++) acc[mt][nt][i] = 0.f;

    // ---- GEMM1: Mid1 = Z @ aw2^T ----
    mm_loop(hR1, hR2, acc, wm, wn, aOff, bOff);
    __syncthreads();

    // ---- Mid1 + ab2 -> R2 ----
#pragma unroll
    for (int mt = 0; mt < 2; mt++)
#pragma unroll
        for (int h = 0; h < 2; h++) {
            const int row = wm * 32 + mt * 16 + g + 8 * h;
#pragma unroll
            for (int nt = 0; nt < 4; nt++) {
                const int col = wn * 32 + nt * 8 + 2 * tig;
                if (col < 120)
                    *(__half2*)(hR2 + row * SH + col) =
                        __floats2half2_rn(acc[mt][nt][2 * h] + sb1[col],
                                          acc[mt][nt][2 * h + 1] + sb1[col + 1]);
            }
        }
#pragma unroll
    for (int mt = 0; mt < 2; mt++)
#pragma unroll
        for (int nt = 0; nt < 4; nt++)
#pragma unroll
            for (int i = 0; i < 4; i++) acc[mt][nt][i] = 0.f;
    __syncthreads();

    // ---- GEMM3: S2 = Mid1 @ att^T ----
    mm_loop(hR2, hR3, acc, wm, wn, aOff, bOff);
    __syncthreads();

    // ---- S2 -> R3 + node partials ; ew -> R2 ----
#pragma unroll
    for (int mt = 0; mt < 2; mt++)
#pragma unroll
        for (int h = 0; h < 2; h++) {
            const int row = wm * 32 + mt * 16 + g + 8 * h;
            float a0 = 0.f, a1 = 0.f, a2 = 0.f;
#pragma unroll
            for (int nt = 0; nt < 4; nt++) {
                const int col = wn * 32 + nt * 8 + 2 * tig;
                const float v0 = acc[mt][nt][2 * h];
                const float v1 = acc[mt][nt][2 * h + 1];
                if (col < 120)
                    *(__half2*)(hR3 + row * SH + col) = __floats2half2_rn(v0, v1);
                if (row < R && col < R) {
                    a0 = fmaf(v0, sXs[col * 3 + 0], fmaf(v1, sXs[col * 3 + 3], a0));
                    a1 = fmaf(v0, sXs[col * 3 + 1], fmaf(v1, sXs[col * 3 + 4], a1));
                    a2 = fmaf(v0, sXs[col * 3 + 2], fmaf(v1, sXs[col * 3 + 5], a2));
                }
            }
            a0 += __shfl_xor_sync(0xffffffffu, a0, 1);
            a0 += __shfl_xor_sync(0xffffffffu, a0, 2);
            a1 += __shfl_xor_sync(0xffffffffu, a1, 1);
            a1 += __shfl_xor_sync(0xffffffffu, a1, 2);
            a2 += __shfl_xor_sync(0xffffffffu, a2, 1);
            a2 += __shfl_xor_sync(0xffffffffu, a2, 2);
            if (tig == 0) {
                pA[0 * 512 + wn * 128 + row] = a0;
                pA[1 * 512 + wn * 128 + row] = a1;
                pA[2 * 512 + wn * 128 + row] = a2;
            }
        }
    for (int idx = tid; idx < 116 * 29; idx += LT) {
        const int r = idx / 29;
        const int c = (idx - r * 29) << 2;
        const float4 v = *(const float4*)(ew + r * R + c);
        __half2* d = (__half2*)(hR2 + r * SH + c);
        d[0] = __floats2half2_rn(v.x, v.y);
        d[1] = __floats2half2_rn(v.z, v.w);
    }
#pragma unroll
    for (int mt = 0; mt < 2; mt++)
#pragma unroll
        for (int nt = 0; nt < 4; nt++)
#pragma unroll
            for (int i = 0; i < 4; i++) acc[mt][nt][i] = 0.f;
    __syncthreads();

    // ---- GEMM2: Et = ew @ Z^T ----
    mm_loop(hR2, hR1, acc, wm, wn, aOff, bOff);
    __syncthreads();

    // ---- Et -> R1 ----
#pragma unroll
    for (int mt = 0; mt < 2; mt++)
#pragma unroll
        for (int h = 0; h < 2; h++) {
            const int row = wm * 32 + mt * 16 + g + 8 * h;
#pragma unroll
            for (int nt = 0; nt < 4; nt++) {
                const int col = wn * 32 + nt * 8 + 2 * tig;
                if (col < 120)
                    *(__half2*)(hR1 + row * SH + col) =
                        __floats2half2_rn(acc[mt][nt][2 * h], acc[mt][nt][2 * h + 1]);
            }
        }
#pragma unroll
    for (int mt = 0; mt < 2; mt++)
#pragma unroll
        for (int nt = 0; nt < 4; nt++)
#pragma unroll
            for (int i = 0; i < 4; i++) acc[mt][nt][i] = 0.f;
    __syncthreads();

    // ---- GEMM4: Z1 = S2 @ Et^T + eb ----
    mm_loop(hR3, hR1, acc, wm, wn, aOff, bOff);

    // ---- epilogue: Z1 (fp16) + edge stats (fp32, pre-rounding) ----
    __half* Cb = g_Z1h + (size_t)b * RR;
#pragma unroll
    for (int mt = 0; mt < 2; mt++) {
#pragma unroll
        for (int h = 0; h < 2; h++) {
            const int row = wm * 32 + mt * 16 + g + 8 * h;
            float s = 0.f, q = 0.f;
#pragma unroll
            for (int nt = 0; nt < 4; nt++) {
                const int col = wn * 32 + nt * 8 + 2 * tig;
                if (col < R) {
                    const float v0 = acc[mt][nt][2 * h] + sb2[col];
                    const float v1 = acc[mt][nt][2 * h + 1] + sb2[col + 1];
                    if (row < R)
                        *(__half2*)(Cb + (size_t)row * R + col) =
                            __floats2half2_rn(v0, v1);
                    s += v0 + v1;
                    q += v0 * v0 + v1 * v1;
                }
            }
            s += __shfl_xor_sync(0xffffffffu, s, 1);
            s += __shfl_xor_sync(0xffffffffu, s, 2);
            q += __shfl_xor_sync(0xffffffffu, q, 1);
            q += __shfl_xor_sync(0xffffffffu, q, 2);
            if (tig == 0) { pS[wn * 128 + row] = s; pQ[wn * 128 + row] = q; }
        }
    }
    __syncthreads();
    if (tid < R) {
        const float s = pS[tid] + pS[128 + tid] + pS[256 + tid] + pS[384 + tid];
        const float q = pQ[tid] + pQ[128 + tid] + pQ[256 + tid] + pQ[384 + tid];
        g_ps[tid * NB + b] = s;
        g_pq[tid * NB + b] = q;
    }
    // ---- node path finish: X1 = (S2 @ X) @ nw^T + nb, node stats ----
    if (tid < R) {
        const int n = tid;
        const float a0 = pA[0 * 512 + n] + pA[0 * 512 + 128 + n] +
                         pA[0 * 512 + 256 + n] + pA[0 * 512 + 384 + n];
        const float a1 = pA[1 * 512 + n] + pA[1 * 512 + 128 + n] +
                         pA[1 * 512 + 256 + n] + pA[1 * 512 + 384 + n];
        const float a2 = pA[2 * 512 + n] + pA[2 * 512 + 128 + n] +
                         pA[2 * 512 + 256 + n] + pA[2 * 512 + 384 + n];
        float ps = 0.f, pq = 0.f;
        float* dst = g_X1 + (size_t)b * (R * 3) + n * 3;
#pragma unroll
        for (int o = 0; o < 3; o++) {
            const float v = fmaf(nw[o * 3 + 0], a0,
                            fmaf(nw[o * 3 + 1], a1,
                            fmaf(nw[o * 3 + 2], a2, nb_[o])));
            dst[o] = v;
            ps += v;
            pq = fmaf(v, v, pq);
        }
        g_psN[n * NB + b] = ps;
        g_pqN[n * NB + b] = pq;
    }
}

// ----------------------------------------------------------------------------
// Both BN channel reductions in one launch. grid = 2R, block = 256.
// ----------------------------------------------------------------------------
__global__ void k_reduce_both(const float* __restrict__ geg, const float* __restrict__ geb,
                              const float* __restrict__ gng, const float* __restrict__ gnb) {
    const bool edge = blockIdx.x < R;
    const int n = edge ? blockIdx.x : blockIdx.x - R;
    const float* PS = edge ? g_ps : g_psN;
    const float* PQ = edge ? g_pq : g_pqN;
    float s = 0.f, q = 0.f;
    for (int b = threadIdx.x; b < NB; b += 256) {
        s += PS[n * NB + b];
        q += PQ[n * NB + b];
    }
    __shared__ float shs[8], shq[8];
    s = wsum(s); q = wsum(q);
    const int w = threadIdx.x >> 5, lane = threadIdx.x & 31;
    if (lane == 0) { shs[w] = s; shq[w] = q; }
    __syncthreads();
    if (w == 0) {
        s = (lane < 8) ? shs[lane] : 0.f;
        q = (lane < 8) ? shq[lane] : 0.f;
        s = wsum(s); q = wsum(q);
        if (lane == 0) {
            const float invcnt = edge ? (1.f / (float)(NB * R)) : (1.f / (float)(3 * NB));
            const float mean = s * invcnt;
            const float var = q * invcnt - mean * mean;
            const float rstd = rsqrtf(var + EPS);
            const float gg = edge ? geg[n] : gng[n];
            const float bb = edge ? geb[n] : gnb[n];
            const float sc = rstd * gg;
            if (edge) { g_scale[n] = sc;  g_shift[n] = bb - mean * sc; }
            else      { g_scaleN[n] = sc; g_shiftN[n] = bb - mean * sc; }
        }
    }
}

// ----------------------------------------------------------------------------
// Combined: Z+=relu(bn(Z1h)) & down-edge  /  X+=relu(bn(X1)) & down-node.
// apply==0: pass-through copy from srcZ/srcX into g_Z/g_X (layer 0).
// grid = 29696 + 928, block = 128. Conv weights in registers (no smem stage).
// ----------------------------------------------------------------------------
__global__ void k_apply_down(const float* __restrict__ dew, const float* __restrict__ deb,
                             const float* __restrict__ dnw, const float* __restrict__ dnb,
                             const float* __restrict__ srcZ, const float* __restrict__ srcX,
                             int offE, int offN, int dpE, int dpN, int apply) {
    __shared__ float sh[8];
    if (blockIdx.x < 29696) {
        // ---------------- edge ----------------
        const int wrp = threadIdx.x >> 5, lane = threadIdx.x & 31;
        const int rowid = blockIdx.x * 4 + wrp;
        const int b = rowid / R, n = rowid - b * R;
        // per-lane conv weights (register-resident, L2/const cached)
        float w0[4], w1[4], w2[4];
#pragma unroll
        for (int d = 0; d < 4; d++) {
            const int e = 4 * lane + d;
            w1[d] = (e < 78) ? dew[e] : 0.f;
            w0[d] = (e < 39) ? dew[39 + e] : 0.f;
            w2[d] = (e >= 39 && e < 116) ? dew[e - 39] : 0.f;
        }
        float4 v = make_float4(0.f, 0.f, 0.f, 0.f);
        float* zrow = g_Z + (size_t)rowid * R;
        if (lane < 29) {
            if (apply) {
                v = *(float4*)(zrow + 4 * lane);
                const __half2* urow = (const __half2*)(g_Z1h + (size_t)rowid * R);
                const float2 u01 = __half22float2(urow[2 * lane]);
                const float2 u23 = __half22float2(urow[2 * lane + 1]);
                const float sc = g_scale[n], sf = g_shift[n];
                v.x += fmaxf(fmaf(u01.x, sc, sf), 0.f);
                v.y += fmaxf(fmaf(u01.y, sc, sf), 0.f);
                v.z += fmaxf(fmaf(u23.x, sc, sf), 0.f);
                v.w += fmaxf(fmaf(u23.y, sc, sf), 0.f);
                *(float4*)(zrow + 4 * lane) = v;
            } else {
                v = *(const float4*)(srcZ + (size_t)rowid * R + 4 * lane);
                *(float4*)(zrow + 4 * lane) = v;
            }
        }
        float f0 = 0.f, f1 = 0.f, f2 = 0.f;
        const float vv[4] = {v.x, v.y, v.z, v.w};
#pragma unroll
        for (int d = 0; d < 4; d++) {
            f1 = fmaf(vv[d], w1[d], f1);
            f0 = fmaf(vv[d], w0[d], f0);
            f2 = fmaf(vv[d], w2[d], f2);
        }
        f0 = wsum(f0); f1 = wsum(f1); f2 = wsum(f2);
        float s = 0.f, q = 0.f;
        if (lane == 0) {
            const float bb = deb[0];
            f0 = fmaxf(f0 + bb, 0.f);
            f1 = fmaxf(f1 + bb, 0.f);
            f2 = fmaxf(f2 + bb, 0.f);
            float* dst = g_XZ + (size_t)b * FEAT + offE + n * 3;
            dst[0] = f0; dst[1] = f1; dst[2] = f2;
            s = f0 + f1 + f2;
            q = f0 * f0 + f1 * f1 + f2 * f2;
            sh[wrp] = s; sh[4 + wrp] = q;
        }
        __syncthreads();
        if (threadIdx.x == 0) {
            g_dpS[dpE + blockIdx.x] = sh[0] + sh[1] + sh[2] + sh[3];
            g_dpQ[dpE + blockIdx.x] = sh[4] + sh[5] + sh[6] + sh[7];
        }
    } else {
        // ---------------- node ----------------
        const int bid = blockIdx.x - 29696;
        const int idx = bid * 128 + threadIdx.x;
        float* xp = g_X + (size_t)idx * 3;
        float x0, x1, x2;
        if (apply) {
            x0 = xp[0]; x1 = xp[1]; x2 = xp[2];
            const int n = idx % R;
            const float sc = g_scaleN[n], sf = g_shiftN[n];
            const float* up = g_X1 + (size_t)idx * 3;
            x0 += fmaxf(fmaf(up[0], sc, sf), 0.f);
            x1 += fmaxf(fmaf(up[1], sc, sf), 0.f);
            x2 += fmaxf(fmaf(up[2], sc, sf), 0.f);
            xp[0] = x0; xp[1] = x1; xp[2] = x2;
        } else {
            const float* sp = srcX + (size_t)idx * 3;
            x0 = sp[0]; x1 = sp[1]; x2 = sp[2];
            xp[0] = x0; xp[1] = x1; xp[2] = x2;
        }
        const float f = fmaxf(fmaf(x0, dnw[0], fmaf(x1, dnw[1], fmaf(x2, dnw[2], dnb[0]))), 0.f);
        const int b = idx / R, r = idx - (idx / R) * R;
        g_XZ[(size_t)b * FEAT + offN + r] = f;
        const float s = wsum(f);
        const float q = wsum(f * f);
        const int wr = threadIdx.x >> 5, lane = threadIdx.x & 31;
        if (lane == 0) { sh[wr] = s; sh[4 + wr] = q; }
        __syncthreads();
        if (threadIdx.x == 0) {
            g_dpS[dpN + bid] = sh[0] + sh[1] + sh[2] + sh[3];
            g_dpQ[dpN + bid] = sh[4] + sh[5] + sh[6] + sh[7];
        }
    }
}

// ----------------------------------------------------------------------------
// All 10 down-sample reductions at once. grid = 10, block = 1024.
// ----------------------------------------------------------------------------
__global__ void k_dreduce_all(const float* __restrict__ dng, const float* __restrict__ dnbe,
                              const float* __restrict__ deg, const float* __restrict__ debe) {
    const int sgm = blockIdx.x;
    const bool node = sgm < 5;
    const int l = node ? sgm : sgm - 5;
    const int base = node ? (EDGET + l * 928) : (l * 29696);
    const int cnt = node ? 928 : 29696;
    const float invcnt = node ? (1.f / (float)(NB * R)) : (1.f / (float)(NB * R * 3));
    float s = 0.f, q = 0.f;
    for (int i = threadIdx.x; i < cnt; i += 1024) {
        s += g_dpS[base + i];
        q += g_dpQ[base + i];
    }
    __shared__ float shs[32], shq[32];
    s = wsum(s); q = wsum(q);
    const int w = threadIdx.x >> 5, lane = threadIdx.x & 31;
    if (lane == 0) { shs[w] = s; shq[w] = q; }
    __syncthreads();
    if (w == 0) {
        s = shs[lane]; q = shq[lane];
        s = wsum(s); q = wsum(q);
        if (lane == 0) {
            const float mean = s * invcnt;
            const float var = q * invcnt - mean * mean;
            const float rstd = rsqrtf(var + EPS);
            const float gg = node ? dng[l] : deg[l];
            const float bb = node ? dnbe[l] : debe[l];
            const float sc = rstd * gg;
            g_dssArr[2 * sgm]     = sc;
            g_dssArr[2 * sgm + 1] = bb - mean * sc;
        }
    }
}

// ----------------------------------------------------------------------------
// Classifier GEMM (fp16, m16n8k16) with slab normalization folded into A-load.
// Tile 128x64, BK=16 double-buffered, 8 warps (4x2), warp tile 32x32.
// smem stride 24 halves (48B rows): conflict-free LDS.32 fragments.
// ----------------------------------------------------------------------------
#define CSTR 24

__global__ void __launch_bounds__(256)
k_cls(const float* __restrict__ A, const float* __restrict__ Bm,
      const float* __restrict__ bias, float* __restrict__ C)
{
    __shared__ __half sA[2][128 * CSTR];
    __shared__ __half sB[2][64 * CSTR];
    __shared__ float sbc[64];
    const int tid = threadIdx.x;
    const int wid = tid >> 5, lane = tid & 31;
    const int wm = wid >> 1, wn = wid & 1;
    const int g = lane >> 2, tig = lane & 3;
    const int row0 = blockIdx.y * 128, col0 = blockIdx.x * 64;

    if (tid < 64) sbc[tid] = bias[col0 + tid];

    float4 pa0, pa1, pb;
    float fsc, fsh;
    const int ar0 = tid >> 2, ac0 = (tid & 3) << 2;
    const int ar1 = (tid + 256) >> 2, ac1 = ac0;
    const int br = tid >> 2, bc = (tid & 3) << 2;

    auto fetch = [&](int k0) {
        const int k = k0 + ac0;
        const int sgm = (k < 580) ? (k / 116) : (5 + (k - 580) / 348);
        fsc = g_dssArr[2 * sgm];
        fsh = g_dssArr[2 * sgm + 1];
        pa0 = *(const float4*)(A + (size_t)(row0 + ar0) * FEAT + k0 + ac0);
        pa1 = *(const float4*)(A + (size_t)(row0 + ar1) * FEAT + k0 + ac1);
        pb  = *(const float4*)(Bm + (size_t)(col0 + br) * FEAT + k0 + bc);
    };
    auto store = [&](int buf) {
        __half2* d0 = (__half2*)&sA[buf][ar0 * CSTR + ac0];
        d0[0] = __floats2half2_rn(fmaf(pa0.x, fsc, fsh), fmaf(pa0.y, fsc, fsh));
        d0[1] = __floats2half2_rn(fmaf(pa0.z, fsc, fsh), fmaf(pa0.w, fsc, fsh));
        __half2* d1 = (__half2*)&sA[buf][ar1 * CSTR + ac1];
        d1[0] = __floats2half2_rn(fmaf(pa1.x, fsc, fsh), fmaf(pa1.y, fsc, fsh));
        d1[1] = __floats2half2_rn(fmaf(pa1.z, fsc, fsh), fmaf(pa1.w, fsc, fsh));
        __half2* d2 = (__half2*)&sB[buf][br * CSTR + bc];
        d2[0] = __floats2half2_rn(pb.x, pb.y);
        d2[1] = __floats2half2_rn(pb.z, pb.w);
    };

    float acc[2][4][4];
#pragma unroll
    for (int mt = 0; mt < 2; mt++)
#pragma unroll
        for (int nt = 0; nt < 4; nt++)
#pragma unroll
            for (int i = 0; i < 4; i++) acc[mt][nt][i] = 0.f;

    const int NS = FEAT / 16;   // 145
    fetch(0);
    store(0);
    __syncthreads();
    int buf = 0;
    for (int ks = 0; ks < NS; ks++) {
        if (ks + 1 < NS) fetch((ks + 1) * 16);
        uint32_t af[2][4], bf[4][2];
#pragma unroll
        for (int mt = 0; mt < 2; mt++) {
            const __half* p0 = &sA[buf][(wm * 32 + mt * 16 + g) * CSTR + 2 * tig];
            af[mt][0] = *(const uint32_t*)(p0);
            af[mt][1] = *(const uint32_t*)(p0 + 8 * CSTR);
            af[mt][2] = *(const uint32_t*)(p0 + 8);
            af[mt][3] = *(const uint32_t*)(p0 + 8 * CSTR + 8);
        }
#pragma unroll
        for (int nt = 0; nt < 4; nt++) {
            const __half* q0 = &sB[buf][(wn * 32 + nt * 8 + g) * CSTR + 2 * tig];
            bf[nt][0] = *(const uint32_t*)(q0);
            bf[nt][1] = *(const uint32_t*)(q0 + 8);
        }
#pragma unroll
        for (int mt = 0; mt < 2; mt++)
#pragma unroll
            for (int nt = 0; nt < 4; nt++)
                mma16(acc[mt][nt], af[mt], bf[nt]);
        if (ks + 1 < NS) store(buf ^ 1);
        __syncthreads();
        buf ^= 1;
    }

#pragma unroll
    for (int mt = 0; mt < 2; mt++)
#pragma unroll
        for (int h = 0; h < 2; h++) {
            const int row = row0 + wm * 32 + mt * 16 + g + 8 * h;
#pragma unroll
            for (int nt = 0; nt < 4; nt++) {
                const int col = wn * 32 + nt * 8 + 2 * tig;
                const float v0 = fmaxf(acc[mt][nt][2 * h] + sbc[col], 0.f);
                const float v1 = fmaxf(acc[mt][nt][2 * h + 1] + sbc[col + 1], 0.f);
                *(float2*)(C + (size_t)row * HID + col0 + col) = make_float2(v0, v1);
            }
        }
}

__global__ void k_out(const float* __restrict__ cw2, const float* __restrict__ cb2,
                      float* __restrict__ out) {
    const int b = blockIdx.x;
    const float* h = g_H + (size_t)b * HID;
    float a0 = 0.f, a1 = 0.f;
    for (int j = threadIdx.x; j < HID; j += 128) {
        const float hv = h[j];
        a0 = fmaf(hv, cw2[j], a0);
        a1 = fmaf(hv, cw2[HID + j], a1);
    }
    a0 = wsum(a0);
    a1 = wsum(a1);
    __shared__ float sh[8];
    const int w = threadIdx.x >> 5, lane = threadIdx.x & 31;
    if (lane == 0) { sh[w] = a0; sh[4 + w] = a1; }
    __syncthreads();
    if (threadIdx.x == 0) {
        out[b * 2 + 0] = sh[0] + sh[1] + sh[2] + sh[3] + cb2[0];
        out[b * 2 + 1] = sh[4] + sh[5] + sh[6] + sh[7] + cb2[1];
    }
}

// ----------------------------------------------------------------------------
// Host orchestration (graph-capturable: kernel launches only)
// ----------------------------------------------------------------------------
extern "C" void kernel_launch(void* const* d_in, const int* in_sizes, int n_in,
                              void* d_out, int out_size) {
    const float* X_in  = (const float*)d_in[0];
    const float* Z_in  = (const float*)d_in[1];
    const float* aw1   = (const float*)d_in[2];
    const float* ab1   = (const float*)d_in[3];
    const float* aw2   = (const float*)d_in[4];
    const float* ab2   = (const float*)d_in[5];
    const float* nw    = (const float*)d_in[6];
    const float* nb    = (const float*)d_in[7];
    const float* ew    = (const float*)d_in[8];
    const float* eb    = (const float*)d_in[9];
    const float* gn_g  = (const float*)d_in[10];
    const float* gn_b  = (const float*)d_in[11];
    const float* ge_g  = (const float*)d_in[12];
    const float* ge_b  = (const float*)d_in[13];
    const float* dn_w  = (const float*)d_in[14];
    const float* dn_b  = (const float*)d_in[15];
    const float* dn_g  = (const float*)d_in[16];
    const float* dn_be = (const float*)d_in[17];
    const float* de_w  = (const float*)d_in[18];
    const float* de_b  = (const float*)d_in[19];
    const float* de_g  = (const float*)d_in[20];
    const float* de_be = (const float*)d_in[21];
    const float* cw1   = (const float*)d_in[22];
    const float* cb1   = (const float*)d_in[23];
    const float* cw2   = (const float*)d_in[24];
    const float* cb2   = (const float*)d_in[25];
    float* out = (float*)d_out;

    cudaFuncSetAttribute(k_layer, cudaFuncAttributeMaxDynamicSharedMemorySize, SM_TOTB);

    float *pXZ, *pH;
    cudaGetSymbolAddress((void**)&pXZ, g_XZ);
    cudaGetSymbolAddress((void**)&pH,  g_H);

    // layer-0 down-sample, fused with input pass-through copy
    k_apply_down<<<29696 + 928, 128>>>(de_w, de_b, dn_w, dn_b,
                                       Z_in, X_in,
                                       580, 0, 0, EDGET, 0);

    for (int i = 0; i < LAYERS; i++) {
        k_layer<<<NB, LT, SM_TOTB>>>(aw2 + (size_t)i * RR, ab2 + i * R,
                                     aw1 + 9 * i, ab1 + 3 * i,
                                     ew + (size_t)i * RR, eb + i * R,
                                     nw + 9 * i, nb + 3 * i);
        k_reduce_both<<<2 * R, 256>>>(ge_g + i * R, ge_b + i * R,
                                      gn_g + i * R, gn_b + i * R);
        const int l = i + 1;
        k_apply_down<<<29696 + 928, 128>>>(de_w + 78 * l, de_b + l,
                                           dn_w + 3 * l, dn_b + l,
                                           nullptr, nullptr,
                                           580 + l * 348, l * R,
                                           l * 29696, EDGET + l * 928, 1);
    }

    k_dreduce_all<<<10, 1024>>>(dn_g, dn_be, de_g, de_be);
    k_cls<<<dim3(HID / 64, NB / 128), 256>>>(pXZ, cw1, cb1, pH);
    k_out<<<NB, 128>>>(cw2, cb2, out);
}

// round 12
// speedup vs baseline: 1.5816x; 1.0581x over previous
#include <cuda_runtime.h>
#include <cuda_fp16.h>
#include <cstddef>
#include <cstdint>

// ----------------------------------------------------------------------------
// Problem constants
// ----------------------------------------------------------------------------
#define NB 1024            // batch
#define R 116              // ROIs
#define RR (R * R)         // 13456
#define LAYERS 4
#define FEAT 2320          // R*4*(L+1)
#define HID 1024
#define EPS 1e-5f

#define SH 136             // smem tile row stride (halves) — LDSM conflict-free
#define REGH (128 * SH)    // halves per region (17408)

// down-sample partial slot layout
#define EDGET 148480       // 5 * 29696 edge partial slots
#define DPTOT 153120       // + 5 * 928 node slots

// ----------------------------------------------------------------------------
// Device scratch (static allocation only)
// ----------------------------------------------------------------------------
__device__ __align__(16) __half g_Zh [(size_t)NB * RR];   // carried Z (fp16)
__device__ __align__(16) __half g_Z1h[(size_t)NB * RR];
__device__ __align__(16) __half g_wh [(size_t)2 * LAYERS * RR]; // aw2 | ew (fp16)
__device__ __align__(16) float  g_X  [NB * R * 3];
__device__ __align__(16) float  g_X1 [NB * R * 3];
__device__ __align__(16) float  g_XZ [(size_t)NB * FEAT];
__device__ __align__(16) float  g_H  [(size_t)NB * HID];
__device__ float g_ps [R * NB];     // edge BN partials
__device__ float g_pq [R * NB];
__device__ float g_psN[R * NB];     // node BN partials
__device__ float g_pqN[R * NB];
__device__ float g_scale [R],  g_shift [R];   // edge BN affine
__device__ float g_scaleN[R],  g_shiftN[R];   // node BN affine
__device__ float g_dpS[DPTOT], g_dpQ[DPTOT];  // down-sample partials
__device__ float g_dssArr[20];                // 10 segments x (scale, shift)

__device__ __forceinline__ float wsum(float v) {
#pragma unroll
    for (int o = 16; o; o >>= 1) v += __shfl_xor_sync(0xffffffffu, v, o);
    return v;
}

__device__ __forceinline__ uint32_t sptr(const void* p) {
    return (uint32_t)__cvta_generic_to_shared(p);
}

// ldmatrix x4: loads 4 8x8 b16 tiles.
#define LDSM4(r0, r1, r2, r3, addr) \
    asm volatile("ldmatrix.sync.aligned.m8n8.x4.shared.b16 {%0,%1,%2,%3}, [%4];" \
                 : "=r"(r0), "=r"(r1), "=r"(r2), "=r"(r3) : "r"(addr))

// mma.sync m16n8k16 fp16 inputs, fp32 accumulate
__device__ __forceinline__ void mma16(float* d, const uint32_t* a, const uint32_t* b) {
    asm volatile(
        "mma.sync.aligned.m16n8k16.row.col.f32.f16.f16.f32 "
        "{%0,%1,%2,%3},{%4,%5,%6,%7},{%8,%9},{%0,%1,%2,%3};"
        : "+f"(d[0]), "+f"(d[1]), "+f"(d[2]), "+f"(d[3])
        : "r"(a[0]), "r"(a[1]), "r"(a[2]), "r"(a[3]), "r"(b[0]), "r"(b[1]));
}

// 128x128x128 NT GEMM over fp16 smem tiles (stride SH halves), 16 warps,
// warp tile 32x32, 8 k-steps of K=16. 4 LDSM.x4 + 8 MMA per k-step.
__device__ __forceinline__ void mm_loop(const __half* __restrict__ sA,
                                        const __half* __restrict__ sB,
                                        float (&acc)[2][4][4],
                                        int wm, int wn,
                                        uint32_t aOff, uint32_t bOff) {
    const uint32_t a0b = sptr(sA) + (uint32_t)(wm * 32 * SH * 2) + aOff;
    const uint32_t a1b = a0b + 16 * SH * 2;
    const uint32_t b0b = sptr(sB) + (uint32_t)(wn * 32 * SH * 2) + bOff;
    const uint32_t b1b = b0b + 16 * SH * 2;
#pragma unroll
    for (int ks = 0; ks < 8; ks++) {
        const uint32_t off = ks * 32;       // 16 halves = 32 bytes per k-step
        uint32_t af[2][4], bf[4][2];
        LDSM4(af[0][0], af[0][1], af[0][2], af[0][3], a0b + off);
        LDSM4(af[1][0], af[1][1], af[1][2], af[1][3], a1b + off);
        LDSM4(bf[0][0], bf[0][1], bf[1][0], bf[1][1], b0b + off);
        LDSM4(bf[2][0], bf[2][1], bf[3][0], bf[3][1], b1b + off);
#pragma unroll
        for (int mt = 0; mt < 2; mt++)
#pragma unroll
            for (int nt = 0; nt < 4; nt++)
                mma16(acc[mt][nt], af[mt], bf[nt]);
    }
}

// ----------------------------------------------------------------------------
// One-time weight conversion: aw2 (L*RR) then ew (L*RR) -> g_wh (fp16)
// ----------------------------------------------------------------------------
__global__ void k_cvtw(const float* __restrict__ aw2, const float* __restrict__ ew) {
    const int i = blockIdx.x * 256 + threadIdx.x;
    const int N = LAYERS * RR;
    if (i < N) g_wh[i] = __float2half_rn(aw2[i]);
    else if (i < 2 * N) g_wh[i] = __float2half_rn(ew[i - N]);
}

// ----------------------------------------------------------------------------
// Mega layer kernel (fp16 tiles): one CTA per batch, 512 threads (16 warps).
// ----------------------------------------------------------------------------
#define HBYTES (3 * REGH * 2)      // 104448
#define EXT_B1 0
#define EXT_B2 128
#define EXT_KS 256                 // 352
#define EXT_XS 608                 // 352
#define EXT_PS 960                 // 512
#define EXT_PQ 1472                // 512
#define EXT_PA 1984                // 1536
#define EXT_TOT 3520
#define SM_TOTB (HBYTES + EXT_TOT * 4)   // 118528

#define LT 512

__global__ void __launch_bounds__(LT, 1)
k_layer(const __half* __restrict__ aw2h, const float* __restrict__ ab2,
        const float* __restrict__ aw1, const float* __restrict__ ab1,
        const __half* __restrict__ ewh,  const float* __restrict__ eb,
        const float* __restrict__ nw,  const float* __restrict__ nb_)
{
    extern __shared__ __align__(16) char smraw[];
    __half* hR1 = (__half*)smraw;            // Z -> Et
    __half* hR2 = hR1 + REGH;                // aw2 -> Mid1 -> ew
    __half* hR3 = hR2 + REGH;                // att -> S2
    float* fext = (float*)(smraw + HBYTES);
    float* sb1 = fext + EXT_B1;
    float* sb2 = fext + EXT_B2;
    float* sKs = fext + EXT_KS;
    float* sXs = fext + EXT_XS;
    float* pS  = fext + EXT_PS;
    float* pQ  = fext + EXT_PQ;
    float* pA  = fext + EXT_PA;

    const int tid = threadIdx.x;
    const int b = blockIdx.x;
    const int wid = tid >> 5, lane = tid & 31;
    const int wm = wid >> 2, wn = wid & 3;
    const int g = lane >> 2, tig = lane & 3;

    // ldmatrix per-lane byte offsets
    const uint32_t aOff = (uint32_t)((lane & 15) * SH * 2 + 16 * (lane >> 4));
    const uint32_t bOff = (uint32_t)(((lane & 7) + 8 * (lane >> 4)) * SH * 2 +
                                     16 * ((lane >> 3) & 1));

    // ---- phase 0: biases, X/Ks, pads, Z & aw2 loads (fp16 copies) ----
    if (tid < 128) {
        sb1[tid] = (tid < R) ? ab2[tid] : 0.f;
        sb2[tid] = (tid < R) ? eb[tid] : 0.f;
    }
    if (tid < R) {
        const float* xp = g_X + (size_t)b * (R * 3) + tid * 3;
        const float y0 = xp[0], y1 = xp[1], y2 = xp[2];
        sXs[tid * 3 + 0] = y0; sXs[tid * 3 + 1] = y1; sXs[tid * 3 + 2] = y2;
#pragma unroll
        for (int o = 0; o < 3; o++)
            sKs[tid * 3 + o] = fmaf(aw1[o * 3 + 0], y0,
                                fmaf(aw1[o * 3 + 1], y1,
                                fmaf(aw1[o * 3 + 2], y2, ab1[o])));
    }
    // zero pad rows 116..127, cols 0..127: 12 rows x 16 uint4 per region
    {
        const uint4 z4u = make_uint4(0, 0, 0, 0);
        for (int idx = tid; idx < 3 * 192; idx += LT) {
            const int t = idx / 192, i2 = idx - t * 192;
            const int r = 116 + i2 / 16, c8 = (i2 & 15) * 8;
            *(uint4*)(hR1 + (size_t)t * REGH + r * SH + c8) = z4u;
        }
    }
    // zero pad cols 116..127 rows 0..115: 3 uint2 per row per region
    {
        const uint2 z2u = make_uint2(0, 0);
        for (int idx = tid; idx < 3 * 116; idx += LT) {
            const int t = idx / 116, r = idx - t * 116;
            uint2* p = (uint2*)(hR1 + (size_t)t * REGH + r * SH + 116);
            p[0] = z2u; p[1] = z2u; p[2] = z2u;
        }
    }
    // Z -> R1, aw2 -> R2 (raw fp16 copies, 4 halves per op)
    {
        const __half* Zb = g_Zh + (size_t)b * RR;
        for (int idx = tid; idx < 116 * 29; idx += LT) {
            const int r = idx / 29;
            const int c = (idx - r * 29) << 2;
            *(uint2*)(hR1 + r * SH + c) = *(const uint2*)(Zb + r * R + c);
            *(uint2*)(hR2 + r * SH + c) = *(const uint2*)(aw2h + r * R + c);
        }
    }
    __syncthreads();

    // ---- attention -> R3 (fp16). No barrier needed before GEMM1. ----
    for (int n = wid; n < R; n += 16) {
        const float k0 = sKs[n * 3], k1 = sKs[n * 3 + 1], k2 = sKs[n * 3 + 2];
        float s[4];
        float mx = -3.0e38f;
#pragma unroll
        for (int it = 0; it < 4; it++) {
            const int m = it * 32 + lane;
            float v = -3.0e38f;
            if (m < R) v = k0 * sKs[m * 3] + k1 * sKs[m * 3 + 1] + k2 * sKs[m * 3 + 2];
            s[it] = v;
            mx = fmaxf(mx, v);
        }
#pragma unroll
        for (int o = 16; o; o >>= 1) mx = fmaxf(mx, __shfl_xor_sync(0xffffffffu, mx, o));
        float sum = 0.f, e[4];
#pragma unroll
        for (int it = 0; it < 4; it++) {
            const int m = it * 32 + lane;
            e[it] = (m < R) ? __expf(s[it] - mx) : 0.f;
            sum += e[it];
        }
        sum = wsum(sum);
        const float inv = 1.f / sum;
#pragma unroll
        for (int it = 0; it < 4; it++) {
            const int m = it * 32 + lane;
            if (m < R) hR3[n * SH + m] = __float2half_rn(e[it] * inv);
        }
    }

    float acc[2][4][4];
#pragma unroll
    for (int mt = 0; mt < 2; mt++)
#pragma unroll
        for (int nt = 0; nt < 4; nt++)
#pragma unroll
            for (int i = 0; i < 4; i++) acc[mt][nt][i] = 0.f;

    // ---- GEMM1: Mid1 = Z @ aw2^T ----
    mm_loop(hR1, hR2, acc, wm, wn, aOff, bOff);
    __syncthreads();

    // ---- Mid1 + ab2 -> R2 ----
#pragma unroll
    for (int mt = 0; mt < 2; mt++)
#pragma unroll
        for (int h = 0; h < 2; h++) {
            const int row = wm * 32 + mt * 16 + g + 8 * h;
#pragma unroll
            for (int nt = 0; nt < 4; nt++) {
                const int col = wn * 32 + nt * 8 + 2 * tig;
                if (col < 120)
                    *(__half2*)(hR2 + row * SH + col) =
                        __floats2half2_rn(acc[mt][nt][2 * h] + sb1[col],
                                          acc[mt][nt][2 * h + 1] + sb1[col + 1]);
            }
        }
#pragma unroll
    for (int mt = 0; mt < 2; mt++)
#pragma unroll
        for (int nt = 0; nt < 4; nt++)
#pragma unroll
            for (int i = 0; i < 4; i++) acc[mt][nt][i] = 0.f;
    __syncthreads();

    // ---- GEMM3: S2 = Mid1 @ att^T ----
    mm_loop(hR2, hR3, acc, wm, wn, aOff, bOff);
    __syncthreads();

    // ---- S2 -> R3 + node partials ; ew -> R2 ----
#pragma unroll
    for (int mt = 0; mt < 2; mt++)
#pragma unroll
        for (int h = 0; h < 2; h++) {
            const int row = wm * 32 + mt * 16 + g + 8 * h;
            float a0 = 0.f, a1 = 0.f, a2 = 0.f;
#pragma unroll
            for (int nt = 0; nt < 4; nt++) {
                const int col = wn * 32 + nt * 8 + 2 * tig;
                const float v0 = acc[mt][nt][2 * h];
                const float v1 = acc[mt][nt][2 * h + 1];
                if (col < 120)
                    *(__half2*)(hR3 + row * SH + col) = __floats2half2_rn(v0, v1);
                if (row < R && col < R) {
                    a0 = fmaf(v0, sXs[col * 3 + 0], fmaf(v1, sXs[col * 3 + 3], a0));
                    a1 = fmaf(v0, sXs[col * 3 + 1], fmaf(v1, sXs[col * 3 + 4], a1));
                    a2 = fmaf(v0, sXs[col * 3 + 2], fmaf(v1, sXs[col * 3 + 5], a2));
                }
            }
            a0 += __shfl_xor_sync(0xffffffffu, a0, 1);
            a0 += __shfl_xor_sync(0xffffffffu, a0, 2);
            a1 += __shfl_xor_sync(0xffffffffu, a1, 1);
            a1 += __shfl_xor_sync(0xffffffffu, a1, 2);
            a2 += __shfl_xor_sync(0xffffffffu, a2, 1);
            a2 += __shfl_xor_sync(0xffffffffu, a2, 2);
            if (tig == 0) {
                pA[0 * 512 + wn * 128 + row] = a0;
                pA[1 * 512 + wn * 128 + row] = a1;
                pA[2 * 512 + wn * 128 + row] = a2;
            }
        }
    for (int idx = tid; idx < 116 * 29; idx += LT) {
        const int r = idx / 29;
        const int c = (idx - r * 29) << 2;
        *(uint2*)(hR2 + r * SH + c) = *(const uint2*)(ewh + r * R + c);
    }
#pragma unroll
    for (int mt = 0; mt < 2; mt++)
#pragma unroll
        for (int nt = 0; nt < 4; nt++)
#pragma unroll
            for (int i = 0; i < 4; i++) acc[mt][nt][i] = 0.f;
    __syncthreads();

    // ---- GEMM2: Et = ew @ Z^T ----
    mm_loop(hR2, hR1, acc, wm, wn, aOff, bOff);
    __syncthreads();

    // ---- Et -> R1 ----
#pragma unroll
    for (int mt = 0; mt < 2; mt++)
#pragma unroll
        for (int h = 0; h < 2; h++) {
            const int row = wm * 32 + mt * 16 + g + 8 * h;
#pragma unroll
            for (int nt = 0; nt < 4; nt++) {
                const int col = wn * 32 + nt * 8 + 2 * tig;
                if (col < 120)
                    *(__half2*)(hR1 + row * SH + col) =
                        __floats2half2_rn(acc[mt][nt][2 * h], acc[mt][nt][2 * h + 1]);
            }
        }
#pragma unroll
    for (int mt = 0; mt < 2; mt++)
#pragma unroll
        for (int nt = 0; nt < 4; nt++)
#pragma unroll
            for (int i = 0; i < 4; i++) acc[mt][nt][i] = 0.f;
    __syncthreads();

    // ---- GEMM4: Z1 = S2 @ Et^T + eb ----
    mm_loop(hR3, hR1, acc, wm, wn, aOff, bOff);

    // ---- epilogue: Z1 (fp16) + edge stats (fp32, pre-rounding) ----
    __half* Cb = g_Z1h + (size_t)b * RR;
#pragma unroll
    for (int mt = 0; mt < 2; mt++) {
#pragma unroll
        for (int h = 0; h < 2; h++) {
            const int row = wm * 32 + mt * 16 + g + 8 * h;
            float s = 0.f, q = 0.f;
#pragma unroll
            for (int nt = 0; nt < 4; nt++) {
                const int col = wn * 32 + nt * 8 + 2 * tig;
                if (col < R) {
                    const float v0 = acc[mt][nt][2 * h] + sb2[col];
                    const float v1 = acc[mt][nt][2 * h + 1] + sb2[col + 1];
                    if (row < R)
                        *(__half2*)(Cb + (size_t)row * R + col) =
                            __floats2half2_rn(v0, v1);
                    s += v0 + v1;
                    q += v0 * v0 + v1 * v1;
                }
            }
            s += __shfl_xor_sync(0xffffffffu, s, 1);
            s += __shfl_xor_sync(0xffffffffu, s, 2);
            q += __shfl_xor_sync(0xffffffffu, q, 1);
            q += __shfl_xor_sync(0xffffffffu, q, 2);
            if (tig == 0) { pS[wn * 128 + row] = s; pQ[wn * 128 + row] = q; }
        }
    }
    __syncthreads();
    if (tid < R) {
        const float s = pS[tid] + pS[128 + tid] + pS[256 + tid] + pS[384 + tid];
        const float q = pQ[tid] + pQ[128 + tid] + pQ[256 + tid] + pQ[384 + tid];
        g_ps[tid * NB + b] = s;
        g_pq[tid * NB + b] = q;
    }
    // ---- node path finish: X1 = (S2 @ X) @ nw^T + nb, node stats ----
    if (tid < R) {
        const int n = tid;
        const float a0 = pA[0 * 512 + n] + pA[0 * 512 + 128 + n] +
                         pA[0 * 512 + 256 + n] + pA[0 * 512 + 384 + n];
        const float a1 = pA[1 * 512 + n] + pA[1 * 512 + 128 + n] +
                         pA[1 * 512 + 256 + n] + pA[1 * 512 + 384 + n];
        const float a2 = pA[2 * 512 + n] + pA[2 * 512 + 128 + n] +
                         pA[2 * 512 + 256 + n] + pA[2 * 512 + 384 + n];
        float ps = 0.f, pq = 0.f;
        float* dst = g_X1 + (size_t)b * (R * 3) + n * 3;
#pragma unroll
        for (int o = 0; o < 3; o++) {
            const float v = fmaf(nw[o * 3 + 0], a0,
                            fmaf(nw[o * 3 + 1], a1,
                            fmaf(nw[o * 3 + 2], a2, nb_[o])));
            dst[o] = v;
            ps += v;
            pq = fmaf(v, v, pq);
        }
        g_psN[n * NB + b] = ps;
        g_pqN[n * NB + b] = pq;
    }
}

// ----------------------------------------------------------------------------
// Both BN channel reductions in one launch. grid = 2R, block = 256.
// ----------------------------------------------------------------------------
__global__ void k_reduce_both(const float* __restrict__ geg, const float* __restrict__ geb,
                              const float* __restrict__ gng, const float* __restrict__ gnb) {
    const bool edge = blockIdx.x < R;
    const int n = edge ? blockIdx.x : blockIdx.x - R;
    const float* PS = edge ? g_ps : g_psN;
    const float* PQ = edge ? g_pq : g_pqN;
    float s = 0.f, q = 0.f;
    for (int b = threadIdx.x; b < NB; b += 256) {
        s += PS[n * NB + b];
        q += PQ[n * NB + b];
    }
    __shared__ float shs[8], shq[8];
    s = wsum(s); q = wsum(q);
    const int w = threadIdx.x >> 5, lane = threadIdx.x & 31;
    if (lane == 0) { shs[w] = s; shq[w] = q; }
    __syncthreads();
    if (w == 0) {
        s = (lane < 8) ? shs[lane] : 0.f;
        q = (lane < 8) ? shq[lane] : 0.f;
        s = wsum(s); q = wsum(q);
        if (lane == 0) {
            const float invcnt = edge ? (1.f / (float)(NB * R)) : (1.f / (float)(3 * NB));
            const float mean = s * invcnt;
            const float var = q * invcnt - mean * mean;
            const float rstd = rsqrtf(var + EPS);
            const float gg = edge ? geg[n] : gng[n];
            const float bb = edge ? geb[n] : gnb[n];
            const float sc = rstd * gg;
            if (edge) { g_scale[n] = sc;  g_shift[n] = bb - mean * sc; }
            else      { g_scaleN[n] = sc; g_shiftN[n] = bb - mean * sc; }
        }
    }
}

// ----------------------------------------------------------------------------
// Combined: Z+=relu(bn(Z1h)) & down-edge  /  X+=relu(bn(X1)) & down-node.
// Z carried as fp16 (g_Zh); conv computed from fp32 pre-rounded values.
// apply==0: pass-through from srcZ/srcX (fp32 inputs). grid = 30624, block 128.
// ----------------------------------------------------------------------------
__global__ void k_apply_down(const float* __restrict__ dew, const float* __restrict__ deb,
                             const float* __restrict__ dnw, const float* __restrict__ dnb,
                             const float* __restrict__ srcZ, const float* __restrict__ srcX,
                             int offE, int offN, int dpE, int dpN, int apply) {
    __shared__ float sh[8];
    if (blockIdx.x < 29696) {
        // ---------------- edge ----------------
        const int wrp = threadIdx.x >> 5, lane = threadIdx.x & 31;
        const int rowid = blockIdx.x * 4 + wrp;
        const int b = rowid / R, n = rowid - b * R;
        float w0[4], w1[4], w2[4];
#pragma unroll
        for (int d = 0; d < 4; d++) {
            const int e = 4 * lane + d;
            w1[d] = (e < 78) ? dew[e] : 0.f;
            w0[d] = (e < 39) ? dew[39 + e] : 0.f;
            w2[d] = (e >= 39 && e < 116) ? dew[e - 39] : 0.f;
        }
        float4 v = make_float4(0.f, 0.f, 0.f, 0.f);
        __half2* zrow = (__half2*)(g_Zh + (size_t)rowid * R);
        if (lane < 29) {
            if (apply) {
                const float2 z01 = __half22float2(zrow[2 * lane]);
                const float2 z23 = __half22float2(zrow[2 * lane + 1]);
                const __half2* urow = (const __half2*)(g_Z1h + (size_t)rowid * R);
                const float2 u01 = __half22float2(urow[2 * lane]);
                const float2 u23 = __half22float2(urow[2 * lane + 1]);
                const float sc = g_scale[n], sf = g_shift[n];
                v.x = z01.x + fmaxf(fmaf(u01.x, sc, sf), 0.f);
                v.y = z01.y + fmaxf(fmaf(u01.y, sc, sf), 0.f);
                v.z = z23.x + fmaxf(fmaf(u23.x, sc, sf), 0.f);
                v.w = z23.y + fmaxf(fmaf(u23.y, sc, sf), 0.f);
                zrow[2 * lane]     = __floats2half2_rn(v.x, v.y);
                zrow[2 * lane + 1] = __floats2half2_rn(v.z, v.w);
            } else {
                v = *(const float4*)(srcZ + (size_t)rowid * R + 4 * lane);
                zrow[2 * lane]     = __floats2half2_rn(v.x, v.y);
                zrow[2 * lane + 1] = __floats2half2_rn(v.z, v.w);
            }
        }
        float f0 = 0.f, f1 = 0.f, f2 = 0.f;
        const float vv[4] = {v.x, v.y, v.z, v.w};
#pragma unroll
        for (int d = 0; d < 4; d++) {
            f1 = fmaf(vv[d], w1[d], f1);
            f0 = fmaf(vv[d], w0[d], f0);
            f2 = fmaf(vv[d], w2[d], f2);
        }
        f0 = wsum(f0); f1 = wsum(f1); f2 = wsum(f2);
        float s = 0.f, q = 0.f;
        if (lane == 0) {
            const float bb = deb[0];
            f0 = fmaxf(f0 + bb, 0.f);
            f1 = fmaxf(f1 + bb, 0.f);
            f2 = fmaxf(f2 + bb, 0.f);
            float* dst = g_XZ + (size_t)b * FEAT + offE + n * 3;
            dst[0] = f0; dst[1] = f1; dst[2] = f2;
            s = f0 + f1 + f2;
            q = f0 * f0 + f1 * f1 + f2 * f2;
            sh[wrp] = s; sh[4 + wrp] = q;
        }
        __syncthreads();
        if (threadIdx.x == 0) {
            g_dpS[dpE + blockIdx.x] = sh[0] + sh[1] + sh[2] + sh[3];
            g_dpQ[dpE + blockIdx.x] = sh[4] + sh[5] + sh[6] + sh[7];
        }
    } else {
        // ---------------- node ----------------
        const int bid = blockIdx.x - 29696;
        const int idx = bid * 128 + threadIdx.x;
        float* xp = g_X + (size_t)idx * 3;
        float x0, x1, x2;
        if (apply) {
            x0 = xp[0]; x1 = xp[1]; x2 = xp[2];
            const int n = idx % R;
            const float sc = g_scaleN[n], sf = g_shiftN[n];
            const float* up = g_X1 + (size_t)idx * 3;
            x0 += fmaxf(fmaf(up[0], sc, sf), 0.f);
            x1 += fmaxf(fmaf(up[1], sc, sf), 0.f);
            x2 += fmaxf(fmaf(up[2], sc, sf), 0.f);
            xp[0] = x0; xp[1] = x1; xp[2] = x2;
        } else {
            const float* sp = srcX + (size_t)idx * 3;
            x0 = sp[0]; x1 = sp[1]; x2 = sp[2];
            xp[0] = x0; xp[1] = x1; xp[2] = x2;
        }
        const float f = fmaxf(fmaf(x0, dnw[0], fmaf(x1, dnw[1], fmaf(x2, dnw[2], dnb[0]))), 0.f);
        const int b = idx / R, r = idx - (idx / R) * R;
        g_XZ[(size_t)b * FEAT + offN + r] = f;
        const float s = wsum(f);
        const float q = wsum(f * f);
        const int wr = threadIdx.x >> 5, lane = threadIdx.x & 31;
        if (lane == 0) { sh[wr] = s; sh[4 + wr] = q; }
        __syncthreads();
        if (threadIdx.x == 0) {
            g_dpS[dpN + bid] = sh[0] + sh[1] + sh[2] + sh[3];
            g_dpQ[dpN + bid] = sh[4] + sh[5] + sh[6] + sh[7];
        }
    }
}

// ----------------------------------------------------------------------------
// All 10 down-sample reductions at once. grid = 10, block = 1024.
// ----------------------------------------------------------------------------
__global__ void k_dreduce_all(const float* __restrict__ dng, const float* __restrict__ dnbe,
                              const float* __restrict__ deg, const float* __restrict__ debe) {
    const int sgm = blockIdx.x;
    const bool node = sgm < 5;
    const int l = node ? sgm : sgm - 5;
    const int base = node ? (EDGET + l * 928) : (l * 29696);
    const int cnt = node ? 928 : 29696;
    const float invcnt = node ? (1.f / (float)(NB * R)) : (1.f / (float)(NB * R * 3));
    float s = 0.f, q = 0.f;
    for (int i = threadIdx.x; i < cnt; i += 1024) {
        s += g_dpS[base + i];
        q += g_dpQ[base + i];
    }
    __shared__ float shs[32], shq[32];
    s = wsum(s); q = wsum(q);
    const int w = threadIdx.x >> 5, lane = threadIdx.x & 31;
    if (lane == 0) { shs[w] = s; shq[w] = q; }
    __syncthreads();
    if (w == 0) {
        s = shs[lane]; q = shq[lane];
        s = wsum(s); q = wsum(q);
        if (lane == 0) {
            const float mean = s * invcnt;
            const float var = q * invcnt - mean * mean;
            const float rstd = rsqrtf(var + EPS);
            const float gg = node ? dng[l] : deg[l];
            const float bb = node ? dnbe[l] : debe[l];
            const float sc = rstd * gg;
            g_dssArr[2 * sgm]     = sc;
            g_dssArr[2 * sgm + 1] = bb - mean * sc;
        }
    }
}

// ----------------------------------------------------------------------------
// Classifier GEMM (fp16, m16n8k16) with slab normalization folded into A-load.
// ----------------------------------------------------------------------------
#define CSTR 24

__global__ void __launch_bounds__(256)
k_cls(const float* __restrict__ A, const float* __restrict__ Bm,
      const float* __restrict__ bias, float* __restrict__ C)
{
    __shared__ __half sA[2][128 * CSTR];
    __shared__ __half sB[2][64 * CSTR];
    __shared__ float sbc[64];
    const int tid = threadIdx.x;
    const int wid = tid >> 5, lane = tid & 31;
    const int wm = wid >> 1, wn = wid & 1;
    const int g = lane >> 2, tig = lane & 3;
    const int row0 = blockIdx.y * 128, col0 = blockIdx.x * 64;

    if (tid < 64) sbc[tid] = bias[col0 + tid];

    float4 pa0, pa1, pb;
    float fsc, fsh;
    const int ar0 = tid >> 2, ac0 = (tid & 3) << 2;
    const int ar1 = (tid + 256) >> 2, ac1 = ac0;
    const int br = tid >> 2, bc = (tid & 3) << 2;

    auto fetch = [&](int k0) {
        const int k = k0 + ac0;
        const int sgm = (k < 580) ? (k / 116) : (5 + (k - 580) / 348);
        fsc = g_dssArr[2 * sgm];
        fsh = g_dssArr[2 * sgm + 1];
        pa0 = *(const float4*)(A + (size_t)(row0 + ar0) * FEAT + k0 + ac0);
        pa1 = *(const float4*)(A + (size_t)(row0 + ar1) * FEAT + k0 + ac1);
        pb  = *(const float4*)(Bm + (size_t)(col0 + br) * FEAT + k0 + bc);
    };
    auto store = [&](int buf) {
        __half2* d0 = (__half2*)&sA[buf][ar0 * CSTR + ac0];
        d0[0] = __floats2half2_rn(fmaf(pa0.x, fsc, fsh), fmaf(pa0.y, fsc, fsh));
        d0[1] = __floats2half2_rn(fmaf(pa0.z, fsc, fsh), fmaf(pa0.w, fsc, fsh));
        __half2* d1 = (__half2*)&sA[buf][ar1 * CSTR + ac1];
        d1[0] = __floats2half2_rn(fmaf(pa1.x, fsc, fsh), fmaf(pa1.y, fsc, fsh));
        d1[1] = __floats2half2_rn(fmaf(pa1.z, fsc, fsh), fmaf(pa1.w, fsc, fsh));
        __half2* d2 = (__half2*)&sB[buf][br * CSTR + bc];
        d2[0] = __floats2half2_rn(pb.x, pb.y);
        d2[1] = __floats2half2_rn(pb.z, pb.w);
    };

    float acc[2][4][4];
#pragma unroll
    for (int mt = 0; mt < 2; mt++)
#pragma unroll
        for (int nt = 0; nt < 4; nt++)
#pragma unroll
            for (int i = 0; i < 4; i++) acc[mt][nt][i] = 0.f;

    const int NS = FEAT / 16;   // 145
    fetch(0);
    store(0);
    __syncthreads();
    int buf = 0;
    for (int ks = 0; ks < NS; ks++) {
        if (ks + 1 < NS) fetch((ks + 1) * 16);
        uint32_t af[2][4], bf[4][2];
#pragma unroll
        for (int mt = 0; mt < 2; mt++) {
            const __half* p0 = &sA[buf][(wm * 32 + mt * 16 + g) * CSTR + 2 * tig];
            af[mt][0] = *(const uint32_t*)(p0);
            af[mt][1] = *(const uint32_t*)(p0 + 8 * CSTR);
            af[mt][2] = *(const uint32_t*)(p0 + 8);
            af[mt][3] = *(const uint32_t*)(p0 + 8 * CSTR + 8);
        }
#pragma unroll
        for (int nt = 0; nt < 4; nt++) {
            const __half* q0 = &sB[buf][(wn * 32 + nt * 8 + g) * CSTR + 2 * tig];
            bf[nt][0] = *(const uint32_t*)(q0);
            bf[nt][1] = *(const uint32_t*)(q0 + 8);
        }
#pragma unroll
        for (int mt = 0; mt < 2; mt++)
#pragma unroll
            for (int nt = 0; nt < 4; nt++)
                mma16(acc[mt][nt], af[mt], bf[nt]);
        if (ks + 1 < NS) store(buf ^ 1);
        __syncthreads();
        buf ^= 1;
    }

#pragma unroll
    for (int mt = 0; mt < 2; mt++)
#pragma unroll
        for (int h = 0; h < 2; h++) {
            const int row = row0 + wm * 32 + mt * 16 + g + 8 * h;
#pragma unroll
            for (int nt = 0; nt < 4; nt++) {
                const int col = wn * 32 + nt * 8 + 2 * tig;
                const float v0 = fmaxf(acc[mt][nt][2 * h] + sbc[col], 0.f);
                const float v1 = fmaxf(acc[mt][nt][2 * h + 1] + sbc[col + 1], 0.f);
                *(float2*)(C + (size_t)row * HID + col0 + col) = make_float2(v0, v1);
            }
        }
}

__global__ void k_out(const float* __restrict__ cw2, const float* __restrict__ cb2,
                      float* __restrict__ out) {
    const int b = blockIdx.x;
    const float* h = g_H + (size_t)b * HID;
    float a0 = 0.f, a1 = 0.f;
    for (int j = threadIdx.x; j < HID; j += 128) {
        const float hv = h[j];
        a0 = fmaf(hv, cw2[j], a0);
        a1 = fmaf(hv, cw2[HID + j], a1);
    }
    a0 = wsum(a0);
    a1 = wsum(a1);
    __shared__ float sh[8];
    const int w = threadIdx.x >> 5, lane = threadIdx.x & 31;
    if (lane == 0) { sh[w] = a0; sh[4 + w] = a1; }
    __syncthreads();
    if (threadIdx.x == 0) {
        out[b * 2 + 0] = sh[0] + sh[1] + sh[2] + sh[3] + cb2[0];
        out[b * 2 + 1] = sh[4] + sh[5] + sh[6] + sh[7] + cb2[1];
    }
}

// ----------------------------------------------------------------------------
// Host orchestration (graph-capturable: kernel launches only)
// ----------------------------------------------------------------------------
extern "C" void kernel_launch(void* const* d_in, const int* in_sizes, int n_in,
                              void* d_out, int out_size) {
    const float* X_in  = (const float*)d_in[0];
    const float* Z_in  = (const float*)d_in[1];
    const float* aw1   = (const float*)d_in[2];
    const float* ab1   = (const float*)d_in[3];
    const float* aw2   = (const float*)d_in[4];
    const float* ab2   = (const float*)d_in[5];
    const float* nw    = (const float*)d_in[6];
    const float* nb    = (const float*)d_in[7];
    const float* ew    = (const float*)d_in[8];
    const float* eb    = (const float*)d_in[9];
    const float* gn_g  = (const float*)d_in[10];
    const float* gn_b  = (const float*)d_in[11];
    const float* ge_g  = (const float*)d_in[12];
    const float* ge_b  = (const float*)d_in[13];
    const float* dn_w  = (const float*)d_in[14];
    const float* dn_b  = (const float*)d_in[15];
    const float* dn_g  = (const float*)d_in[16];
    const float* dn_be = (const float*)d_in[17];
    const float* de_w  = (const float*)d_in[18];
    const float* de_b  = (const float*)d_in[19];
    const float* de_g  = (const float*)d_in[20];
    const float* de_be = (const float*)d_in[21];
    const float* cw1   = (const float*)d_in[22];
    const float* cb1   = (const float*)d_in[23];
    const float* cw2   = (const float*)d_in[24];
    const float* cb2   = (const float*)d_in[25];
    float* out = (float*)d_out;

    cudaFuncSetAttribute(k_layer, cudaFuncAttributeMaxDynamicSharedMemorySize, SM_TOTB);

    float *pXZ, *pH;
    __half* pWh;
    cudaGetSymbolAddress((void**)&pXZ, g_XZ);
    cudaGetSymbolAddress((void**)&pH,  g_H);
    cudaGetSymbolAddress((void**)&pWh, g_wh);

    // one-time weight fp16 conversion (aw2 then ew)
    k_cvtw<<<(2 * LAYERS * RR + 255) / 256, 256>>>(aw2, ew);

    // layer-0 down-sample, fused with input pass-through copy
    k_apply_down<<<29696 + 928, 128>>>(de_w, de_b, dn_w, dn_b,
                                       Z_in, X_in,
                                       580, 0, 0, EDGET, 0);

    for (int i = 0; i < LAYERS; i++) {
        k_layer<<<NB, LT, SM_TOTB>>>(pWh + (size_t)i * RR, ab2 + i * R,
                                     aw1 + 9 * i, ab1 + 3 * i,
                                     pWh + (size_t)(LAYERS + i) * RR, eb + i * R,
                                     nw + 9 * i, nb + 3 * i);
        k_reduce_both<<<2 * R, 256>>>(ge_g + i * R, ge_b + i * R,
                                      gn_g + i * R, gn_b + i * R);
        const int l = i + 1;
        k_apply_down<<<29696 + 928, 128>>>(de_w + 78 * l, de_b + l,
                                           dn_w + 3 * l, dn_b + l,
                                           nullptr, nullptr,
                                           580 + l * 348, l * R,
                                           l * 29696, EDGET + l * 928, 1);
    }

    k_dreduce_all<<<10, 1024>>>(dn_g, dn_be, de_g, de_be);
    k_cls<<<dim3(HID / 64, NB / 128), 256>>>(pXZ, cw1, cb1, pH);
    k_out<<<NB, 128>>>(cw2, cb2, out);
}

// round 13
// speedup vs baseline: 1.7418x; 1.1013x over previous
#include <cuda_runtime.h>
#include <cuda_fp16.h>
#include <cstddef>
#include <cstdint>

// ----------------------------------------------------------------------------
// Problem constants
// ----------------------------------------------------------------------------
#define NB 1024            // batch
#define R 116              // ROIs
#define RR (R * R)         // 13456
#define LAYERS 4
#define FEAT 2320          // R*4*(L+1)
#define HID 1024
#define EPS 1e-5f

#define SH 136             // smem tile row stride (halves) — LDSM conflict-free
#define REGH (128 * SH)    // halves per region (17408)

// down-sample partial slot layout
#define EDGET 148480       // 5 * 29696 edge partial slots
#define DPTOT 153120       // + 5 * 928 node slots

// ----------------------------------------------------------------------------
// Device scratch (static allocation only)
// ----------------------------------------------------------------------------
__device__ __align__(16) __half g_Zh [(size_t)NB * RR];   // carried Z (fp16)
__device__ __align__(16) __half g_Z1h[(size_t)NB * RR];
__device__ __align__(16) __half g_wh [(size_t)2 * LAYERS * RR]; // aw2 | ew (fp16)
__device__ __align__(16) float  g_X  [NB * R * 3];
__device__ __align__(16) float  g_X1 [NB * R * 3];
__device__ __align__(16) float  g_XZ [(size_t)NB * FEAT];
__device__ __align__(16) float  g_Hp [(size_t)NB * 32];   // cls partial dots
__device__ float g_ps [R * NB];     // edge BN partials
__device__ float g_pq [R * NB];
__device__ float g_psN[R * NB];     // node BN partials
__device__ float g_pqN[R * NB];
__device__ float g_scale [R],  g_shift [R];   // edge BN affine
__device__ float g_scaleN[R],  g_shiftN[R];   // node BN affine
__device__ float g_dpS[DPTOT], g_dpQ[DPTOT];  // down-sample partials
__device__ float g_dssArr[20];                // 10 segments x (scale, shift)

__device__ __forceinline__ float wsum(float v) {
#pragma unroll
    for (int o = 16; o; o >>= 1) v += __shfl_xor_sync(0xffffffffu, v, o);
    return v;
}

__device__ __forceinline__ uint32_t sptr(const void* p) {
    return (uint32_t)__cvta_generic_to_shared(p);
}

// cp.async 8-byte copy (sm_80 baseline; compiles at compute_103)
#define CP8(saddr, gptr) \
    asm volatile("cp.async.ca.shared.global [%0], [%1], 8;" \
                 :: "r"(saddr), "l"(gptr))
#define CP_COMMIT() asm volatile("cp.async.commit_group;")
#define CP_WAIT0()  asm volatile("cp.async.wait_group 0;")

// ldmatrix x4: loads 4 8x8 b16 tiles.
#define LDSM4(r0, r1, r2, r3, addr) \
    asm volatile("ldmatrix.sync.aligned.m8n8.x4.shared.b16 {%0,%1,%2,%3}, [%4];" \
                 : "=r"(r0), "=r"(r1), "=r"(r2), "=r"(r3) : "r"(addr))

// mma.sync m16n8k16 fp16 inputs, fp32 accumulate
__device__ __forceinline__ void mma16(float* d, const uint32_t* a, const uint32_t* b) {
    asm volatile(
        "mma.sync.aligned.m16n8k16.row.col.f32.f16.f16.f32 "
        "{%0,%1,%2,%3},{%4,%5,%6,%7},{%8,%9},{%0,%1,%2,%3};"
        : "+f"(d[0]), "+f"(d[1]), "+f"(d[2]), "+f"(d[3])
        : "r"(a[0]), "r"(a[1]), "r"(a[2]), "r"(a[3]), "r"(b[0]), "r"(b[1]));
}

// 128x128x128 NT GEMM over fp16 smem tiles (stride SH halves), 16 warps,
// warp tile 32x32, 8 k-steps of K=16. 4 LDSM.x4 + 8 MMA per k-step.
__device__ __forceinline__ void mm_loop(const __half* __restrict__ sA,
                                        const __half* __restrict__ sB,
                                        float (&acc)[2][4][4],
                                        int wm, int wn,
                                        uint32_t aOff, uint32_t bOff) {
    const uint32_t a0b = sptr(sA) + (uint32_t)(wm * 32 * SH * 2) + aOff;
    const uint32_t a1b = a0b + 16 * SH * 2;
    const uint32_t b0b = sptr(sB) + (uint32_t)(wn * 32 * SH * 2) + bOff;
    const uint32_t b1b = b0b + 16 * SH * 2;
#pragma unroll
    for (int ks = 0; ks < 8; ks++) {
        const uint32_t off = ks * 32;       // 16 halves = 32 bytes per k-step
        uint32_t af[2][4], bf[4][2];
        LDSM4(af[0][0], af[0][1], af[0][2], af[0][3], a0b + off);
        LDSM4(af[1][0], af[1][1], af[1][2], af[1][3], a1b + off);
        LDSM4(bf[0][0], bf[0][1], bf[1][0], bf[1][1], b0b + off);
        LDSM4(bf[2][0], bf[2][1], bf[3][0], bf[3][1], b1b + off);
#pragma unroll
        for (int mt = 0; mt < 2; mt++)
#pragma unroll
            for (int nt = 0; nt < 4; nt++)
                mma16(acc[mt][nt], af[mt], bf[nt]);
    }
}

// ----------------------------------------------------------------------------
// One-time weight conversion: aw2 (L*RR) then ew (L*RR) -> g_wh (fp16)
// ----------------------------------------------------------------------------
__global__ void k_cvtw(const float* __restrict__ aw2, const float* __restrict__ ew) {
    const int i = blockIdx.x * 256 + threadIdx.x;
    const int N = LAYERS * RR;
    if (i < N) g_wh[i] = __float2half_rn(aw2[i]);
    else if (i < 2 * N) g_wh[i] = __float2half_rn(ew[i - N]);
}

// ----------------------------------------------------------------------------
// Mega layer kernel (fp16 tiles): one CTA per batch, 512 threads (16 warps).
// ----------------------------------------------------------------------------
#define HBYTES (3 * REGH * 2)      // 104448
#define EXT_B1 0
#define EXT_B2 128
#define EXT_KS 256                 // 352
#define EXT_XS 608                 // 352
#define EXT_PS 960                 // 512
#define EXT_PQ 1472                // 512
#define EXT_PA 1984                // 1536
#define EXT_TOT 3520
#define SM_TOTB (HBYTES + EXT_TOT * 4)   // 118528

#define LT 512

__global__ void __launch_bounds__(LT, 1)
k_layer(const __half* __restrict__ aw2h, const float* __restrict__ ab2,
        const float* __restrict__ aw1, const float* __restrict__ ab1,
        const __half* __restrict__ ewh,  const float* __restrict__ eb,
        const float* __restrict__ nw,  const float* __restrict__ nb_)
{
    extern __shared__ __align__(16) char smraw[];
    __half* hR1 = (__half*)smraw;            // Z -> Et
    __half* hR2 = hR1 + REGH;                // aw2 -> Mid1 -> ew
    __half* hR3 = hR2 + REGH;                // att -> S2
    float* fext = (float*)(smraw + HBYTES);
    float* sb1 = fext + EXT_B1;
    float* sb2 = fext + EXT_B2;
    float* sKs = fext + EXT_KS;
    float* sXs = fext + EXT_XS;
    float* pS  = fext + EXT_PS;
    float* pQ  = fext + EXT_PQ;
    float* pA  = fext + EXT_PA;

    const int tid = threadIdx.x;
    const int b = blockIdx.x;
    const int wid = tid >> 5, lane = tid & 31;
    const int wm = wid >> 2, wn = wid & 3;
    const int g = lane >> 2, tig = lane & 3;

    // ldmatrix per-lane byte offsets
    const uint32_t aOff = (uint32_t)((lane & 15) * SH * 2 + 16 * (lane >> 4));
    const uint32_t bOff = (uint32_t)(((lane & 7) + 8 * (lane >> 4)) * SH * 2 +
                                     16 * ((lane >> 3) & 1));

    // ---- phase 0: biases, X/Ks, pads; async Z & aw2 loads overlap attention ----
    if (tid < 128) {
        sb1[tid] = (tid < R) ? ab2[tid] : 0.f;
        sb2[tid] = (tid < R) ? eb[tid] : 0.f;
    }
    if (tid < R) {
        const float* xp = g_X + (size_t)b * (R * 3) + tid * 3;
        const float y0 = xp[0], y1 = xp[1], y2 = xp[2];
        sXs[tid * 3 + 0] = y0; sXs[tid * 3 + 1] = y1; sXs[tid * 3 + 2] = y2;
#pragma unroll
        for (int o = 0; o < 3; o++)
            sKs[tid * 3 + o] = fmaf(aw1[o * 3 + 0], y0,
                                fmaf(aw1[o * 3 + 1], y1,
                                fmaf(aw1[o * 3 + 2], y2, ab1[o])));
    }
    // zero pad rows 116..127, cols 0..127: 12 rows x 16 uint4 per region
    {
        const uint4 z4u = make_uint4(0, 0, 0, 0);
        for (int idx = tid; idx < 3 * 192; idx += LT) {
            const int t = idx / 192, i2 = idx - t * 192;
            const int r = 116 + i2 / 16, c8 = (i2 & 15) * 8;
            *(uint4*)(hR1 + (size_t)t * REGH + r * SH + c8) = z4u;
        }
    }
    // zero pad cols 116..127 rows 0..115: 3 uint2 per row per region
    {
        const uint2 z2u = make_uint2(0, 0);
        for (int idx = tid; idx < 3 * 116; idx += LT) {
            const int t = idx / 116, r = idx - t * 116;
            uint2* p = (uint2*)(hR1 + (size_t)t * REGH + r * SH + 116);
            p[0] = z2u; p[1] = z2u; p[2] = z2u;
        }
    }
    // Z -> R1, aw2 -> R2 via cp.async (8B each); overlapped with attention below
    {
        const __half* Zb = g_Zh + (size_t)b * RR;
        const uint32_t r1b = sptr(hR1), r2b = sptr(hR2);
        for (int idx = tid; idx < 116 * 29; idx += LT) {
            const int r = idx / 29;
            const int c = (idx - r * 29) << 2;
            const uint32_t so = (uint32_t)(r * SH + c) * 2;
            CP8(r1b + so, Zb + r * R + c);
            CP8(r2b + so, aw2h + r * R + c);
        }
        CP_COMMIT();
    }
    __syncthreads();    // sKs + pads visible; cp.async still in flight

    // ---- attention -> R3 (fp16), overlapping the async tile loads ----
    for (int n = wid; n < R; n += 16) {
        const float k0 = sKs[n * 3], k1 = sKs[n * 3 + 1], k2 = sKs[n * 3 + 2];
        float s[4];
        float mx = -3.0e38f;
#pragma unroll
        for (int it = 0; it < 4; it++) {
            const int m = it * 32 + lane;
            float v = -3.0e38f;
            if (m < R) v = k0 * sKs[m * 3] + k1 * sKs[m * 3 + 1] + k2 * sKs[m * 3 + 2];
            s[it] = v;
            mx = fmaxf(mx, v);
        }
#pragma unroll
        for (int o = 16; o; o >>= 1) mx = fmaxf(mx, __shfl_xor_sync(0xffffffffu, mx, o));
        float sum = 0.f, e[4];
#pragma unroll
        for (int it = 0; it < 4; it++) {
            const int m = it * 32 + lane;
            e[it] = (m < R) ? __expf(s[it] - mx) : 0.f;
            sum += e[it];
        }
        sum = wsum(sum);
        const float inv = 1.f / sum;
#pragma unroll
        for (int it = 0; it < 4; it++) {
            const int m = it * 32 + lane;
            if (m < R) hR3[n * SH + m] = __float2half_rn(e[it] * inv);
        }
    }
    CP_WAIT0();
    __syncthreads();    // all threads' async copies complete

    float acc[2][4][4];
#pragma unroll
    for (int mt = 0; mt < 2; mt++)
#pragma unroll
        for (int nt = 0; nt < 4; nt++)
#pragma unroll
            for (int i = 0; i < 4; i++) acc[mt][nt][i] = 0.f;

    // ---- GEMM1: Mid1 = Z @ aw2^T ----
    mm_loop(hR1, hR2, acc, wm, wn, aOff, bOff);
    __syncthreads();

    // ---- Mid1 + ab2 -> R2 ----
#pragma unroll
    for (int mt = 0; mt < 2; mt++)
#pragma unroll
        for (int h = 0; h < 2; h++) {
            const int row = wm * 32 + mt * 16 + g + 8 * h;
#pragma unroll
            for (int nt = 0; nt < 4; nt++) {
                const int col = wn * 32 + nt * 8 + 2 * tig;
                if (col < 120)
                    *(__half2*)(hR2 + row * SH + col) =
                        __floats2half2_rn(acc[mt][nt][2 * h] + sb1[col],
                                          acc[mt][nt][2 * h + 1] + sb1[col + 1]);
            }
        }
#pragma unroll
    for (int mt = 0; mt < 2; mt++)
#pragma unroll
        for (int nt = 0; nt < 4; nt++)
#pragma unroll
            for (int i = 0; i < 4; i++) acc[mt][nt][i] = 0.f;
    __syncthreads();

    // ---- GEMM3: S2 = Mid1 @ att^T ----
    mm_loop(hR2, hR3, acc, wm, wn, aOff, bOff);
    __syncthreads();

    // ---- ew -> R2 async; S2 -> R3 + node partials ----
    {
        const uint32_t r2b = sptr(hR2);
        for (int idx = tid; idx < 116 * 29; idx += LT) {
            const int r = idx / 29;
            const int c = (idx - r * 29) << 2;
            CP8(r2b + (uint32_t)(r * SH + c) * 2, ewh + r * R + c);
        }
        CP_COMMIT();
    }
#pragma unroll
    for (int mt = 0; mt < 2; mt++)
#pragma unroll
        for (int h = 0; h < 2; h++) {
            const int row = wm * 32 + mt * 16 + g + 8 * h;
            float a0 = 0.f, a1 = 0.f, a2 = 0.f;
#pragma unroll
            for (int nt = 0; nt < 4; nt++) {
                const int col = wn * 32 + nt * 8 + 2 * tig;
                const float v0 = acc[mt][nt][2 * h];
                const float v1 = acc[mt][nt][2 * h + 1];
                if (col < 120)
                    *(__half2*)(hR3 + row * SH + col) = __floats2half2_rn(v0, v1);
                if (row < R && col < R) {
                    a0 = fmaf(v0, sXs[col * 3 + 0], fmaf(v1, sXs[col * 3 + 3], a0));
                    a1 = fmaf(v0, sXs[col * 3 + 1], fmaf(v1, sXs[col * 3 + 4], a1));
                    a2 = fmaf(v0, sXs[col * 3 + 2], fmaf(v1, sXs[col * 3 + 5], a2));
                }
            }
            a0 += __shfl_xor_sync(0xffffffffu, a0, 1);
            a0 += __shfl_xor_sync(0xffffffffu, a0, 2);
            a1 += __shfl_xor_sync(0xffffffffu, a1, 1);
            a1 += __shfl_xor_sync(0xffffffffu, a1, 2);
            a2 += __shfl_xor_sync(0xffffffffu, a2, 1);
            a2 += __shfl_xor_sync(0xffffffffu, a2, 2);
            if (tig == 0) {
                pA[0 * 512 + wn * 128 + row] = a0;
                pA[1 * 512 + wn * 128 + row] = a1;
                pA[2 * 512 + wn * 128 + row] = a2;
            }
        }
#pragma unroll
    for (int mt = 0; mt < 2; mt++)
#pragma unroll
        for (int nt = 0; nt < 4; nt++)
#pragma unroll
            for (int i = 0; i < 4; i++) acc[mt][nt][i] = 0.f;
    CP_WAIT0();
    __syncthreads();

    // ---- GEMM2: Et = ew @ Z^T ----
    mm_loop(hR2, hR1, acc, wm, wn, aOff, bOff);
    __syncthreads();

    // ---- Et -> R1 ----
#pragma unroll
    for (int mt = 0; mt < 2; mt++)
#pragma unroll
        for (int h = 0; h < 2; h++) {
            const int row = wm * 32 + mt * 16 + g + 8 * h;
#pragma unroll
            for (int nt = 0; nt < 4; nt++) {
                const int col = wn * 32 + nt * 8 + 2 * tig;
                if (col < 120)
                    *(__half2*)(hR1 + row * SH + col) =
                        __floats2half2_rn(acc[mt][nt][2 * h], acc[mt][nt][2 * h + 1]);
            }
        }
#pragma unroll
    for (int mt = 0; mt < 2; mt++)
#pragma unroll
        for (int nt = 0; nt < 4; nt++)
#pragma unroll
            for (int i = 0; i < 4; i++) acc[mt][nt][i] = 0.f;
    __syncthreads();

    // ---- GEMM4: Z1 = S2 @ Et^T + eb ----
    mm_loop(hR3, hR1, acc, wm, wn, aOff, bOff);

    // ---- epilogue: Z1 (fp16) + edge stats (fp32, pre-rounding) ----
    __half* Cb = g_Z1h + (size_t)b * RR;
#pragma unroll
    for (int mt = 0; mt < 2; mt++) {
#pragma unroll
        for (int h = 0; h < 2; h++) {
            const int row = wm * 32 + mt * 16 + g + 8 * h;
            float s = 0.f, q = 0.f;
#pragma unroll
            for (int nt = 0; nt < 4; nt++) {
                const int col = wn * 32 + nt * 8 + 2 * tig;
                if (col < R) {
                    const float v0 = acc[mt][nt][2 * h] + sb2[col];
                    const float v1 = acc[mt][nt][2 * h + 1] + sb2[col + 1];
                    if (row < R)
                        *(__half2*)(Cb + (size_t)row * R + col) =
                            __floats2half2_rn(v0, v1);
                    s += v0 + v1;
                    q += v0 * v0 + v1 * v1;
                }
            }
            s += __shfl_xor_sync(0xffffffffu, s, 1);
            s += __shfl_xor_sync(0xffffffffu, s, 2);
            q += __shfl_xor_sync(0xffffffffu, q, 1);
            q += __shfl_xor_sync(0xffffffffu, q, 2);
            if (tig == 0) { pS[wn * 128 + row] = s; pQ[wn * 128 + row] = q; }
        }
    }
    __syncthreads();
    if (tid < R) {
        const float s = pS[tid] + pS[128 + tid] + pS[256 + tid] + pS[384 + tid];
        const float q = pQ[tid] + pQ[128 + tid] + pQ[256 + tid] + pQ[384 + tid];
        g_ps[tid * NB + b] = s;
        g_pq[tid * NB + b] = q;
    }
    // ---- node path finish: X1 = (S2 @ X) @ nw^T + nb, node stats ----
    if (tid < R) {
        const int n = tid;
        const float a0 = pA[0 * 512 + n] + pA[0 * 512 + 128 + n] +
                         pA[0 * 512 + 256 + n] + pA[0 * 512 + 384 + n];
        const float a1 = pA[1 * 512 + n] + pA[1 * 512 + 128 + n] +
                         pA[1 * 512 + 256 + n] + pA[1 * 512 + 384 + n];
        const float a2 = pA[2 * 512 + n] + pA[2 * 512 + 128 + n] +
                         pA[2 * 512 + 256 + n] + pA[2 * 512 + 384 + n];
        float ps = 0.f, pq = 0.f;
        float* dst = g_X1 + (size_t)b * (R * 3) + n * 3;
#pragma unroll
        for (int o = 0; o < 3; o++) {
            const float v = fmaf(nw[o * 3 + 0], a0,
                            fmaf(nw[o * 3 + 1], a1,
                            fmaf(nw[o * 3 + 2], a2, nb_[o])));
            dst[o] = v;
            ps += v;
            pq = fmaf(v, v, pq);
        }
        g_psN[n * NB + b] = ps;
        g_pqN[n * NB + b] = pq;
    }
}

// ----------------------------------------------------------------------------
// Both BN channel reductions in one launch. grid = 2R, block = 256.
// ----------------------------------------------------------------------------
__global__ void k_reduce_both(const float* __restrict__ geg, const float* __restrict__ geb,
                              const float* __restrict__ gng, const float* __restrict__ gnb) {
    const bool edge = blockIdx.x < R;
    const int n = edge ? blockIdx.x : blockIdx.x - R;
    const float* PS = edge ? g_ps : g_psN;
    const float* PQ = edge ? g_pq : g_pqN;
    float s = 0.f, q = 0.f;
    for (int b = threadIdx.x; b < NB; b += 256) {
        s += PS[n * NB + b];
        q += PQ[n * NB + b];
    }
    __shared__ float shs[8], shq[8];
    s = wsum(s); q = wsum(q);
    const int w = threadIdx.x >> 5, lane = threadIdx.x & 31;
    if (lane == 0) { shs[w] = s; shq[w] = q; }
    __syncthreads();
    if (w == 0) {
        s = (lane < 8) ? shs[lane] : 0.f;
        q = (lane < 8) ? shq[lane] : 0.f;
        s = wsum(s); q = wsum(q);
        if (lane == 0) {
            const float invcnt = edge ? (1.f / (float)(NB * R)) : (1.f / (float)(3 * NB));
            const float mean = s * invcnt;
            const float var = q * invcnt - mean * mean;
            const float rstd = rsqrtf(var + EPS);
            const float gg = edge ? geg[n] : gng[n];
            const float bb = edge ? geb[n] : gnb[n];
            const float sc = rstd * gg;
            if (edge) { g_scale[n] = sc;  g_shift[n] = bb - mean * sc; }
            else      { g_scaleN[n] = sc; g_shiftN[n] = bb - mean * sc; }
        }
    }
}

// ----------------------------------------------------------------------------
// Combined: Z+=relu(bn(Z1h)) & down-edge  /  X+=relu(bn(X1)) & down-node.
// ----------------------------------------------------------------------------
__global__ void k_apply_down(const float* __restrict__ dew, const float* __restrict__ deb,
                             const float* __restrict__ dnw, const float* __restrict__ dnb,
                             const float* __restrict__ srcZ, const float* __restrict__ srcX,
                             int offE, int offN, int dpE, int dpN, int apply) {
    __shared__ float sh[8];
    if (blockIdx.x < 29696) {
        // ---------------- edge ----------------
        const int wrp = threadIdx.x >> 5, lane = threadIdx.x & 31;
        const int rowid = blockIdx.x * 4 + wrp;
        const int b = rowid / R, n = rowid - b * R;
        float w0[4], w1[4], w2[4];
#pragma unroll
        for (int d = 0; d < 4; d++) {
            const int e = 4 * lane + d;
            w1[d] = (e < 78) ? dew[e] : 0.f;
            w0[d] = (e < 39) ? dew[39 + e] : 0.f;
            w2[d] = (e >= 39 && e < 116) ? dew[e - 39] : 0.f;
        }
        float4 v = make_float4(0.f, 0.f, 0.f, 0.f);
        __half2* zrow = (__half2*)(g_Zh + (size_t)rowid * R);
        if (lane < 29) {
            if (apply) {
                const float2 z01 = __half22float2(zrow[2 * lane]);
                const float2 z23 = __half22float2(zrow[2 * lane + 1]);
                const __half2* urow = (const __half2*)(g_Z1h + (size_t)rowid * R);
                const float2 u01 = __half22float2(urow[2 * lane]);
                const float2 u23 = __half22float2(urow[2 * lane + 1]);
                const float sc = g_scale[n], sf = g_shift[n];
                v.x = z01.x + fmaxf(fmaf(u01.x, sc, sf), 0.f);
                v.y = z01.y + fmaxf(fmaf(u01.y, sc, sf), 0.f);
                v.z = z23.x + fmaxf(fmaf(u23.x, sc, sf), 0.f);
                v.w = z23.y + fmaxf(fmaf(u23.y, sc, sf), 0.f);
                zrow[2 * lane]     = __floats2half2_rn(v.x, v.y);
                zrow[2 * lane + 1] = __floats2half2_rn(v.z, v.w);
            } else {
                v = *(const float4*)(srcZ + (size_t)rowid * R + 4 * lane);
                zrow[2 * lane]     = __floats2half2_rn(v.x, v.y);
                zrow[2 * lane + 1] = __floats2half2_rn(v.z, v.w);
            }
        }
        float f0 = 0.f, f1 = 0.f, f2 = 0.f;
        const float vv[4] = {v.x, v.y, v.z, v.w};
#pragma unroll
        for (int d = 0; d < 4; d++) {
            f1 = fmaf(vv[d], w1[d], f1);
            f0 = fmaf(vv[d], w0[d], f0);
            f2 = fmaf(vv[d], w2[d], f2);
        }
        f0 = wsum(f0); f1 = wsum(f1); f2 = wsum(f2);
        float s = 0.f, q = 0.f;
        if (lane == 0) {
            const float bb = deb[0];
            f0 = fmaxf(f0 + bb, 0.f);
            f1 = fmaxf(f1 + bb, 0.f);
            f2 = fmaxf(f2 + bb, 0.f);
            float* dst = g_XZ + (size_t)b * FEAT + offE + n * 3;
            dst[0] = f0; dst[1] = f1; dst[2] = f2;
            s = f0 + f1 + f2;
            q = f0 * f0 + f1 * f1 + f2 * f2;
            sh[wrp] = s; sh[4 + wrp] = q;
        }
        __syncthreads();
        if (threadIdx.x == 0) {
            g_dpS[dpE + blockIdx.x] = sh[0] + sh[1] + sh[2] + sh[3];
            g_dpQ[dpE + blockIdx.x] = sh[4] + sh[5] + sh[6] + sh[7];
        }
    } else {
        // ---------------- node ----------------
        const int bid = blockIdx.x - 29696;
        const int idx = bid * 128 + threadIdx.x;
        float* xp = g_X + (size_t)idx * 3;
        float x0, x1, x2;
        if (apply) {
            x0 = xp[0]; x1 = xp[1]; x2 = xp[2];
            const int n = idx % R;
            const float sc = g_scaleN[n], sf = g_shiftN[n];
            const float* up = g_X1 + (size_t)idx * 3;
            x0 += fmaxf(fmaf(up[0], sc, sf), 0.f);
            x1 += fmaxf(fmaf(up[1], sc, sf), 0.f);
            x2 += fmaxf(fmaf(up[2], sc, sf), 0.f);
            xp[0] = x0; xp[1] = x1; xp[2] = x2;
        } else {
            const float* sp = srcX + (size_t)idx * 3;
            x0 = sp[0]; x1 = sp[1]; x2 = sp[2];
            xp[0] = x0; xp[1] = x1; xp[2] = x2;
        }
        const float f = fmaxf(fmaf(x0, dnw[0], fmaf(x1, dnw[1], fmaf(x2, dnw[2], dnb[0]))), 0.f);
        const int b = idx / R, r = idx - (idx / R) * R;
        g_XZ[(size_t)b * FEAT + offN + r] = f;
        const float s = wsum(f);
        const float q = wsum(f * f);
        const int wr = threadIdx.x >> 5, lane = threadIdx.x & 31;
        if (lane == 0) { sh[wr] = s; sh[4 + wr] = q; }
        __syncthreads();
        if (threadIdx.x == 0) {
            g_dpS[dpN + bid] = sh[0] + sh[1] + sh[2] + sh[3];
            g_dpQ[dpN + bid] = sh[4] + sh[5] + sh[6] + sh[7];
        }
    }
}

// ----------------------------------------------------------------------------
// All 10 down-sample reductions at once. grid = 10, block = 1024.
// ----------------------------------------------------------------------------
__global__ void k_dreduce_all(const float* __restrict__ dng, const float* __restrict__ dnbe,
                              const float* __restrict__ deg, const float* __restrict__ debe) {
    const int sgm = blockIdx.x;
    const bool node = sgm < 5;
    const int l = node ? sgm : sgm - 5;
    const int base = node ? (EDGET + l * 928) : (l * 29696);
    const int cnt = node ? 928 : 29696;
    const float invcnt = node ? (1.f / (float)(NB * R)) : (1.f / (float)(NB * R * 3));
    float s = 0.f, q = 0.f;
    for (int i = threadIdx.x; i < cnt; i += 1024) {
        s += g_dpS[base + i];
        q += g_dpQ[base + i];
    }
    __shared__ float shs[32], shq[32];
    s = wsum(s); q = wsum(q);
    const int w = threadIdx.x >> 5, lane = threadIdx.x & 31;
    if (lane == 0) { shs[w] = s; shq[w] = q; }
    __syncthreads();
    if (w == 0) {
        s = shs[lane]; q = shq[lane];
        s = wsum(s); q = wsum(q);
        if (lane == 0) {
            const float mean = s * invcnt;
            const float var = q * invcnt - mean * mean;
            const float rstd = rsqrtf(var + EPS);
            const float gg = node ? dng[l] : deg[l];
            const float bb = node ? dnbe[l] : debe[l];
            const float sc = rstd * gg;
            g_dssArr[2 * sgm]     = sc;
            g_dssArr[2 * sgm + 1] = bb - mean * sc;
        }
    }
}

// ----------------------------------------------------------------------------
// Classifier GEMM (fp16) + fused out-projection partials (g_H eliminated).
// Each block reduces its 128x64 relu tile against cw2 into 2 partials/row.
// ----------------------------------------------------------------------------
#define CSTR 24

__global__ void __launch_bounds__(256)
k_cls(const float* __restrict__ A, const float* __restrict__ Bm,
      const float* __restrict__ bias, const float* __restrict__ cw2)
{
    __shared__ __half sA[2][128 * CSTR];
    __shared__ __half sB[2][64 * CSTR];
    __shared__ float sbc[64];
    __shared__ float sc2[2][64];
    __shared__ float pOut[128][4];
    const int tid = threadIdx.x;
    const int wid = tid >> 5, lane = tid & 31;
    const int wm = wid >> 1, wn = wid & 1;
    const int g = lane >> 2, tig = lane & 3;
    const int row0 = blockIdx.y * 128, col0 = blockIdx.x * 64;

    if (tid < 64) {
        sbc[tid] = bias[col0 + tid];
        sc2[0][tid] = cw2[col0 + tid];
        sc2[1][tid] = cw2[HID + col0 + tid];
    }

    float4 pa0, pa1, pb;
    float fsc, fsh;
    const int ar0 = tid >> 2, ac0 = (tid & 3) << 2;
    const int ar1 = (tid + 256) >> 2, ac1 = ac0;
    const int br = tid >> 2, bc = (tid & 3) << 2;

    auto fetch = [&](int k0) {
        const int k = k0 + ac0;
        const int sgm = (k < 580) ? (k / 116) : (5 + (k - 580) / 348);
        fsc = g_dssArr[2 * sgm];
        fsh = g_dssArr[2 * sgm + 1];
        pa0 = *(const float4*)(A + (size_t)(row0 + ar0) * FEAT + k0 + ac0);
        pa1 = *(const float4*)(A + (size_t)(row0 + ar1) * FEAT + k0 + ac1);
        pb  = *(const float4*)(Bm + (size_t)(col0 + br) * FEAT + k0 + bc);
    };
    auto store = [&](int buf) {
        __half2* d0 = (__half2*)&sA[buf][ar0 * CSTR + ac0];
        d0[0] = __floats2half2_rn(fmaf(pa0.x, fsc, fsh), fmaf(pa0.y, fsc, fsh));
        d0[1] = __floats2half2_rn(fmaf(pa0.z, fsc, fsh), fmaf(pa0.w, fsc, fsh));
        __half2* d1 = (__half2*)&sA[buf][ar1 * CSTR + ac1];
        d1[0] = __floats2half2_rn(fmaf(pa1.x, fsc, fsh), fmaf(pa1.y, fsc, fsh));
        d1[1] = __floats2half2_rn(fmaf(pa1.z, fsc, fsh), fmaf(pa1.w, fsc, fsh));
        __half2* d2 = (__half2*)&sB[buf][br * CSTR + bc];
        d2[0] = __floats2half2_rn(pb.x, pb.y);
        d2[1] = __floats2half2_rn(pb.z, pb.w);
    };

    float acc[2][4][4];
#pragma unroll
    for (int mt = 0; mt < 2; mt++)
#pragma unroll
        for (int nt = 0; nt < 4; nt++)
#pragma unroll
            for (int i = 0; i < 4; i++) acc[mt][nt][i] = 0.f;

    const int NS = FEAT / 16;   // 145
    fetch(0);
    store(0);
    __syncthreads();
    int buf = 0;
    for (int ks = 0; ks < NS; ks++) {
        if (ks + 1 < NS) fetch((ks + 1) * 16);
        uint32_t af[2][4], bf[4][2];
#pragma unroll
        for (int mt = 0; mt < 2; mt++) {
            const __half* p0 = &sA[buf][(wm * 32 + mt * 16 + g) * CSTR + 2 * tig];
            af[mt][0] = *(const uint32_t*)(p0);
            af[mt][1] = *(const uint32_t*)(p0 + 8 * CSTR);
            af[mt][2] = *(const uint32_t*)(p0 + 8);
            af[mt][3] = *(const uint32_t*)(p0 + 8 * CSTR + 8);
        }
#pragma unroll
        for (int nt = 0; nt < 4; nt++) {
            const __half* q0 = &sB[buf][(wn * 32 + nt * 8 + g) * CSTR + 2 * tig];
            bf[nt][0] = *(const uint32_t*)(q0);
            bf[nt][1] = *(const uint32_t*)(q0 + 8);
        }
#pragma unroll
        for (int mt = 0; mt < 2; mt++)
#pragma unroll
            for (int nt = 0; nt < 4; nt++)
                mma16(acc[mt][nt], af[mt], bf[nt]);
        if (ks + 1 < NS) store(buf ^ 1);
        __syncthreads();
        buf ^= 1;
    }

    // fused epilogue: relu + dot with cw2 slice -> per-row partials
#pragma unroll
    for (int mt = 0; mt < 2; mt++)
#pragma unroll
        for (int h = 0; h < 2; h++) {
            const int rl = wm * 32 + mt * 16 + g + 8 * h;
            float p0 = 0.f, p1 = 0.f;
#pragma unroll
            for (int nt = 0; nt < 4; nt++) {
                const int col = wn * 32 + nt * 8 + 2 * tig;
                const float v0 = fmaxf(acc[mt][nt][2 * h] + sbc[col], 0.f);
                const float v1 = fmaxf(acc[mt][nt][2 * h + 1] + sbc[col + 1], 0.f);
                p0 = fmaf(v0, sc2[0][col], fmaf(v1, sc2[0][col + 1], p0));
                p1 = fmaf(v0, sc2[1][col], fmaf(v1, sc2[1][col + 1], p1));
            }
            p0 += __shfl_xor_sync(0xffffffffu, p0, 1);
            p0 += __shfl_xor_sync(0xffffffffu, p0, 2);
            p1 += __shfl_xor_sync(0xffffffffu, p1, 1);
            p1 += __shfl_xor_sync(0xffffffffu, p1, 2);
            if (tig == 0) {
                pOut[rl][wn * 2 + 0] = p0;
                pOut[rl][wn * 2 + 1] = p1;
            }
        }
    __syncthreads();
    if (tid < 128) {
        g_Hp[(size_t)(row0 + tid) * 32 + blockIdx.x * 2 + 0] = pOut[tid][0] + pOut[tid][2];
        g_Hp[(size_t)(row0 + tid) * 32 + blockIdx.x * 2 + 1] = pOut[tid][1] + pOut[tid][3];
    }
}

// Final fold: out[b][c] = sum_k g_Hp[b][2k+c] + cb2[c]. grid = 4, block = 256.
__global__ void k_out2(const float* __restrict__ cb2, float* __restrict__ out) {
    const int b = blockIdx.x * 256 + threadIdx.x;
    const float* p = g_Hp + (size_t)b * 32;
    float a0 = 0.f, a1 = 0.f;
#pragma unroll
    for (int k = 0; k < 16; k++) {
        a0 += p[2 * k];
        a1 += p[2 * k + 1];
    }
    out[b * 2 + 0] = a0 + cb2[0];
    out[b * 2 + 1] = a1 + cb2[1];
}

// ----------------------------------------------------------------------------
// Host orchestration (graph-capturable: kernel launches only)
// ----------------------------------------------------------------------------
extern "C" void kernel_launch(void* const* d_in, const int* in_sizes, int n_in,
                              void* d_out, int out_size) {
    const float* X_in  = (const float*)d_in[0];
    const float* Z_in  = (const float*)d_in[1];
    const float* aw1   = (const float*)d_in[2];
    const float* ab1   = (const float*)d_in[3];
    const float* aw2   = (const float*)d_in[4];
    const float* ab2   = (const float*)d_in[5];
    const float* nw    = (const float*)d_in[6];
    const float* nb    = (const float*)d_in[7];
    const float* ew    = (const float*)d_in[8];
    const float* eb    = (const float*)d_in[9];
    const float* gn_g  = (const float*)d_in[10];
    const float* gn_b  = (const float*)d_in[11];
    const float* ge_g  = (const float*)d_in[12];
    const float* ge_b  = (const float*)d_in[13];
    const float* dn_w  = (const float*)d_in[14];
    const float* dn_b  = (const float*)d_in[15];
    const float* dn_g  = (const float*)d_in[16];
    const float* dn_be = (const float*)d_in[17];
    const float* de_w  = (const float*)d_in[18];
    const float* de_b  = (const float*)d_in[19];
    const float* de_g  = (const float*)d_in[20];
    const float* de_be = (const float*)d_in[21];
    const float* cw1   = (const float*)d_in[22];
    const float* cb1   = (const float*)d_in[23];
    const float* cw2   = (const float*)d_in[24];
    const float* cb2   = (const float*)d_in[25];
    float* out = (float*)d_out;

    cudaFuncSetAttribute(k_layer, cudaFuncAttributeMaxDynamicSharedMemorySize, SM_TOTB);

    float* pXZ;
    __half* pWh;
    cudaGetSymbolAddress((void**)&pXZ, g_XZ);
    cudaGetSymbolAddress((void**)&pWh, g_wh);

    // one-time weight fp16 conversion (aw2 then ew)
    k_cvtw<<<(2 * LAYERS * RR + 255) / 256, 256>>>(aw2, ew);

    // layer-0 down-sample, fused with input pass-through copy
    k_apply_down<<<29696 + 928, 128>>>(de_w, de_b, dn_w, dn_b,
                                       Z_in, X_in,
                                       580, 0, 0, EDGET, 0);

    for (int i = 0; i < LAYERS; i++) {
        k_layer<<<NB, LT, SM_TOTB>>>(pWh + (size_t)i * RR, ab2 + i * R,
                                     aw1 + 9 * i, ab1 + 3 * i,
                                     pWh + (size_t)(LAYERS + i) * RR, eb + i * R,
                                     nw + 9 * i, nb + 3 * i);
        k_reduce_both<<<2 * R, 256>>>(ge_g + i * R, ge_b + i * R,
                                      gn_g + i * R, gn_b + i * R);
        const int l = i + 1;
        k_apply_down<<<29696 + 928, 128>>>(de_w + 78 * l, de_b + l,
                                           dn_w + 3 * l, dn_b + l,
                                           nullptr, nullptr,
                                           580 + l * 348, l * R,
                                           l * 29696, EDGET + l * 928, 1);
    }

    k_dreduce_all<<<10, 1024>>>(dn_g, dn_be, de_g, de_be);
    k_cls<<<dim3(HID / 64, NB / 128), 256>>>(pXZ, cw1, cb1, cw2);
    k_out2<<<NB / 256, 256>>>(cb2, out);
}

// round 15
// speedup vs baseline: 1.7498x; 1.0046x over previous
#include <cuda_runtime.h>
#include <cuda_fp16.h>
#include <cstddef>
#include <cstdint>

// ----------------------------------------------------------------------------
// Problem constants
// ----------------------------------------------------------------------------
#define NB 1024            // batch
#define R 116              // ROIs
#define RR (R * R)         // 13456
#define LAYERS 4
#define FEAT 2320          // R*4*(L+1)
#define HID 1024
#define EPS 1e-5f

#define SH 136             // smem tile row stride (halves) — LDSM conflict-free
#define REGH (128 * SH)    // halves per region (17408)

// down-sample partial slot layout
#define EDGET 148480       // 5 * 29696 edge partial slots
#define DPTOT 153120       // + 5 * 928 node slots

// weight-conversion tail blocks: each block converts 256 elements
// (128 threads x 2). total = 2*LAYERS*RR = 107648 -> 421 blocks.
#define CVTB ((2 * LAYERS * RR + 255) / 256)

// ----------------------------------------------------------------------------
// Device scratch (static allocation only)
// ----------------------------------------------------------------------------
__device__ __align__(16) __half g_Zh [(size_t)NB * RR];   // carried Z (fp16)
__device__ __align__(16) __half g_Z1h[(size_t)NB * RR];
__device__ __align__(16) __half g_wh [(size_t)2 * LAYERS * RR]; // aw2 | ew (fp16)
__device__ __align__(16) float  g_X  [NB * R * 3];
__device__ __align__(16) float  g_X1 [NB * R * 3];
__device__ __align__(16) float  g_XZ [(size_t)NB * FEAT];
__device__ __align__(16) float  g_Hp [(size_t)NB * 32];   // cls partial dots
__device__ float g_ps [R * NB];     // edge BN partials
__device__ float g_pq [R * NB];
__device__ float g_psN[R * NB];     // node BN partials
__device__ float g_pqN[R * NB];
__device__ float g_scale [R],  g_shift [R];   // edge BN affine
__device__ float g_scaleN[R],  g_shiftN[R];   // node BN affine
__device__ float g_dpS[DPTOT], g_dpQ[DPTOT];  // down-sample partials
__device__ float g_dssArr[20];                // 10 segments x (scale, shift)

__device__ __forceinline__ float wsum(float v) {
#pragma unroll
    for (int o = 16; o; o >>= 1) v += __shfl_xor_sync(0xffffffffu, v, o);
    return v;
}

__device__ __forceinline__ uint32_t sptr(const void* p) {
    return (uint32_t)__cvta_generic_to_shared(p);
}

// cp.async 8-byte copy (sm_80 baseline; compiles at compute_103)
#define CP8(saddr, gptr) \
    asm volatile("cp.async.ca.shared.global [%0], [%1], 8;" \
                 :: "r"(saddr), "l"(gptr))
#define CP_COMMIT() asm volatile("cp.async.commit_group;")
#define CP_WAIT0()  asm volatile("cp.async.wait_group 0;")

// ldmatrix x4: loads 4 8x8 b16 tiles.
#define LDSM4(r0, r1, r2, r3, addr) \
    asm volatile("ldmatrix.sync.aligned.m8n8.x4.shared.b16 {%0,%1,%2,%3}, [%4];" \
                 : "=r"(r0), "=r"(r1), "=r"(r2), "=r"(r3) : "r"(addr))

// mma.sync m16n8k16 fp16 inputs, fp32 accumulate
__device__ __forceinline__ void mma16(float* d, const uint32_t* a, const uint32_t* b) {
    asm volatile(
        "mma.sync.aligned.m16n8k16.row.col.f32.f16.f16.f32 "
        "{%0,%1,%2,%3},{%4,%5,%6,%7},{%8,%9},{%0,%1,%2,%3};"
        : "+f"(d[0]), "+f"(d[1]), "+f"(d[2]), "+f"(d[3])
        : "r"(a[0]), "r"(a[1]), "r"(a[2]), "r"(a[3]), "r"(b[0]), "r"(b[1]));
}

// 128x128x128 NT GEMM over fp16 smem tiles (stride SH halves), 16 warps,
// warp tile 32x32, 8 k-steps of K=16. 4 LDSM.x4 + 8 MMA per k-step.
__device__ __forceinline__ void mm_loop(const __half* __restrict__ sA,
                                        const __half* __restrict__ sB,
                                        float (&acc)[2][4][4],
                                        int wm, int wn,
                                        uint32_t aOff, uint32_t bOff) {
    const uint32_t a0b = sptr(sA) + (uint32_t)(wm * 32 * SH * 2) + aOff;
    const uint32_t a1b = a0b + 16 * SH * 2;
    const uint32_t b0b = sptr(sB) + (uint32_t)(wn * 32 * SH * 2) + bOff;
    const uint32_t b1b = b0b + 16 * SH * 2;
#pragma unroll
    for (int ks = 0; ks < 8; ks++) {
        const uint32_t off = ks * 32;       // 16 halves = 32 bytes per k-step
        uint32_t af[2][4], bf[4][2];
        LDSM4(af[0][0], af[0][1], af[0][2], af[0][3], a0b + off);
        LDSM4(af[1][0], af[1][1], af[1][2], af[1][3], a1b + off);
        LDSM4(bf[0][0], bf[0][1], bf[1][0], bf[1][1], b0b + off);
        LDSM4(bf[2][0], bf[2][1], bf[3][0], bf[3][1], b1b + off);
#pragma unroll
        for (int mt = 0; mt < 2; mt++)
#pragma unroll
            for (int nt = 0; nt < 4; nt++)
                mma16(acc[mt][nt], af[mt], bf[nt]);
    }
}

// ----------------------------------------------------------------------------
// Mega layer kernel (fp16 tiles): one CTA per batch, 512 threads (16 warps).
// ----------------------------------------------------------------------------
#define HBYTES (3 * REGH * 2)      // 104448
#define EXT_B1 0
#define EXT_B2 128
#define EXT_KS 256                 // 352
#define EXT_XS 608                 // 352
#define EXT_PS 960                 // 512
#define EXT_PQ 1472                // 512
#define EXT_PA 1984                // 1536
#define EXT_TOT 3520
#define SM_TOTB (HBYTES + EXT_TOT * 4)   // 118528

#define LT 512

__global__ void __launch_bounds__(LT, 1)
k_layer(const __half* __restrict__ aw2h, const float* __restrict__ ab2,
        const float* __restrict__ aw1, const float* __restrict__ ab1,
        const __half* __restrict__ ewh,  const float* __restrict__ eb,
        const float* __restrict__ nw,  const float* __restrict__ nb_)
{
    extern __shared__ __align__(16) char smraw[];
    __half* hR1 = (__half*)smraw;            // Z -> Et
    __half* hR2 = hR1 + REGH;                // aw2 -> Mid1 -> ew
    __half* hR3 = hR2 + REGH;                // att -> S2
    float* fext = (float*)(smraw + HBYTES);
    float* sb1 = fext + EXT_B1;
    float* sb2 = fext + EXT_B2;
    float* sKs = fext + EXT_KS;
    float* sXs = fext + EXT_XS;
    float* pS  = fext + EXT_PS;
    float* pQ  = fext + EXT_PQ;
    float* pA  = fext + EXT_PA;

    const int tid = threadIdx.x;
    const int b = blockIdx.x;
    const int wid = tid >> 5, lane = tid & 31;
    const int wm = wid >> 2, wn = wid & 3;
    const int g = lane >> 2, tig = lane & 3;

    // ldmatrix per-lane byte offsets
    const uint32_t aOff = (uint32_t)((lane & 15) * SH * 2 + 16 * (lane >> 4));
    const uint32_t bOff = (uint32_t)(((lane & 7) + 8 * (lane >> 4)) * SH * 2 +
                                     16 * ((lane >> 3) & 1));

    // ---- phase 0: biases, X/Ks, pads; async Z & aw2 loads overlap attention ----
    if (tid < 128) {
        sb1[tid] = (tid < R) ? ab2[tid] : 0.f;
        sb2[tid] = (tid < R) ? eb[tid] : 0.f;
    }
    if (tid < R) {
        const float* xp = g_X + (size_t)b * (R * 3) + tid * 3;
        const float y0 = xp[0], y1 = xp[1], y2 = xp[2];
        sXs[tid * 3 + 0] = y0; sXs[tid * 3 + 1] = y1; sXs[tid * 3 + 2] = y2;
#pragma unroll
        for (int o = 0; o < 3; o++)
            sKs[tid * 3 + o] = fmaf(aw1[o * 3 + 0], y0,
                                fmaf(aw1[o * 3 + 1], y1,
                                fmaf(aw1[o * 3 + 2], y2, ab1[o])));
    }
    // zero pad rows 116..127, cols 0..127: 12 rows x 16 uint4 per region
    {
        const uint4 z4u = make_uint4(0, 0, 0, 0);
        for (int idx = tid; idx < 3 * 192; idx += LT) {
            const int t = idx / 192, i2 = idx - t * 192;
            const int r = 116 + i2 / 16, c8 = (i2 & 15) * 8;
            *(uint4*)(hR1 + (size_t)t * REGH + r * SH + c8) = z4u;
        }
    }
    // zero pad cols 116..127 rows 0..115: 3 uint2 per row per region
    {
        const uint2 z2u = make_uint2(0, 0);
        for (int idx = tid; idx < 3 * 116; idx += LT) {
            const int t = idx / 116, r = idx - t * 116;
            uint2* p = (uint2*)(hR1 + (size_t)t * REGH + r * SH + 116);
            p[0] = z2u; p[1] = z2u; p[2] = z2u;
        }
    }
    // Z -> R1, aw2 -> R2 via cp.async (8B each); overlapped with attention below
    {
        const __half* Zb = g_Zh + (size_t)b * RR;
        const uint32_t r1b = sptr(hR1), r2b = sptr(hR2);
        for (int idx = tid; idx < 116 * 29; idx += LT) {
            const int r = idx / 29;
            const int c = (idx - r * 29) << 2;
            const uint32_t so = (uint32_t)(r * SH + c) * 2;
            CP8(r1b + so, Zb + r * R + c);
            CP8(r2b + so, aw2h + r * R + c);
        }
        CP_COMMIT();
    }
    __syncthreads();    // sKs + pads visible; cp.async still in flight

    // ---- attention -> R3 (fp16), overlapping the async tile loads ----
    for (int n = wid; n < R; n += 16) {
        const float k0 = sKs[n * 3], k1 = sKs[n * 3 + 1], k2 = sKs[n * 3 + 2];
        float s[4];
        float mx = -3.0e38f;
#pragma unroll
        for (int it = 0; it < 4; it++) {
            const int m = it * 32 + lane;
            float v = -3.0e38f;
            if (m < R) v = k0 * sKs[m * 3] + k1 * sKs[m * 3 + 1] + k2 * sKs[m * 3 + 2];
            s[it] = v;
            mx = fmaxf(mx, v);
        }
#pragma unroll
        for (int o = 16; o; o >>= 1) mx = fmaxf(mx, __shfl_xor_sync(0xffffffffu, mx, o));
        float sum = 0.f, e[4];
#pragma unroll
        for (int it = 0; it < 4; it++) {
            const int m = it * 32 + lane;
            e[it] = (m < R) ? __expf(s[it] - mx) : 0.f;
            sum += e[it];
        }
        sum = wsum(sum);
        const float inv = 1.f / sum;
#pragma unroll
        for (int it = 0; it < 4; it++) {
            const int m = it * 32 + lane;
            if (m < R) hR3[n * SH + m] = __float2half_rn(e[it] * inv);
        }
    }
    CP_WAIT0();
    __syncthreads();    // all threads' async copies complete

    float acc[2][4][4];
#pragma unroll
    for (int mt = 0; mt < 2; mt++)
#pragma unroll
        for (int nt = 0; nt < 4; nt++)
#pragma unroll
            for (int i = 0; i < 4; i++) acc[mt][nt][i] = 0.f;

    // ---- GEMM1: Mid1 = Z @ aw2^T ----
    mm_loop(hR1, hR2, acc, wm, wn, aOff, bOff);
    __syncthreads();

    // ---- Mid1 + ab2 -> R2 ----
#pragma unroll
    for (int mt = 0; mt < 2; mt++)
#pragma unroll
        for (int h = 0; h < 2; h++) {
            const int row = wm * 32 + mt * 16 + g + 8 * h;
#pragma unroll
            for (int nt = 0; nt < 4; nt++) {
                const int col = wn * 32 + nt * 8 + 2 * tig;
                if (col < 120)
                    *(__half2*)(hR2 + row * SH + col) =
                        __floats2half2_rn(acc[mt][nt][2 * h] + sb1[col],
                                          acc[mt][nt][2 * h + 1] + sb1[col + 1]);
            }
        }
#pragma unroll
    for (int mt = 0; mt < 2; mt++)
#pragma unroll
        for (int nt = 0; nt < 4; nt++)
#pragma unroll
            for (int i = 0; i < 4; i++) acc[mt][nt][i] = 0.f;
    __syncthreads();

    // ---- GEMM3: S2 = Mid1 @ att^T ----
    mm_loop(hR2, hR3, acc, wm, wn, aOff, bOff);
    __syncthreads();

    // ---- ew -> R2 async; S2 -> R3 + node partials ----
    {
        const uint32_t r2b = sptr(hR2);
        for (int idx = tid; idx < 116 * 29; idx += LT) {
            const int r = idx / 29;
            const int c = (idx - r * 29) << 2;
            CP8(r2b + (uint32_t)(r * SH + c) * 2, ewh + r * R + c);
        }
        CP_COMMIT();
    }
#pragma unroll
    for (int mt = 0; mt < 2; mt++)
#pragma unroll
        for (int h = 0; h < 2; h++) {
            const int row = wm * 32 + mt * 16 + g + 8 * h;
            float a0 = 0.f, a1 = 0.f, a2 = 0.f;
#pragma unroll
            for (int nt = 0; nt < 4; nt++) {
                const int col = wn * 32 + nt * 8 + 2 * tig;
                const float v0 = acc[mt][nt][2 * h];
                const float v1 = acc[mt][nt][2 * h + 1];
                if (col < 120)
                    *(__half2*)(hR3 + row * SH + col) = __floats2half2_rn(v0, v1);
                if (row < R && col < R) {
                    a0 = fmaf(v0, sXs[col * 3 + 0], fmaf(v1, sXs[col * 3 + 3], a0));
                    a1 = fmaf(v0, sXs[col * 3 + 1], fmaf(v1, sXs[col * 3 + 4], a1));
                    a2 = fmaf(v0, sXs[col * 3 + 2], fmaf(v1, sXs[col * 3 + 5], a2));
                }
            }
            a0 += __shfl_xor_sync(0xffffffffu, a0, 1);
            a0 += __shfl_xor_sync(0xffffffffu, a0, 2);
            a1 += __shfl_xor_sync(0xffffffffu, a1, 1);
            a1 += __shfl_xor_sync(0xffffffffu, a1, 2);
            a2 += __shfl_xor_sync(0xffffffffu, a2, 1);
            a2 += __shfl_xor_sync(0xffffffffu, a2, 2);
            if (tig == 0) {
                pA[0 * 512 + wn * 128 + row] = a0;
                pA[1 * 512 + wn * 128 + row] = a1;
                pA[2 * 512 + wn * 128 + row] = a2;
            }
        }
#pragma unroll
    for (int mt = 0; mt < 2; mt++)
#pragma unroll
        for (int nt = 0; nt < 4; nt++)
#pragma unroll
            for (int i = 0; i < 4; i++) acc[mt][nt][i] = 0.f;
    CP_WAIT0();
    __syncthreads();

    // ---- GEMM2: Et = ew @ Z^T ----
    mm_loop(hR2, hR1, acc, wm, wn, aOff, bOff);
    __syncthreads();

    // ---- Et -> R1 ----
#pragma unroll
    for (int mt = 0; mt < 2; mt++)
#pragma unroll
        for (int h = 0; h < 2; h++) {
            const int row = wm * 32 + mt * 16 + g + 8 * h;
#pragma unroll
            for (int nt = 0; nt < 4; nt++) {
                const int col = wn * 32 + nt * 8 + 2 * tig;
                if (col < 120)
                    *(__half2*)(hR1 + row * SH + col) =
                        __floats2half2_rn(acc[mt][nt][2 * h], acc[mt][nt][2 * h + 1]);
            }
        }
#pragma unroll
    for (int mt = 0; mt < 2; mt++)
#pragma unroll
        for (int nt = 0; nt < 4; nt++)
#pragma unroll
            for (int i = 0; i < 4; i++) acc[mt][nt][i] = 0.f;
    __syncthreads();

    // ---- GEMM4: Z1 = S2 @ Et^T + eb ----
    mm_loop(hR3, hR1, acc, wm, wn, aOff, bOff);

    // ---- epilogue: Z1 (fp16) + edge stats (fp32, pre-rounding) ----
    __half* Cb = g_Z1h + (size_t)b * RR;
#pragma unroll
    for (int mt = 0; mt < 2; mt++) {
#pragma unroll
        for (int h = 0; h < 2; h++) {
            const int row = wm * 32 + mt * 16 + g + 8 * h;
            float s = 0.f, q = 0.f;
#pragma unroll
            for (int nt = 0; nt < 4; nt++) {
                const int col = wn * 32 + nt * 8 + 2 * tig;
                if (col < R) {
                    const float v0 = acc[mt][nt][2 * h] + sb2[col];
                    const float v1 = acc[mt][nt][2 * h + 1] + sb2[col + 1];
                    if (row < R)
                        *(__half2*)(Cb + (size_t)row * R + col) =
                            __floats2half2_rn(v0, v1);
                    s += v0 + v1;
                    q += v0 * v0 + v1 * v1;
                }
            }
            s += __shfl_xor_sync(0xffffffffu, s, 1);
            s += __shfl_xor_sync(0xffffffffu, s, 2);
            q += __shfl_xor_sync(0xffffffffu, q, 1);
            q += __shfl_xor_sync(0xffffffffu, q, 2);
            if (tig == 0) { pS[wn * 128 + row] = s; pQ[wn * 128 + row] = q; }
        }
    }
    __syncthreads();
    if (tid < R) {
        const float s = pS[tid] + pS[128 + tid] + pS[256 + tid] + pS[384 + tid];
        const float q = pQ[tid] + pQ[128 + tid] + pQ[256 + tid] + pQ[384 + tid];
        g_ps[tid * NB + b] = s;
        g_pq[tid * NB + b] = q;
    }
    // ---- node path finish: X1 = (S2 @ X) @ nw^T + nb, node stats ----
    if (tid < R) {
        const int n = tid;
        const float a0 = pA[0 * 512 + n] + pA[0 * 512 + 128 + n] +
                         pA[0 * 512 + 256 + n] + pA[0 * 512 + 384 + n];
        const float a1 = pA[1 * 512 + n] + pA[1 * 512 + 128 + n] +
                         pA[1 * 512 + 256 + n] + pA[1 * 512 + 384 + n];
        const float a2 = pA[2 * 512 + n] + pA[2 * 512 + 128 + n] +
                         pA[2 * 512 + 256 + n] + pA[2 * 512 + 384 + n];
        float ps = 0.f, pq = 0.f;
        float* dst = g_X1 + (size_t)b * (R * 3) + n * 3;
#pragma unroll
        for (int o = 0; o < 3; o++) {
            const float v = fmaf(nw[o * 3 + 0], a0,
                            fmaf(nw[o * 3 + 1], a1,
                            fmaf(nw[o * 3 + 2], a2, nb_[o])));
            dst[o] = v;
            ps += v;
            pq = fmaf(v, v, pq);
        }
        g_psN[n * NB + b] = ps;
        g_pqN[n * NB + b] = pq;
    }
}

// ----------------------------------------------------------------------------
// Both BN channel reductions fused per channel. grid = R, block = 512.
// Threads 0..255 reduce edge channel n; 256..511 reduce node channel n.
// ----------------------------------------------------------------------------
__global__ void __launch_bounds__(512)
k_reduce_both(const float* __restrict__ geg, const float* __restrict__ geb,
              const float* __restrict__ gng, const float* __restrict__ gnb) {
    const int n = blockIdx.x;
    const int half = threadIdx.x >> 8;        // 0 = edge, 1 = node
    const int t = threadIdx.x & 255;
    const float* PS = half ? g_psN : g_ps;
    const float* PQ = half ? g_pqN : g_pq;
    float s = 0.f, q = 0.f;
    // 256 threads x float2 x 2 passes = 1024 floats
#pragma unroll
    for (int it = 0; it < 2; it++) {
        const int b2 = it * 256 + t;
        const float2 vs = *(const float2*)(PS + n * NB + 2 * b2);
        const float2 vq = *(const float2*)(PQ + n * NB + 2 * b2);
        s += vs.x + vs.y;
        q += vq.x + vq.y;
    }
    __shared__ float shs[2][8], shq[2][8];
    s = wsum(s); q = wsum(q);
    const int w = t >> 5, lane = t & 31;
    if (lane == 0) { shs[half][w] = s; shq[half][w] = q; }
    __syncthreads();
    if (t == 0) {
        s = shs[half][0] + shs[half][1] + shs[half][2] + shs[half][3] +
            shs[half][4] + shs[half][5] + shs[half][6] + shs[half][7];
        q = shq[half][0] + shq[half][1] + shq[half][2] + shq[half][3] +
            shq[half][4] + shq[half][5] + shq[half][6] + shq[half][7];
        const float invcnt = half ? (1.f / (float)(3 * NB)) : (1.f / (float)(NB * R));
        const float mean = s * invcnt;
        const float var = q * invcnt - mean * mean;
        const float rstd = rsqrtf(var + EPS);
        const float gg = half ? gng[n] : geg[n];
        const float bb = half ? gnb[n] : geb[n];
        const float sc = rstd * gg;
        if (half) { g_scaleN[n] = sc; g_shiftN[n] = bb - mean * sc; }
        else      { g_scale[n] = sc;  g_shift[n] = bb - mean * sc; }
    }
}

// ----------------------------------------------------------------------------
// Combined: Z+=relu(bn(Z1h)) & down-edge / X+=relu(bn(X1)) & down-node,
// plus (layer 0 only) fused fp16 weight conversion in tail blocks.
// grid = 29696 + 928 (+CVTB when cvt!=0), block = 128.
// ----------------------------------------------------------------------------
__global__ void k_apply_down(const float* __restrict__ dew, const float* __restrict__ deb,
                             const float* __restrict__ dnw, const float* __restrict__ dnb,
                             const float* __restrict__ srcZ, const float* __restrict__ srcX,
                             const float* __restrict__ aw2f, const float* __restrict__ ewf,
                             int offE, int offN, int dpE, int dpN, int apply) {
    __shared__ float sh[8];
    if (blockIdx.x >= 30624) {
        // ---------------- weight conversion (layer 0 launch only) ----------------
        // 128 threads x 2 elements = 256 elements per block
        const int i = (blockIdx.x - 30624) * 256 + threadIdx.x * 2;
        const int N = LAYERS * RR;
        if (i < N) {
            g_wh[i] = __float2half_rn(aw2f[i]);
            if (i + 1 < N) g_wh[i + 1] = __float2half_rn(aw2f[i + 1]);
            else if (i + 1 < 2 * N) g_wh[i + 1] = __float2half_rn(ewf[i + 1 - N]);
        } else if (i < 2 * N) {
            g_wh[i] = __float2half_rn(ewf[i - N]);
            if (i + 1 < 2 * N) g_wh[i + 1] = __float2half_rn(ewf[i + 1 - N]);
        }
        return;
    }
    if (blockIdx.x < 29696) {
        // ---------------- edge ----------------
        const int wrp = threadIdx.x >> 5, lane = threadIdx.x & 31;
        const int rowid = blockIdx.x * 4 + wrp;
        const int b = rowid / R, n = rowid - b * R;
        float w0[4], w1[4], w2[4];
#pragma unroll
        for (int d = 0; d < 4; d++) {
            const int e = 4 * lane + d;
            w1[d] = (e < 78) ? dew[e] : 0.f;
            w0[d] = (e < 39) ? dew[39 + e] : 0.f;
            w2[d] = (e >= 39 && e < 116) ? dew[e - 39] : 0.f;
        }
        float4 v = make_float4(0.f, 0.f, 0.f, 0.f);
        __half2* zrow = (__half2*)(g_Zh + (size_t)rowid * R);
        if (lane < 29) {
            if (apply) {
                const uint2 zu = *(const uint2*)(zrow + 2 * lane);
                const uint2 uu = *(const uint2*)((const __half2*)(g_Z1h + (size_t)rowid * R) + 2 * lane);
                const float2 z01 = __half22float2(*(const __half2*)&zu.x);
                const float2 z23 = __half22float2(*(const __half2*)&zu.y);
                const float2 u01 = __half22float2(*(const __half2*)&uu.x);
                const float2 u23 = __half22float2(*(const __half2*)&uu.y);
                const float sc = g_scale[n], sf = g_shift[n];
                v.x = z01.x + fmaxf(fmaf(u01.x, sc, sf), 0.f);
                v.y = z01.y + fmaxf(fmaf(u01.y, sc, sf), 0.f);
                v.z = z23.x + fmaxf(fmaf(u23.x, sc, sf), 0.f);
                v.w = z23.y + fmaxf(fmaf(u23.y, sc, sf), 0.f);
                uint2 ou;
                *(__half2*)&ou.x = __floats2half2_rn(v.x, v.y);
                *(__half2*)&ou.y = __floats2half2_rn(v.z, v.w);
                *(uint2*)(zrow + 2 * lane) = ou;
            } else {
                v = *(const float4*)(srcZ + (size_t)rowid * R + 4 * lane);
                uint2 ou;
                *(__half2*)&ou.x = __floats2half2_rn(v.x, v.y);
                *(__half2*)&ou.y = __floats2half2_rn(v.z, v.w);
                *(uint2*)(zrow + 2 * lane) = ou;
            }
        }
        float f0 = 0.f, f1 = 0.f, f2 = 0.f;
        const float vv[4] = {v.x, v.y, v.z, v.w};
#pragma unroll
        for (int d = 0; d < 4; d++) {
            f1 = fmaf(vv[d], w1[d], f1);
            f0 = fmaf(vv[d], w0[d], f0);
            f2 = fmaf(vv[d], w2[d], f2);
        }
        f0 = wsum(f0); f1 = wsum(f1); f2 = wsum(f2);
        float s = 0.f, q = 0.f;
        if (lane == 0) {
            const float bb = deb[0];
            f0 = fmaxf(f0 + bb, 0.f);
            f1 = fmaxf(f1 + bb, 0.f);
            f2 = fmaxf(f2 + bb, 0.f);
            float* dst = g_XZ + (size_t)b * FEAT + offE + n * 3;
            dst[0] = f0; dst[1] = f1; dst[2] = f2;
            s = f0 + f1 + f2;
            q = f0 * f0 + f1 * f1 + f2 * f2;
            sh[wrp] = s; sh[4 + wrp] = q;
        }
        __syncthreads();
        if (threadIdx.x == 0) {
            g_dpS[dpE + blockIdx.x] = sh[0] + sh[1] + sh[2] + sh[3];
            g_dpQ[dpE + blockIdx.x] = sh[4] + sh[5] + sh[6] + sh[7];
        }
    } else {
        // ---------------- node ----------------
        const int bid = blockIdx.x - 29696;
        const int idx = bid * 128 + threadIdx.x;
        float* xp = g_X + (size_t)idx * 3;
        float x0, x1, x2;
        if (apply) {
            x0 = xp[0]; x1 = xp[1]; x2 = xp[2];
            const int n = idx % R;
            const float sc = g_scaleN[n], sf = g_shiftN[n];
            const float* up = g_X1 + (size_t)idx * 3;
            x0 += fmaxf(fmaf(up[0], sc, sf), 0.f);
            x1 += fmaxf(fmaf(up[1], sc, sf), 0.f);
            x2 += fmaxf(fmaf(up[2], sc, sf), 0.f);
            xp[0] = x0; xp[1] = x1; xp[2] = x2;
        } else {
            const float* sp = srcX + (size_t)idx * 3;
            x0 = sp[0]; x1 = sp[1]; x2 = sp[2];
            xp[0] = x0; xp[1] = x1; xp[2] = x2;
        }
        const float f = fmaxf(fmaf(x0, dnw[0], fmaf(x1, dnw[1], fmaf(x2, dnw[2], dnb[0]))), 0.f);
        const int b = idx / R, r = idx - (idx / R) * R;
        g_XZ[(size_t)b * FEAT + offN + r] = f;
        const float s = wsum(f);
        const float q = wsum(f * f);
        const int wr = threadIdx.x >> 5, lane = threadIdx.x & 31;
        if (lane == 0) { sh[wr] = s; sh[4 + wr] = q; }
        __syncthreads();
        if (threadIdx.x == 0) {
            g_dpS[dpN + bid] = sh[0] + sh[1] + sh[2] + sh[3];
            g_dpQ[dpN + bid] = sh[4] + sh[5] + sh[6] + sh[7];
        }
    }
}

// ----------------------------------------------------------------------------
// All 10 down-sample reductions at once. grid = 10, block = 1024.
// ----------------------------------------------------------------------------
__global__ void k_dreduce_all(const float* __restrict__ dng, const float* __restrict__ dnbe,
                              const float* __restrict__ deg, const float* __restrict__ debe) {
    const int sgm = blockIdx.x;
    const bool node = sgm < 5;
    const int l = node ? sgm : sgm - 5;
    const int base = node ? (EDGET + l * 928) : (l * 29696);
    const int cnt = node ? 928 : 29696;
    const float invcnt = node ? (1.f / (float)(NB * R)) : (1.f / (float)(NB * R * 3));
    float s = 0.f, q = 0.f;
    for (int i = threadIdx.x; i < cnt; i += 1024) {
        s += g_dpS[base + i];
        q += g_dpQ[base + i];
    }
    __shared__ float shs[32], shq[32];
    s = wsum(s); q = wsum(q);
    const int w = threadIdx.x >> 5, lane = threadIdx.x & 31;
    if (lane == 0) { shs[w] = s; shq[w] = q; }
    __syncthreads();
    if (w == 0) {
        s = shs[lane]; q = shq[lane];
        s = wsum(s); q = wsum(q);
        if (lane == 0) {
            const float mean = s * invcnt;
            const float var = q * invcnt - mean * mean;
            const float rstd = rsqrtf(var + EPS);
            const float gg = node ? dng[l] : deg[l];
            const float bb = node ? dnbe[l] : debe[l];
            const float sc = rstd * gg;
            g_dssArr[2 * sgm]     = sc;
            g_dssArr[2 * sgm + 1] = bb - mean * sc;
        }
    }
}

// ----------------------------------------------------------------------------
// Classifier GEMM (fp16) + fused out-projection partials.
// ----------------------------------------------------------------------------
#define CSTR 24

__global__ void __launch_bounds__(256)
k_cls(const float* __restrict__ A, const float* __restrict__ Bm,
      const float* __restrict__ bias, const float* __restrict__ cw2)
{
    __shared__ __half sA[2][128 * CSTR];
    __shared__ __half sB[2][64 * CSTR];
    __shared__ float sbc[64];
    __shared__ float sc2[2][64];
    __shared__ float pOut[128][4];
    const int tid = threadIdx.x;
    const int wid = tid >> 5, lane = tid & 31;
    const int wm = wid >> 1, wn = wid & 1;
    const int g = lane >> 2, tig = lane & 3;
    const int row0 = blockIdx.y * 128, col0 = blockIdx.x * 64;

    if (tid < 64) {
        sbc[tid] = bias[col0 + tid];
        sc2[0][tid] = cw2[col0 + tid];
        sc2[1][tid] = cw2[HID + col0 + tid];
    }

    float4 pa0, pa1, pb;
    float fsc, fsh;
    const int ar0 = tid >> 2, ac0 = (tid & 3) << 2;
    const int ar1 = (tid + 256) >> 2, ac1 = ac0;
    const int br = tid >> 2, bc = (tid & 3) << 2;

    auto fetch = [&](int k0) {
        const int k = k0 + ac0;
        const int sgm = (k < 580) ? (k / 116) : (5 + (k - 580) / 348);
        fsc = g_dssArr[2 * sgm];
        fsh = g_dssArr[2 * sgm + 1];
        pa0 = *(const float4*)(A + (size_t)(row0 + ar0) * FEAT + k0 + ac0);
        pa1 = *(const float4*)(A + (size_t)(row0 + ar1) * FEAT + k0 + ac1);
        pb  = *(const float4*)(Bm + (size_t)(col0 + br) * FEAT + k0 + bc);
    };
    auto store = [&](int buf) {
        __half2* d0 = (__half2*)&sA[buf][ar0 * CSTR + ac0];
        d0[0] = __floats2half2_rn(fmaf(pa0.x, fsc, fsh), fmaf(pa0.y, fsc, fsh));
        d0[1] = __floats2half2_rn(fmaf(pa0.z, fsc, fsh), fmaf(pa0.w, fsc, fsh));
        __half2* d1 = (__half2*)&sA[buf][ar1 * CSTR + ac1];
        d1[0] = __floats2half2_rn(fmaf(pa1.x, fsc, fsh), fmaf(pa1.y, fsc, fsh));
        d1[1] = __floats2half2_rn(fmaf(pa1.z, fsc, fsh), fmaf(pa1.w, fsc, fsh));
        __half2* d2 = (__half2*)&sB[buf][br * CSTR + bc];
        d2[0] = __floats2half2_rn(pb.x, pb.y);
        d2[1] = __floats2half2_rn(pb.z, pb.w);
    };

    float acc[2][4][4];
#pragma unroll
    for (int mt = 0; mt < 2; mt++)
#pragma unroll
        for (int nt = 0; nt < 4; nt++)
#pragma unroll
            for (int i = 0; i < 4; i++) acc[mt][nt][i] = 0.f;

    const int NS = FEAT / 16;   // 145
    fetch(0);
    store(0);
    __syncthreads();
    int buf = 0;
    for (int ks = 0; ks < NS; ks++) {
        if (ks + 1 < NS) fetch((ks + 1) * 16);
        uint32_t af[2][4], bf[4][2];
#pragma unroll
        for (int mt = 0; mt < 2; mt++) {
            const __half* p0 = &sA[buf][(wm * 32 + mt * 16 + g) * CSTR + 2 * tig];
            af[mt][0] = *(const uint32_t*)(p0);
            af[mt][1] = *(const uint32_t*)(p0 + 8 * CSTR);
            af[mt][2] = *(const uint32_t*)(p0 + 8);
            af[mt][3] = *(const uint32_t*)(p0 + 8 * CSTR + 8);
        }
#pragma unroll
        for (int nt = 0; nt < 4; nt++) {
            const __half* q0 = &sB[buf][(wn * 32 + nt * 8 + g) * CSTR + 2 * tig];
            bf[nt][0] = *(const uint32_t*)(q0);
            bf[nt][1] = *(const uint32_t*)(q0 + 8);
        }
#pragma unroll
        for (int mt = 0; mt < 2; mt++)
#pragma unroll
            for (int nt = 0; nt < 4; nt++)
                mma16(acc[mt][nt], af[mt], bf[nt]);
        if (ks + 1 < NS) store(buf ^ 1);
        __syncthreads();
        buf ^= 1;
    }

    // fused epilogue: relu + dot with cw2 slice -> per-row partials
#pragma unroll
    for (int mt = 0; mt < 2; mt++)
#pragma unroll
        for (int h = 0; h < 2; h++) {
            const int rl = wm * 32 + mt * 16 + g + 8 * h;
            float p0 = 0.f, p1 = 0.f;
#pragma unroll
            for (int nt = 0; nt < 4; nt++) {
                const int col = wn * 32 + nt * 8 + 2 * tig;
                const float v0 = fmaxf(acc[mt][nt][2 * h] + sbc[col], 0.f);
                const float v1 = fmaxf(acc[mt][nt][2 * h + 1] + sbc[col + 1], 0.f);
                p0 = fmaf(v0, sc2[0][col], fmaf(v1, sc2[0][col + 1], p0));
                p1 = fmaf(v0, sc2[1][col], fmaf(v1, sc2[1][col + 1], p1));
            }
            p0 += __shfl_xor_sync(0xffffffffu, p0, 1);
            p0 += __shfl_xor_sync(0xffffffffu, p0, 2);
            p1 += __shfl_xor_sync(0xffffffffu, p1, 1);
            p1 += __shfl_xor_sync(0xffffffffu, p1, 2);
            if (tig == 0) {
                pOut[rl][wn * 2 + 0] = p0;
                pOut[rl][wn * 2 + 1] = p1;
            }
        }
    __syncthreads();
    if (tid < 128) {
        g_Hp[(size_t)(row0 + tid) * 32 + blockIdx.x * 2 + 0] = pOut[tid][0] + pOut[tid][2];
        g_Hp[(size_t)(row0 + tid) * 32 + blockIdx.x * 2 + 1] = pOut[tid][1] + pOut[tid][3];
    }
}

// Final fold: out[b][c] = sum_k g_Hp[b][2k+c] + cb2[c]. grid = 4, block = 256.
__global__ void k_out2(const float* __restrict__ cb2, float* __restrict__ out) {
    const int b = blockIdx.x * 256 + threadIdx.x;
    const float* p = g_Hp + (size_t)b * 32;
    float a0 = 0.f, a1 = 0.f;
#pragma unroll
    for (int k = 0; k < 16; k++) {
        a0 += p[2 * k];
        a1 += p[2 * k + 1];
    }
    out[b * 2 + 0] = a0 + cb2[0];
    out[b * 2 + 1] = a1 + cb2[1];
}

// ----------------------------------------------------------------------------
// Host orchestration (graph-capturable: kernel launches only)
// ----------------------------------------------------------------------------
extern "C" void kernel_launch(void* const* d_in, const int* in_sizes, int n_in,
                              void* d_out, int out_size) {
    const float* X_in  = (const float*)d_in[0];
    const float* Z_in  = (const float*)d_in[1];
    const float* aw1   = (const float*)d_in[2];
    const float* ab1   = (const float*)d_in[3];
    const float* aw2   = (const float*)d_in[4];
    const float* ab2   = (const float*)d_in[5];
    const float* nw    = (const float*)d_in[6];
    const float* nb    = (const float*)d_in[7];
    const float* ew    = (const float*)d_in[8];
    const float* eb    = (const float*)d_in[9];
    const float* gn_g  = (const float*)d_in[10];
    const float* gn_b  = (const float*)d_in[11];
    const float* ge_g  = (const float*)d_in[12];
    const float* ge_b  = (const float*)d_in[13];
    const float* dn_w  = (const float*)d_in[14];
    const float* dn_b  = (const float*)d_in[15];
    const float* dn_g  = (const float*)d_in[16];
    const float* dn_be = (const float*)d_in[17];
    const float* de_w  = (const float*)d_in[18];
    const float* de_b  = (const float*)d_in[19];
    const float* de_g  = (const float*)d_in[20];
    const float* de_be = (const float*)d_in[21];
    const float* cw1   = (const float*)d_in[22];
    const float* cb1   = (const float*)d_in[23];
    const float* cw2   = (const float*)d_in[24];
    const float* cb2   = (const float*)d_in[25];
    float* out = (float*)d_out;

    cudaFuncSetAttribute(k_layer, cudaFuncAttributeMaxDynamicSharedMemorySize, SM_TOTB);

    float* pXZ;
    __half* pWh;
    cudaGetSymbolAddress((void**)&pXZ, g_XZ);
    cudaGetSymbolAddress((void**)&pWh, g_wh);

    // layer-0 down-sample + input pass-through + fused weight fp16 conversion
    k_apply_down<<<29696 + 928 + CVTB, 128>>>(de_w, de_b, dn_w, dn_b,
                                              Z_in, X_in, aw2, ew,
                                              580, 0, 0, EDGET, 0);

    for (int i = 0; i < LAYERS; i++) {
        k_layer<<<NB, LT, SM_TOTB>>>(pWh + (size_t)i * RR, ab2 + i * R,
                                     aw1 + 9 * i, ab1 + 3 * i,
                                     pWh + (size_t)(LAYERS + i) * RR, eb + i * R,
                                     nw + 9 * i, nb + 3 * i);
        k_reduce_both<<<R, 512>>>(ge_g + i * R, ge_b + i * R,
                                  gn_g + i * R, gn_b + i * R);
        const int l = i + 1;
        k_apply_down<<<29696 + 928, 128>>>(de_w + 78 * l, de_b + l,
                                           dn_w + 3 * l, dn_b + l,
                                           nullptr, nullptr, nullptr, nullptr,
                                           580 + l * 348, l * R,
                                           l * 29696, EDGET + l * 928, 1);
    }

    k_dreduce_all<<<10, 1024>>>(dn_g, dn_be, de_g, de_be);
    k_cls<<<dim3(HID / 64, NB / 128), 256>>>(pXZ, cw1, cb1, cw2);
    k_out2<<<NB / 256, 256>>>(cb2, out);
}

// round 16
// speedup vs baseline: 1.7627x; 1.0073x over previous
#include <cuda_runtime.h>
#include <cuda_fp16.h>
#include <cstddef>
#include <cstdint>

// ----------------------------------------------------------------------------
// Problem constants
// ----------------------------------------------------------------------------
#define NB 1024            // batch
#define R 116              // ROIs
#define RR (R * R)         // 13456
#define LAYERS 4
#define FEAT 2320          // R*4*(L+1)
#define HID 1024
#define EPS 1e-5f

#define SH 136             // smem tile row stride (halves) — LDSM conflict-free
#define REGH (128 * SH)    // halves per region (17408)

// down-sample partial slot layout
#define DP_E0 0            // edge l=0: 29696 slots
#define DP_E4 29696        // edge l=4: 29696 slots
#define DP_EF 59392        // edge l=1..3: 1024 each
#define DP_N0 62464        // node l=0: 928
#define DP_N4 63392        // node l=4: 928
#define DP_NF 64320        // node l=1..3: 1024 each
#define DPTOT 67392

// weight-conversion tail blocks: 128 threads x 2 elems = 256/block
#define CVTB ((2 * LAYERS * RR + 255) / 256)

// ----------------------------------------------------------------------------
// Device scratch (static allocation only)
// ----------------------------------------------------------------------------
__device__ __align__(16) __half g_Zh [(size_t)NB * RR];   // carried Z (fp16)
__device__ __align__(16) __half g_Z1h[(size_t)NB * RR];
__device__ __align__(16) __half g_wh [(size_t)2 * LAYERS * RR]; // aw2 | ew (fp16)
__device__ __align__(16) float  g_X  [NB * R * 3];
__device__ __align__(16) float  g_X1 [NB * R * 3];
__device__ __align__(16) float  g_XZ [(size_t)NB * FEAT];
__device__ __align__(16) float  g_Hp [(size_t)NB * 32];   // cls partial dots
__device__ float g_ps [R * NB];     // edge BN partials
__device__ float g_pq [R * NB];
__device__ float g_psN[R * NB];     // node BN partials
__device__ float g_pqN[R * NB];
__device__ float g_scale [R],  g_shift [R];   // edge BN affine
__device__ float g_scaleN[R],  g_shiftN[R];   // node BN affine
__device__ float g_dpS[DPTOT], g_dpQ[DPTOT];  // down-sample partials
__device__ float g_dssArr[20];                // 10 segments x (scale, shift)

__device__ __forceinline__ float wsum(float v) {
#pragma unroll
    for (int o = 16; o; o >>= 1) v += __shfl_xor_sync(0xffffffffu, v, o);
    return v;
}

__device__ __forceinline__ uint32_t sptr(const void* p) {
    return (uint32_t)__cvta_generic_to_shared(p);
}

// cp.async 8-byte copy (sm_80 baseline; compiles at compute_103)
#define CP8(saddr, gptr) \
    asm volatile("cp.async.ca.shared.global [%0], [%1], 8;" \
                 :: "r"(saddr), "l"(gptr))
#define CP_COMMIT() asm volatile("cp.async.commit_group;")
#define CP_WAIT0()  asm volatile("cp.async.wait_group 0;")

// ldmatrix x4: loads 4 8x8 b16 tiles.
#define LDSM4(r0, r1, r2, r3, addr) \
    asm volatile("ldmatrix.sync.aligned.m8n8.x4.shared.b16 {%0,%1,%2,%3}, [%4];" \
                 : "=r"(r0), "=r"(r1), "=r"(r2), "=r"(r3) : "r"(addr))

// mma.sync m16n8k16 fp16 inputs, fp32 accumulate
__device__ __forceinline__ void mma16(float* d, const uint32_t* a, const uint32_t* b) {
    asm volatile(
        "mma.sync.aligned.m16n8k16.row.col.f32.f16.f16.f32 "
        "{%0,%1,%2,%3},{%4,%5,%6,%7},{%8,%9},{%0,%1,%2,%3};"
        : "+f"(d[0]), "+f"(d[1]), "+f"(d[2]), "+f"(d[3])
        : "r"(a[0]), "r"(a[1]), "r"(a[2]), "r"(a[3]), "r"(b[0]), "r"(b[1]));
}

// 128x128x128 NT GEMM over fp16 smem tiles (stride SH halves), 16 warps,
// warp tile 32x32, 8 k-steps of K=16. 4 LDSM.x4 + 8 MMA per k-step.
__device__ __forceinline__ void mm_loop(const __half* __restrict__ sA,
                                        const __half* __restrict__ sB,
                                        float (&acc)[2][4][4],
                                        int wm, int wn,
                                        uint32_t aOff, uint32_t bOff) {
    const uint32_t a0b = sptr(sA) + (uint32_t)(wm * 32 * SH * 2) + aOff;
    const uint32_t a1b = a0b + 16 * SH * 2;
    const uint32_t b0b = sptr(sB) + (uint32_t)(wn * 32 * SH * 2) + bOff;
    const uint32_t b1b = b0b + 16 * SH * 2;
#pragma unroll
    for (int ks = 0; ks < 8; ks++) {
        const uint32_t off = ks * 32;       // 16 halves = 32 bytes per k-step
        uint32_t af[2][4], bf[4][2];
        LDSM4(af[0][0], af[0][1], af[0][2], af[0][3], a0b + off);
        LDSM4(af[1][0], af[1][1], af[1][2], af[1][3], a1b + off);
        LDSM4(bf[0][0], bf[0][1], bf[1][0], bf[1][1], b0b + off);
        LDSM4(bf[2][0], bf[2][1], bf[3][0], bf[3][1], b1b + off);
#pragma unroll
        for (int mt = 0; mt < 2; mt++)
#pragma unroll
            for (int nt = 0; nt < 4; nt++)
                mma16(acc[mt][nt], af[mt], bf[nt]);
    }
}

// ----------------------------------------------------------------------------
// Mega layer kernel (fp16 tiles): one CTA per batch, 512 threads (16 warps).
// apply=1 (layers 1..3): prologue also applies Z/X BN residual updates and
// emits down-edge / down-node features + per-batch partials. Z1h is staged
// into a 4th smem region via cp.async (overlapped with the softmax).
// ----------------------------------------------------------------------------
#define HBYTES (4 * REGH * 2)      // 139264
#define EXT_B1 0
#define EXT_B2 128
#define EXT_KS 256                 // 352
#define EXT_XS 608                 // 352
#define EXT_PS 960                 // 512
#define EXT_PQ 1472                // 512
#define EXT_PA 1984                // 1536
#define EXT_TOT 3520
#define SM_TOTB (HBYTES + EXT_TOT * 4)   // 153344

#define LT 512

__global__ void __launch_bounds__(LT, 1)
k_layer(const __half* __restrict__ aw2h, const float* __restrict__ ab2,
        const float* __restrict__ aw1, const float* __restrict__ ab1,
        const __half* __restrict__ ewh,  const float* __restrict__ eb,
        const float* __restrict__ nw,  const float* __restrict__ nb_,
        const float* __restrict__ dew, const float* __restrict__ deb,
        const float* __restrict__ dnw, const float* __restrict__ dnb,
        int offE, int offN, int dpE, int dpN, int apply)
{
    extern __shared__ __align__(16) char smraw[];
    __half* hR1 = (__half*)smraw;            // Z -> Et
    __half* hR2 = hR1 + REGH;                // aw2 -> Mid1 -> ew
    __half* hR3 = hR2 + REGH;                // att -> S2
    __half* hR4 = hR3 + REGH;                // Z1h staging (apply only)
    float* fext = (float*)(smraw + HBYTES);
    float* sb1 = fext + EXT_B1;
    float* sb2 = fext + EXT_B2;
    float* sKs = fext + EXT_KS;
    float* sXs = fext + EXT_XS;
    float* pS  = fext + EXT_PS;
    float* pQ  = fext + EXT_PQ;
    float* pA  = fext + EXT_PA;

    const int tid = threadIdx.x;
    const int b = blockIdx.x;
    const int wid = tid >> 5, lane = tid & 31;
    const int wm = wid >> 2, wn = wid & 3;
    const int g = lane >> 2, tig = lane & 3;

    // ldmatrix per-lane byte offsets
    const uint32_t aOff = (uint32_t)((lane & 15) * SH * 2 + 16 * (lane >> 4));
    const uint32_t bOff = (uint32_t)(((lane & 7) + 8 * (lane >> 4)) * SH * 2 +
                                     16 * ((lane >> 3) & 1));

    // ---- phase 0: biases, X update/Ks, pads; async Z/Z1/aw2 loads ----
    if (tid < 128) {
        sb1[tid] = (tid < R) ? ab2[tid] : 0.f;
        sb2[tid] = (tid < R) ? eb[tid] : 0.f;
    }
    if (tid < R) {
        float* xp = g_X + (size_t)b * (R * 3) + tid * 3;
        float y0, y1, y2;
        if (apply) {
            const float scn = g_scaleN[tid], sfn = g_shiftN[tid];
            const float* up = g_X1 + (size_t)b * (R * 3) + tid * 3;
            y0 = xp[0] + fmaxf(fmaf(up[0], scn, sfn), 0.f);
            y1 = xp[1] + fmaxf(fmaf(up[1], scn, sfn), 0.f);
            y2 = xp[2] + fmaxf(fmaf(up[2], scn, sfn), 0.f);
            xp[0] = y0; xp[1] = y1; xp[2] = y2;
            const float f = fmaxf(fmaf(y0, dnw[0],
                             fmaf(y1, dnw[1], fmaf(y2, dnw[2], dnb[0]))), 0.f);
            g_XZ[(size_t)b * FEAT + offN + tid] = f;
            pA[tid] = f;                       // node feature scratch
        } else {
            y0 = xp[0]; y1 = xp[1]; y2 = xp[2];
        }
        sXs[tid * 3 + 0] = y0; sXs[tid * 3 + 1] = y1; sXs[tid * 3 + 2] = y2;
#pragma unroll
        for (int o = 0; o < 3; o++)
            sKs[tid * 3 + o] = fmaf(aw1[o * 3 + 0], y0,
                                fmaf(aw1[o * 3 + 1], y1,
                                fmaf(aw1[o * 3 + 2], y2, ab1[o])));
    }
    // zero pad rows 116..127, cols 0..127: 12 rows x 16 uint4, regions R1..R3
    {
        const uint4 z4u = make_uint4(0, 0, 0, 0);
        for (int idx = tid; idx < 3 * 192; idx += LT) {
            const int t = idx / 192, i2 = idx - t * 192;
            const int r = 116 + i2 / 16, c8 = (i2 & 15) * 8;
            *(uint4*)(hR1 + (size_t)t * REGH + r * SH + c8) = z4u;
        }
    }
    // zero pad cols 116..127 rows 0..115: 3 uint2 per row, regions R1..R3
    {
        const uint2 z2u = make_uint2(0, 0);
        for (int idx = tid; idx < 3 * 116; idx += LT) {
            const int t = idx / 116, r = idx - t * 116;
            uint2* p = (uint2*)(hR1 + (size_t)t * REGH + r * SH + 116);
            p[0] = z2u; p[1] = z2u; p[2] = z2u;
        }
    }
    // Zh -> R1, aw2 -> R2 (+ Z1h -> R4 when applying), via cp.async
    {
        const __half* Zb = g_Zh + (size_t)b * RR;
        const __half* Ub = g_Z1h + (size_t)b * RR;
        const uint32_t r1b = sptr(hR1), r2b = sptr(hR2), r4b = sptr(hR4);
        for (int idx = tid; idx < 116 * 29; idx += LT) {
            const int r = idx / 29;
            const int c = (idx - r * 29) << 2;
            const uint32_t so = (uint32_t)(r * SH + c) * 2;
            CP8(r1b + so, Zb + r * R + c);
            CP8(r2b + so, aw2h + r * R + c);
            if (apply) CP8(r4b + so, Ub + r * R + c);
        }
        CP_COMMIT();
    }
    __syncthreads();    // sKs/sXs/pA/pads visible; cp.async still in flight

    // ---- attention -> R3 (fp16), overlapping the async tile loads ----
    for (int n = wid; n < R; n += 16) {
        const float k0 = sKs[n * 3], k1 = sKs[n * 3 + 1], k2 = sKs[n * 3 + 2];
        float s[4];
        float mx = -3.0e38f;
#pragma unroll
        for (int it = 0; it < 4; it++) {
            const int m = it * 32 + lane;
            float v = -3.0e38f;
            if (m < R) v = k0 * sKs[m * 3] + k1 * sKs[m * 3 + 1] + k2 * sKs[m * 3 + 2];
            s[it] = v;
            mx = fmaxf(mx, v);
        }
#pragma unroll
        for (int o = 16; o; o >>= 1) mx = fmaxf(mx, __shfl_xor_sync(0xffffffffu, mx, o));
        float sum = 0.f, e[4];
#pragma unroll
        for (int it = 0; it < 4; it++) {
            const int m = it * 32 + lane;
            e[it] = (m < R) ? __expf(s[it] - mx) : 0.f;
            sum += e[it];
        }
        sum = wsum(sum);
        const float inv = 1.f / sum;
#pragma unroll
        for (int it = 0; it < 4; it++) {
            const int m = it * 32 + lane;
            if (m < R) hR3[n * SH + m] = __float2half_rn(e[it] * inv);
        }
    }
    CP_WAIT0();
    __syncthreads();    // all async copies complete

    // ---- fused Z apply + down-edge (layers 1..3) ----
    if (apply) {
        float w0[4], w1[4], w2[4];
#pragma unroll
        for (int d = 0; d < 4; d++) {
            const int e = 4 * lane + d;
            w1[d] = (e < 78) ? dew[e] : 0.f;
            w0[d] = (e < 39) ? dew[39 + e] : 0.f;
            w2[d] = (e >= 39 && e < 116) ? dew[e - 39] : 0.f;
        }
        const float debv = deb[0];
        __half* Zg = g_Zh + (size_t)b * RR;
        for (int r = wid; r < R; r += 16) {
            float4 v = make_float4(0.f, 0.f, 0.f, 0.f);
            if (lane < 29) {
                const uint2 zu = *(const uint2*)(hR1 + r * SH + 4 * lane);
                const uint2 uu = *(const uint2*)(hR4 + r * SH + 4 * lane);
                const float2 z01 = __half22float2(*(const __half2*)&zu.x);
                const float2 z23 = __half22float2(*(const __half2*)&zu.y);
                const float2 u01 = __half22float2(*(const __half2*)&uu.x);
                const float2 u23 = __half22float2(*(const __half2*)&uu.y);
                const float sc = g_scale[r], sf = g_shift[r];
                v.x = z01.x + fmaxf(fmaf(u01.x, sc, sf), 0.f);
                v.y = z01.y + fmaxf(fmaf(u01.y, sc, sf), 0.f);
                v.z = z23.x + fmaxf(fmaf(u23.x, sc, sf), 0.f);
                v.w = z23.y + fmaxf(fmaf(u23.y, sc, sf), 0.f);
                uint2 ou;
                *(__half2*)&ou.x = __floats2half2_rn(v.x, v.y);
                *(__half2*)&ou.y = __floats2half2_rn(v.z, v.w);
                *(uint2*)(hR1 + r * SH + 4 * lane) = ou;     // fp16 tile for GEMMs
                *(uint2*)(Zg + r * R + 4 * lane) = ou;       // carried state
            }
            float f0 = 0.f, f1 = 0.f, f2 = 0.f;
            const float vv[4] = {v.x, v.y, v.z, v.w};
#pragma unroll
            for (int d = 0; d < 4; d++) {
                f1 = fmaf(vv[d], w1[d], f1);
                f0 = fmaf(vv[d], w0[d], f0);
                f2 = fmaf(vv[d], w2[d], f2);
            }
            f0 = wsum(f0); f1 = wsum(f1); f2 = wsum(f2);
            if (lane == 0) {
                f0 = fmaxf(f0 + debv, 0.f);
                f1 = fmaxf(f1 + debv, 0.f);
                f2 = fmaxf(f2 + debv, 0.f);
                float* dst = g_XZ + (size_t)b * FEAT + offE + r * 3;
                dst[0] = f0; dst[1] = f1; dst[2] = f2;
                pS[r] = f0 + f1 + f2;
                pQ[r] = f0 * f0 + f1 * f1 + f2 * f2;
            }
        }
        // node dp fold (pA visible since sync #1)
        if (wid == 15) {
            float s = 0.f, q = 0.f;
            for (int n = lane; n < R; n += 32) {
                const float f = pA[n];
                s += f; q = fmaf(f, f, q);
            }
            s = wsum(s); q = wsum(q);
            if (lane == 0) { g_dpS[dpN + b] = s; g_dpQ[dpN + b] = q; }
        }
        __syncthreads();    // updated R1 + pS/pQ visible
        if (wid == 0) {
            float s = 0.f, q = 0.f;
            for (int r = lane; r < R; r += 32) { s += pS[r]; q += pQ[r]; }
            s = wsum(s); q = wsum(q);
            if (lane == 0) { g_dpS[dpE + b] = s; g_dpQ[dpE + b] = q; }
        }
    }

    float acc[2][4][4];
#pragma unroll
    for (int mt = 0; mt < 2; mt++)
#pragma unroll
        for (int nt = 0; nt < 4; nt++)
#pragma unroll
            for (int i = 0; i < 4; i++) acc[mt][nt][i] = 0.f;

    // ---- GEMM1: Mid1 = Z @ aw2^T ----
    mm_loop(hR1, hR2, acc, wm, wn, aOff, bOff);
    __syncthreads();

    // ---- Mid1 + ab2 -> R2 ----
#pragma unroll
    for (int mt = 0; mt < 2; mt++)
#pragma unroll
        for (int h = 0; h < 2; h++) {
            const int row = wm * 32 + mt * 16 + g + 8 * h;
#pragma unroll
            for (int nt = 0; nt < 4; nt++) {
                const int col = wn * 32 + nt * 8 + 2 * tig;
                if (col < 120)
                    *(__half2*)(hR2 + row * SH + col) =
                        __floats2half2_rn(acc[mt][nt][2 * h] + sb1[col],
                                          acc[mt][nt][2 * h + 1] + sb1[col + 1]);
            }
        }
#pragma unroll
    for (int mt = 0; mt < 2; mt++)
#pragma unroll
        for (int nt = 0; nt < 4; nt++)
#pragma unroll
            for (int i = 0; i < 4; i++) acc[mt][nt][i] = 0.f;
    __syncthreads();

    // ---- GEMM3: S2 = Mid1 @ att^T ----
    mm_loop(hR2, hR3, acc, wm, wn, aOff, bOff);
    __syncthreads();

    // ---- ew -> R2 async; S2 -> R3 + node partials ----
    {
        const uint32_t r2b = sptr(hR2);
        for (int idx = tid; idx < 116 * 29; idx += LT) {
            const int r = idx / 29;
            const int c = (idx - r * 29) << 2;
            CP8(r2b + (uint32_t)(r * SH + c) * 2, ewh + r * R + c);
        }
        CP_COMMIT();
    }
#pragma unroll
    for (int mt = 0; mt < 2; mt++)
#pragma unroll
        for (int h = 0; h < 2; h++) {
            const int row = wm * 32 + mt * 16 + g + 8 * h;
            float a0 = 0.f, a1 = 0.f, a2 = 0.f;
#pragma unroll
            for (int nt = 0; nt < 4; nt++) {
                const int col = wn * 32 + nt * 8 + 2 * tig;
                const float v0 = acc[mt][nt][2 * h];
                const float v1 = acc[mt][nt][2 * h + 1];
                if (col < 120)
                    *(__half2*)(hR3 + row * SH + col) = __floats2half2_rn(v0, v1);
                if (row < R && col < R) {
                    a0 = fmaf(v0, sXs[col * 3 + 0], fmaf(v1, sXs[col * 3 + 3], a0));
                    a1 = fmaf(v0, sXs[col * 3 + 1], fmaf(v1, sXs[col * 3 + 4], a1));
                    a2 = fmaf(v0, sXs[col * 3 + 2], fmaf(v1, sXs[col * 3 + 5], a2));
                }
            }
            a0 += __shfl_xor_sync(0xffffffffu, a0, 1);
            a0 += __shfl_xor_sync(0xffffffffu, a0, 2);
            a1 += __shfl_xor_sync(0xffffffffu, a1, 1);
            a1 += __shfl_xor_sync(0xffffffffu, a1, 2);
            a2 += __shfl_xor_sync(0xffffffffu, a2, 1);
            a2 += __shfl_xor_sync(0xffffffffu, a2, 2);
            if (tig == 0) {
                pA[0 * 512 + wn * 128 + row] = a0;
                pA[1 * 512 + wn * 128 + row] = a1;
                pA[2 * 512 + wn * 128 + row] = a2;
            }
        }
#pragma unroll
    for (int mt = 0; mt < 2; mt++)
#pragma unroll
        for (int nt = 0; nt < 4; nt++)
#pragma unroll
            for (int i = 0; i < 4; i++) acc[mt][nt][i] = 0.f;
    CP_WAIT0();
    __syncthreads();

    // ---- GEMM2: Et = ew @ Z^T ----
    mm_loop(hR2, hR1, acc, wm, wn, aOff, bOff);
    __syncthreads();

    // ---- Et -> R1 ----
#pragma unroll
    for (int mt = 0; mt < 2; mt++)
#pragma unroll
        for (int h = 0; h < 2; h++) {
            const int row = wm * 32 + mt * 16 + g + 8 * h;
#pragma unroll
            for (int nt = 0; nt < 4; nt++) {
                const int col = wn * 32 + nt * 8 + 2 * tig;
                if (col < 120)
                    *(__half2*)(hR1 + row * SH + col) =
                        __floats2half2_rn(acc[mt][nt][2 * h], acc[mt][nt][2 * h + 1]);
            }
        }
#pragma unroll
    for (int mt = 0; mt < 2; mt++)
#pragma unroll
        for (int nt = 0; nt < 4; nt++)
#pragma unroll
            for (int i = 0; i < 4; i++) acc[mt][nt][i] = 0.f;
    __syncthreads();

    // ---- GEMM4: Z1 = S2 @ Et^T + eb ----
    mm_loop(hR3, hR1, acc, wm, wn, aOff, bOff);

    // ---- epilogue: Z1 (fp16) + edge stats (fp32, pre-rounding) ----
    __half* Cb = g_Z1h + (size_t)b * RR;
#pragma unroll
    for (int mt = 0; mt < 2; mt++) {
#pragma unroll
        for (int h = 0; h < 2; h++) {
            const int row = wm * 32 + mt * 16 + g + 8 * h;
            float s = 0.f, q = 0.f;
#pragma unroll
            for (int nt = 0; nt < 4; nt++) {
                const int col = wn * 32 + nt * 8 + 2 * tig;
                if (col < R) {
                    const float v0 = acc[mt][nt][2 * h] + sb2[col];
                    const float v1 = acc[mt][nt][2 * h + 1] + sb2[col + 1];
                    if (row < R)
                        *(__half2*)(Cb + (size_t)row * R + col) =
                            __floats2half2_rn(v0, v1);
                    s += v0 + v1;
                    q += v0 * v0 + v1 * v1;
                }
            }
            s += __shfl_xor_sync(0xffffffffu, s, 1);
            s += __shfl_xor_sync(0xffffffffu, s, 2);
            q += __shfl_xor_sync(0xffffffffu, q, 1);
            q += __shfl_xor_sync(0xffffffffu, q, 2);
            if (tig == 0) { pS[wn * 128 + row] = s; pQ[wn * 128 + row] = q; }
        }
    }
    __syncthreads();
    if (tid < R) {
        const float s = pS[tid] + pS[128 + tid] + pS[256 + tid] + pS[384 + tid];
        const float q = pQ[tid] + pQ[128 + tid] + pQ[256 + tid] + pQ[384 + tid];
        g_ps[tid * NB + b] = s;
        g_pq[tid * NB + b] = q;
    }
    // ---- node path finish: X1 = (S2 @ X) @ nw^T + nb, node stats ----
    if (tid < R) {
        const int n = tid;
        const float a0 = pA[0 * 512 + n] + pA[0 * 512 + 128 + n] +
                         pA[0 * 512 + 256 + n] + pA[0 * 512 + 384 + n];
        const float a1 = pA[1 * 512 + n] + pA[1 * 512 + 128 + n] +
                         pA[1 * 512 + 256 + n] + pA[1 * 512 + 384 + n];
        const float a2 = pA[2 * 512 + n] + pA[2 * 512 + 128 + n] +
                         pA[2 * 512 + 256 + n] + pA[2 * 512 + 384 + n];
        float ps = 0.f, pq = 0.f;
        float* dst = g_X1 + (size_t)b * (R * 3) + n * 3;
#pragma unroll
        for (int o = 0; o < 3; o++) {
            const float v = fmaf(nw[o * 3 + 0], a0,
                            fmaf(nw[o * 3 + 1], a1,
                            fmaf(nw[o * 3 + 2], a2, nb_[o])));
            dst[o] = v;
            ps += v;
            pq = fmaf(v, v, pq);
        }
        g_psN[n * NB + b] = ps;
        g_pqN[n * NB + b] = pq;
    }
}

// ----------------------------------------------------------------------------
// Both BN channel reductions fused per channel. grid = R, block = 512.
// ----------------------------------------------------------------------------
__global__ void __launch_bounds__(512)
k_reduce_both(const float* __restrict__ geg, const float* __restrict__ geb,
              const float* __restrict__ gng, const float* __restrict__ gnb) {
    const int n = blockIdx.x;
    const int half = threadIdx.x >> 8;        // 0 = edge, 1 = node
    const int t = threadIdx.x & 255;
    const float* PS = half ? g_psN : g_ps;
    const float* PQ = half ? g_pqN : g_pq;
    float s = 0.f, q = 0.f;
#pragma unroll
    for (int it = 0; it < 2; it++) {
        const int b2 = it * 256 + t;
        const float2 vs = *(const float2*)(PS + n * NB + 2 * b2);
        const float2 vq = *(const float2*)(PQ + n * NB + 2 * b2);
        s += vs.x + vs.y;
        q += vq.x + vq.y;
    }
    __shared__ float shs[2][8], shq[2][8];
    s = wsum(s); q = wsum(q);
    const int w = t >> 5, lane = t & 31;
    if (lane == 0) { shs[half][w] = s; shq[half][w] = q; }
    __syncthreads();
    if (t == 0) {
        s = shs[half][0] + shs[half][1] + shs[half][2] + shs[half][3] +
            shs[half][4] + shs[half][5] + shs[half][6] + shs[half][7];
        q = shq[half][0] + shq[half][1] + shq[half][2] + shq[half][3] +
            shq[half][4] + shq[half][5] + shq[half][6] + shq[half][7];
        const float invcnt = half ? (1.f / (float)(3 * NB)) : (1.f / (float)(NB * R));
        const float mean = s * invcnt;
        const float var = q * invcnt - mean * mean;
        const float rstd = rsqrtf(var + EPS);
        const float gg = half ? gng[n] : geg[n];
        const float bb = half ? gnb[n] : geb[n];
        const float sc = rstd * gg;
        if (half) { g_scaleN[n] = sc; g_shiftN[n] = bb - mean * sc; }
        else      { g_scale[n] = sc;  g_shift[n] = bb - mean * sc; }
    }
}

// ----------------------------------------------------------------------------
// Standalone apply+down: only l=0 (pass-through + weight cvt tail) and l=4.
// grid = 29696 + 928 (+CVTB for l=0), block = 128.
// ----------------------------------------------------------------------------
__global__ void k_apply_down(const float* __restrict__ dew, const float* __restrict__ deb,
                             const float* __restrict__ dnw, const float* __restrict__ dnb,
                             const float* __restrict__ srcZ, const float* __restrict__ srcX,
                             const float* __restrict__ aw2f, const float* __restrict__ ewf,
                             int offE, int offN, int dpE, int dpN, int apply) {
    __shared__ float sh[8];
    if (blockIdx.x >= 30624) {
        // ---------------- weight conversion (layer 0 launch only) ----------------
        const int i = (blockIdx.x - 30624) * 256 + threadIdx.x * 2;
        const int N = LAYERS * RR;
        if (i < N) {
            g_wh[i] = __float2half_rn(aw2f[i]);
            if (i + 1 < N) g_wh[i + 1] = __float2half_rn(aw2f[i + 1]);
            else if (i + 1 < 2 * N) g_wh[i + 1] = __float2half_rn(ewf[i + 1 - N]);
        } else if (i < 2 * N) {
            g_wh[i] = __float2half_rn(ewf[i - N]);
            if (i + 1 < 2 * N) g_wh[i + 1] = __float2half_rn(ewf[i + 1 - N]);
        }
        return;
    }
    if (blockIdx.x < 29696) {
        // ---------------- edge ----------------
        const int wrp = threadIdx.x >> 5, lane = threadIdx.x & 31;
        const int rowid = blockIdx.x * 4 + wrp;
        const int b = rowid / R, n = rowid - b * R;
        float w0[4], w1[4], w2[4];
#pragma unroll
        for (int d = 0; d < 4; d++) {
            const int e = 4 * lane + d;
            w1[d] = (e < 78) ? dew[e] : 0.f;
            w0[d] = (e < 39) ? dew[39 + e] : 0.f;
            w2[d] = (e >= 39 && e < 116) ? dew[e - 39] : 0.f;
        }
        float4 v = make_float4(0.f, 0.f, 0.f, 0.f);
        __half2* zrow = (__half2*)(g_Zh + (size_t)rowid * R);
        if (lane < 29) {
            if (apply) {
                const uint2 zu = *(const uint2*)(zrow + 2 * lane);
                const uint2 uu = *(const uint2*)((const __half2*)(g_Z1h + (size_t)rowid * R) + 2 * lane);
                const float2 z01 = __half22float2(*(const __half2*)&zu.x);
                const float2 z23 = __half22float2(*(const __half2*)&zu.y);
                const float2 u01 = __half22float2(*(const __half2*)&uu.x);
                const float2 u23 = __half22float2(*(const __half2*)&uu.y);
                const float sc = g_scale[n], sf = g_shift[n];
                v.x = z01.x + fmaxf(fmaf(u01.x, sc, sf), 0.f);
                v.y = z01.y + fmaxf(fmaf(u01.y, sc, sf), 0.f);
                v.z = z23.x + fmaxf(fmaf(u23.x, sc, sf), 0.f);
                v.w = z23.y + fmaxf(fmaf(u23.y, sc, sf), 0.f);
                uint2 ou;
                *(__half2*)&ou.x = __floats2half2_rn(v.x, v.y);
                *(__half2*)&ou.y = __floats2half2_rn(v.z, v.w);
                *(uint2*)(zrow + 2 * lane) = ou;
            } else {
                v = *(const float4*)(srcZ + (size_t)rowid * R + 4 * lane);
                uint2 ou;
                *(__half2*)&ou.x = __floats2half2_rn(v.x, v.y);
                *(__half2*)&ou.y = __floats2half2_rn(v.z, v.w);
                *(uint2*)(zrow + 2 * lane) = ou;
            }
        }
        float f0 = 0.f, f1 = 0.f, f2 = 0.f;
        const float vv[4] = {v.x, v.y, v.z, v.w};
#pragma unroll
        for (int d = 0; d < 4; d++) {
            f1 = fmaf(vv[d], w1[d], f1);
            f0 = fmaf(vv[d], w0[d], f0);
            f2 = fmaf(vv[d], w2[d], f2);
        }
        f0 = wsum(f0); f1 = wsum(f1); f2 = wsum(f2);
        float s = 0.f, q = 0.f;
        if (lane == 0) {
            const float bb = deb[0];
            f0 = fmaxf(f0 + bb, 0.f);
            f1 = fmaxf(f1 + bb, 0.f);
            f2 = fmaxf(f2 + bb, 0.f);
            float* dst = g_XZ + (size_t)b * FEAT + offE + n * 3;
            dst[0] = f0; dst[1] = f1; dst[2] = f2;
            s = f0 + f1 + f2;
            q = f0 * f0 + f1 * f1 + f2 * f2;
            sh[wrp] = s; sh[4 + wrp] = q;
        }
        __syncthreads();
        if (threadIdx.x == 0) {
            g_dpS[dpE + blockIdx.x] = sh[0] + sh[1] + sh[2] + sh[3];
            g_dpQ[dpE + blockIdx.x] = sh[4] + sh[5] + sh[6] + sh[7];
        }
    } else {
        // ---------------- node ----------------
        const int bid = blockIdx.x - 29696;
        const int idx = bid * 128 + threadIdx.x;
        float* xp = g_X + (size_t)idx * 3;
        float x0, x1, x2;
        if (apply) {
            x0 = xp[0]; x1 = xp[1]; x2 = xp[2];
            const int n = idx % R;
            const float sc = g_scaleN[n], sf = g_shiftN[n];
            const float* up = g_X1 + (size_t)idx * 3;
            x0 += fmaxf(fmaf(up[0], sc, sf), 0.f);
            x1 += fmaxf(fmaf(up[1], sc, sf), 0.f);
            x2 += fmaxf(fmaf(up[2], sc, sf), 0.f);
            xp[0] = x0; xp[1] = x1; xp[2] = x2;
        } else {
            const float* sp = srcX + (size_t)idx * 3;
            x0 = sp[0]; x1 = sp[1]; x2 = sp[2];
            xp[0] = x0; xp[1] = x1; xp[2] = x2;
        }
        const float f = fmaxf(fmaf(x0, dnw[0], fmaf(x1, dnw[1], fmaf(x2, dnw[2], dnb[0]))), 0.f);
        const int b = idx / R, r = idx - (idx / R) * R;
        g_XZ[(size_t)b * FEAT + offN + r] = f;
        const float s = wsum(f);
        const float q = wsum(f * f);
        const int wr = threadIdx.x >> 5, lane = threadIdx.x & 31;
        if (lane == 0) { sh[wr] = s; sh[4 + wr] = q; }
        __syncthreads();
        if (threadIdx.x == 0) {
            g_dpS[dpN + bid] = sh[0] + sh[1] + sh[2] + sh[3];
            g_dpQ[dpN + bid] = sh[4] + sh[5] + sh[6] + sh[7];
        }
    }
}

// ----------------------------------------------------------------------------
// All 10 down-sample reductions at once. grid = 10, block = 1024.
// sgm 0..4 node l, 5..9 edge l-5.
// ----------------------------------------------------------------------------
__global__ void k_dreduce_all(const float* __restrict__ dng, const float* __restrict__ dnbe,
                              const float* __restrict__ deg, const float* __restrict__ debe) {
    const int sgm = blockIdx.x;
    const bool node = sgm < 5;
    const int l = node ? sgm : sgm - 5;
    int base, cnt;
    if (node) {
        if (l == 0)      { base = DP_N0; cnt = 928; }
        else if (l == 4) { base = DP_N4; cnt = 928; }
        else             { base = DP_NF + (l - 1) * 1024; cnt = 1024; }
    } else {
        if (l == 0)      { base = DP_E0; cnt = 29696; }
        else if (l == 4) { base = DP_E4; cnt = 29696; }
        else             { base = DP_EF + (l - 1) * 1024; cnt = 1024; }
    }
    const float invcnt = node ? (1.f / (float)(NB * R)) : (1.f / (float)(NB * R * 3));
    float s = 0.f, q = 0.f;
    for (int i = threadIdx.x; i < cnt; i += 1024) {
        s += g_dpS[base + i];
        q += g_dpQ[base + i];
    }
    __shared__ float shs[32], shq[32];
    s = wsum(s); q = wsum(q);
    const int w = threadIdx.x >> 5, lane = threadIdx.x & 31;
    if (lane == 0) { shs[w] = s; shq[w] = q; }
    __syncthreads();
    if (w == 0) {
        s = shs[lane]; q = shq[lane];
        s = wsum(s); q = wsum(q);
        if (lane == 0) {
            const float mean = s * invcnt;
            const float var = q * invcnt - mean * mean;
            const float rstd = rsqrtf(var + EPS);
            const float gg = node ? dng[l] : deg[l];
            const float bb = node ? dnbe[l] : debe[l];
            const float sc = rstd * gg;
            g_dssArr[2 * sgm]     = sc;
            g_dssArr[2 * sgm + 1] = bb - mean * sc;
        }
    }
}

// ----------------------------------------------------------------------------
// Classifier GEMM (fp16) + fused out-projection partials.
// ----------------------------------------------------------------------------
#define CSTR 24

__global__ void __launch_bounds__(256)
k_cls(const float* __restrict__ A, const float* __restrict__ Bm,
      const float* __restrict__ bias, const float* __restrict__ cw2)
{
    __shared__ __half sA[2][128 * CSTR];
    __shared__ __half sB[2][64 * CSTR];
    __shared__ float sbc[64];
    __shared__ float sc2[2][64];
    __shared__ float pOut[128][4];
    const int tid = threadIdx.x;
    const int wid = tid >> 5, lane = tid & 31;
    const int wm = wid >> 1, wn = wid & 1;
    const int g = lane >> 2, tig = lane & 3;
    const int row0 = blockIdx.y * 128, col0 = blockIdx.x * 64;

    if (tid < 64) {
        sbc[tid] = bias[col0 + tid];
        sc2[0][tid] = cw2[col0 + tid];
        sc2[1][tid] = cw2[HID + col0 + tid];
    }

    float4 pa0, pa1, pb;
    float fsc, fsh;
    const int ar0 = tid >> 2, ac0 = (tid & 3) << 2;
    const int ar1 = (tid + 256) >> 2, ac1 = ac0;
    const int br = tid >> 2, bc = (tid & 3) << 2;

    auto fetch = [&](int k0) {
        const int k = k0 + ac0;
        const int sgm = (k < 580) ? (k / 116) : (5 + (k - 580) / 348);
        fsc = g_dssArr[2 * sgm];
        fsh = g_dssArr[2 * sgm + 1];
        pa0 = *(const float4*)(A + (size_t)(row0 + ar0) * FEAT + k0 + ac0);
        pa1 = *(const float4*)(A + (size_t)(row0 + ar1) * FEAT + k0 + ac1);
        pb  = *(const float4*)(Bm + (size_t)(col0 + br) * FEAT + k0 + bc);
    };
    auto store = [&](int buf) {
        __half2* d0 = (__half2*)&sA[buf][ar0 * CSTR + ac0];
        d0[0] = __floats2half2_rn(fmaf(pa0.x, fsc, fsh), fmaf(pa0.y, fsc, fsh));
        d0[1] = __floats2half2_rn(fmaf(pa0.z, fsc, fsh), fmaf(pa0.w, fsc, fsh));
        __half2* d1 = (__half2*)&sA[buf][ar1 * CSTR + ac1];
        d1[0] = __floats2half2_rn(fmaf(pa1.x, fsc, fsh), fmaf(pa1.y, fsc, fsh));
        d1[1] = __floats2half2_rn(fmaf(pa1.z, fsc, fsh), fmaf(pa1.w, fsc, fsh));
        __half2* d2 = (__half2*)&sB[buf][br * CSTR + bc];
        d2[0] = __floats2half2_rn(pb.x, pb.y);
        d2[1] = __floats2half2_rn(pb.z, pb.w);
    };

    float acc[2][4][4];
#pragma unroll
    for (int mt = 0; mt < 2; mt++)
#pragma unroll
        for (int nt = 0; nt < 4; nt++)
#pragma unroll
            for (int i = 0; i < 4; i++) acc[mt][nt][i] = 0.f;

    const int NS = FEAT / 16;   // 145
    fetch(0);
    store(0);
    __syncthreads();
    int buf = 0;
    for (int ks = 0; ks < NS; ks++) {
        if (ks + 1 < NS) fetch((ks + 1) * 16);
        uint32_t af[2][4], bf[4][2];
#pragma unroll
        for (int mt = 0; mt < 2; mt++) {
            const __half* p0 = &sA[buf][(wm * 32 + mt * 16 + g) * CSTR + 2 * tig];
            af[mt][0] = *(const uint32_t*)(p0);
            af[mt][1] = *(const uint32_t*)(p0 + 8 * CSTR);
            af[mt][2] = *(const uint32_t*)(p0 + 8);
            af[mt][3] = *(const uint32_t*)(p0 + 8 * CSTR + 8);
        }
#pragma unroll
        for (int nt = 0; nt < 4; nt++) {
            const __half* q0 = &sB[buf][(wn * 32 + nt * 8 + g) * CSTR + 2 * tig];
            bf[nt][0] = *(const uint32_t*)(q0);
            bf[nt][1] = *(const uint32_t*)(q0 + 8);
        }
#pragma unroll
        for (int mt = 0; mt < 2; mt++)
#pragma unroll
            for (int nt = 0; nt < 4; nt++)
                mma16(acc[mt][nt], af[mt], bf[nt]);
        if (ks + 1 < NS) store(buf ^ 1);
        __syncthreads();
        buf ^= 1;
    }

    // fused epilogue: relu + dot with cw2 slice -> per-row partials
#pragma unroll
    for (int mt = 0; mt < 2; mt++)
#pragma unroll
        for (int h = 0; h < 2; h++) {
            const int rl = wm * 32 + mt * 16 + g + 8 * h;
            float p0 = 0.f, p1 = 0.f;
#pragma unroll
            for (int nt = 0; nt < 4; nt++) {
                const int col = wn * 32 + nt * 8 + 2 * tig;
                const float v0 = fmaxf(acc[mt][nt][2 * h] + sbc[col], 0.f);
                const float v1 = fmaxf(acc[mt][nt][2 * h + 1] + sbc[col + 1], 0.f);
                p0 = fmaf(v0, sc2[0][col], fmaf(v1, sc2[0][col + 1], p0));
                p1 = fmaf(v0, sc2[1][col], fmaf(v1, sc2[1][col + 1], p1));
            }
            p0 += __shfl_xor_sync(0xffffffffu, p0, 1);
            p0 += __shfl_xor_sync(0xffffffffu, p0, 2);
            p1 += __shfl_xor_sync(0xffffffffu, p1, 1);
            p1 += __shfl_xor_sync(0xffffffffu, p1, 2);
            if (tig == 0) {
                pOut[rl][wn * 2 + 0] = p0;
                pOut[rl][wn * 2 + 1] = p1;
            }
        }
    __syncthreads();
    if (tid < 128) {
        g_Hp[(size_t)(row0 + tid) * 32 + blockIdx.x * 2 + 0] = pOut[tid][0] + pOut[tid][2];
        g_Hp[(size_t)(row0 + tid) * 32 + blockIdx.x * 2 + 1] = pOut[tid][1] + pOut[tid][3];
    }
}

// Final fold: out[b][c] = sum_k g_Hp[b][2k+c] + cb2[c]. grid = 4, block = 256.
__global__ void k_out2(const float* __restrict__ cb2, float* __restrict__ out) {
    const int b = blockIdx.x * 256 + threadIdx.x;
    const float* p = g_Hp + (size_t)b * 32;
    float a0 = 0.f, a1 = 0.f;
#pragma unroll
    for (int k = 0; k < 16; k++) {
        a0 += p[2 * k];
        a1 += p[2 * k + 1];
    }
    out[b * 2 + 0] = a0 + cb2[0];
    out[b * 2 + 1] = a1 + cb2[1];
}

// ----------------------------------------------------------------------------
// Host orchestration (graph-capturable: kernel launches only)
// ----------------------------------------------------------------------------
extern "C" void kernel_launch(void* const* d_in, const int* in_sizes, int n_in,
                              void* d_out, int out_size) {
    const float* X_in  = (const float*)d_in[0];
    const float* Z_in  = (const float*)d_in[1];
    const float* aw1   = (const float*)d_in[2];
    const float* ab1   = (const float*)d_in[3];
    const float* aw2   = (const float*)d_in[4];
    const float* ab2   = (const float*)d_in[5];
    const float* nw    = (const float*)d_in[6];
    const float* nb    = (const float*)d_in[7];
    const float* ew    = (const float*)d_in[8];
    const float* eb    = (const float*)d_in[9];
    const float* gn_g  = (const float*)d_in[10];
    const float* gn_b  = (const float*)d_in[11];
    const float* ge_g  = (const float*)d_in[12];
    const float* ge_b  = (const float*)d_in[13];
    const float* dn_w  = (const float*)d_in[14];
    const float* dn_b  = (const float*)d_in[15];
    const float* dn_g  = (const float*)d_in[16];
    const float* dn_be = (const float*)d_in[17];
    const float* de_w  = (const float*)d_in[18];
    const float* de_b  = (const float*)d_in[19];
    const float* de_g  = (const float*)d_in[20];
    const float* de_be = (const float*)d_in[21];
    const float* cw1   = (const float*)d_in[22];
    const float* cb1   = (const float*)d_in[23];
    const float* cw2   = (const float*)d_in[24];
    const float* cb2   = (const float*)d_in[25];
    float* out = (float*)d_out;

    cudaFuncSetAttribute(k_layer, cudaFuncAttributeMaxDynamicSharedMemorySize, SM_TOTB);

    float* pXZ;
    __half* pWh;
    cudaGetSymbolAddress((void**)&pXZ, g_XZ);
    cudaGetSymbolAddress((void**)&pWh, g_wh);

    // layer-0 down-sample + input pass-through + fused weight fp16 conversion
    k_apply_down<<<29696 + 928 + CVTB, 128>>>(de_w, de_b, dn_w, dn_b,
                                              Z_in, X_in, aw2, ew,
                                              580, 0, DP_E0, DP_N0, 0);

    for (int i = 0; i < LAYERS; i++) {
        const int ap = (i > 0) ? 1 : 0;
        const int dpE = ap ? (DP_EF + (i - 1) * 1024) : 0;
        const int dpN = ap ? (DP_NF + (i - 1) * 1024) : 0;
        k_layer<<<NB, LT, SM_TOTB>>>(pWh + (size_t)i * RR, ab2 + i * R,
                                     aw1 + 9 * i, ab1 + 3 * i,
                                     pWh + (size_t)(LAYERS + i) * RR, eb + i * R,
                                     nw + 9 * i, nb + 3 * i,
                                     de_w + 78 * i, de_b + i,
                                     dn_w + 3 * i, dn_b + i,
                                     580 + i * 348, i * R, dpE, dpN, ap);
        k_reduce_both<<<R, 512>>>(ge_g + i * R, ge_b + i * R,
                                  gn_g + i * R, gn_b + i * R);
    }

    // final apply + down-sample for l = 4
    k_apply_down<<<29696 + 928, 128>>>(de_w + 78 * 4, de_b + 4,
                                       dn_w + 3 * 4, dn_b + 4,
                                       nullptr, nullptr, nullptr, nullptr,
                                       580 + 4 * 348, 4 * R, DP_E4, DP_N4, 1);

    k_dreduce_all<<<10, 1024>>>(dn_g, dn_be, de_g, de_be);
    k_cls<<<dim3(HID / 64, NB / 128), 256>>>(pXZ, cw1, cb1, cw2);
    k_out2<<<NB / 256, 256>>>(cb2, out);
}

// round 17
// speedup vs baseline: 1.7889x; 1.0149x over previous
#include <cuda_runtime.h>
#include <cuda_fp16.h>
#include <cstddef>
#include <cstdint>

// ----------------------------------------------------------------------------
// Problem constants
// ----------------------------------------------------------------------------
#define NB 1024            // batch
#define R 116              // ROIs
#define RR (R * R)         // 13456
#define LAYERS 4
#define FEAT 2320          // R*4*(L+1)
#define HID 1024
#define EPS 1e-5f

#define SH 136             // smem tile row stride (halves) — LDSM conflict-free
#define REGH (128 * SH)    // halves per region (17408)

// down-sample partial slot layout
#define DP_E0 0            // edge l=0: 29696 slots
#define DP_E4 29696        // edge l=4: 29696 slots
#define DP_EF 59392        // edge l=1..3: 1024 each
#define DP_N0 62464        // node l=0: 928
#define DP_N4 63392        // node l=4: 928
#define DP_NF 64320        // node l=1..3: 1024 each
#define DPTOT 67392

// weight-conversion tail blocks: 128 threads x 2 elems = 256/block
#define CVTB ((2 * LAYERS * RR + 255) / 256)

// ----------------------------------------------------------------------------
// Device scratch (static allocation only)
// ----------------------------------------------------------------------------
__device__ __align__(16) __half g_Zh [(size_t)NB * RR];   // carried Z (fp16)
__device__ __align__(16) __half g_Z1h[(size_t)NB * RR];
__device__ __align__(16) __half g_wh [(size_t)2 * LAYERS * RR]; // aw2 | ew (fp16)
__device__ __align__(16) float  g_X  [NB * R * 3];
__device__ __align__(16) float  g_X1 [NB * R * 3];
__device__ __align__(16) float  g_XZ [(size_t)NB * FEAT];
__device__ __align__(16) float  g_Hp [(size_t)NB * 32];   // cls partial dots
__device__ float g_ps [R * NB];     // edge BN partials
__device__ float g_pq [R * NB];
__device__ float g_psN[R * NB];     // node BN partials
__device__ float g_pqN[R * NB];
__device__ float g_scale [R],  g_shift [R];   // edge BN affine
__device__ float g_scaleN[R],  g_shiftN[R];   // node BN affine
__device__ float g_dpS[DPTOT], g_dpQ[DPTOT];  // down-sample partials
__device__ float g_dssArr[20];                // 10 segments x (scale, shift)

__device__ __forceinline__ float wsum(float v) {
#pragma unroll
    for (int o = 16; o; o >>= 1) v += __shfl_xor_sync(0xffffffffu, v, o);
    return v;
}

__device__ __forceinline__ uint32_t sptr(const void* p) {
    return (uint32_t)__cvta_generic_to_shared(p);
}

// cp.async 8-byte copy (sm_80 baseline; compiles at compute_103)
#define CP8(saddr, gptr) \
    asm volatile("cp.async.ca.shared.global [%0], [%1], 8;" \
                 :: "r"(saddr), "l"(gptr))
#define CP_COMMIT() asm volatile("cp.async.commit_group;")
#define CP_WAIT0()  asm volatile("cp.async.wait_group 0;")

// ldmatrix x4: loads 4 8x8 b16 tiles.
#define LDSM4(r0, r1, r2, r3, addr) \
    asm volatile("ldmatrix.sync.aligned.m8n8.x4.shared.b16 {%0,%1,%2,%3}, [%4];" \
                 : "=r"(r0), "=r"(r1), "=r"(r2), "=r"(r3) : "r"(addr))

// mma.sync m16n8k16 fp16 inputs, fp32 accumulate
__device__ __forceinline__ void mma16(float* d, const uint32_t* a, const uint32_t* b) {
    asm volatile(
        "mma.sync.aligned.m16n8k16.row.col.f32.f16.f16.f32 "
        "{%0,%1,%2,%3},{%4,%5,%6,%7},{%8,%9},{%0,%1,%2,%3};"
        : "+f"(d[0]), "+f"(d[1]), "+f"(d[2]), "+f"(d[3])
        : "r"(a[0]), "r"(a[1]), "r"(a[2]), "r"(a[3]), "r"(b[0]), "r"(b[1]));
}

// 128x128x128 NT GEMM over fp16 smem tiles (stride SH halves), 16 warps,
// warp tile 32x32, 8 k-steps of K=16. 4 LDSM.x4 + 8 MMA per k-step.
__device__ __forceinline__ void mm_loop(const __half* __restrict__ sA,
                                        const __half* __restrict__ sB,
                                        float (&acc)[2][4][4],
                                        int wm, int wn,
                                        uint32_t aOff, uint32_t bOff) {
    const uint32_t a0b = sptr(sA) + (uint32_t)(wm * 32 * SH * 2) + aOff;
    const uint32_t a1b = a0b + 16 * SH * 2;
    const uint32_t b0b = sptr(sB) + (uint32_t)(wn * 32 * SH * 2) + bOff;
    const uint32_t b1b = b0b + 16 * SH * 2;
#pragma unroll
    for (int ks = 0; ks < 8; ks++) {
        const uint32_t off = ks * 32;       // 16 halves = 32 bytes per k-step
        uint32_t af[2][4], bf[4][2];
        LDSM4(af[0][0], af[0][1], af[0][2], af[0][3], a0b + off);
        LDSM4(af[1][0], af[1][1], af[1][2], af[1][3], a1b + off);
        LDSM4(bf[0][0], bf[0][1], bf[1][0], bf[1][1], b0b + off);
        LDSM4(bf[2][0], bf[2][1], bf[3][0], bf[3][1], b1b + off);
#pragma unroll
        for (int mt = 0; mt < 2; mt++)
#pragma unroll
            for (int nt = 0; nt < 4; nt++)
                mma16(acc[mt][nt], af[mt], bf[nt]);
    }
}

// ----------------------------------------------------------------------------
// Mega layer kernel (fp16 tiles): one CTA per batch, 512 threads (16 warps).
// 5 smem regions, buffer rotation (every store targets a dead region):
//   R1 = Z (apply-updated)     R2 = aw2 -> S2
//   R3 = att -> Et             R4 = Z1h -> Mid1      R5 = ew (preloaded)
// GEMM1: R1xR2 -> R4 ; GEMM3: R4xR3 -> R2 ; GEMM2: R5xR1 -> R3 ;
// GEMM4: R2xR3 -> gmem.
// ----------------------------------------------------------------------------
#define NREG 5
#define HBYTES (NREG * REGH * 2)   // 174080
#define EXT_B1 0
#define EXT_B2 128
#define EXT_KS 256                 // 352
#define EXT_XS 608                 // 352
#define EXT_PS 960                 // 512
#define EXT_PQ 1472                // 512
#define EXT_PA 1984                // 1536
#define EXT_TOT 3520
#define SM_TOTB (HBYTES + EXT_TOT * 4)   // 188160

#define LT 512

__global__ void __launch_bounds__(LT, 1)
k_layer(const __half* __restrict__ aw2h, const float* __restrict__ ab2,
        const float* __restrict__ aw1, const float* __restrict__ ab1,
        const __half* __restrict__ ewh,  const float* __restrict__ eb,
        const float* __restrict__ nw,  const float* __restrict__ nb_,
        const float* __restrict__ dew, const float* __restrict__ deb,
        const float* __restrict__ dnw, const float* __restrict__ dnb,
        int offE, int offN, int dpE, int dpN, int apply)
{
    extern __shared__ __align__(16) char smraw[];
    __half* hR1 = (__half*)smraw;            // Z
    __half* hR2 = hR1 + REGH;                // aw2 -> S2
    __half* hR3 = hR2 + REGH;                // att -> Et
    __half* hR4 = hR3 + REGH;                // Z1h -> Mid1
    __half* hR5 = hR4 + REGH;                // ew
    float* fext = (float*)(smraw + HBYTES);
    float* sb1 = fext + EXT_B1;
    float* sb2 = fext + EXT_B2;
    float* sKs = fext + EXT_KS;
    float* sXs = fext + EXT_XS;
    float* pS  = fext + EXT_PS;
    float* pQ  = fext + EXT_PQ;
    float* pA  = fext + EXT_PA;

    const int tid = threadIdx.x;
    const int b = blockIdx.x;
    const int wid = tid >> 5, lane = tid & 31;
    const int wm = wid >> 2, wn = wid & 3;
    const int g = lane >> 2, tig = lane & 3;

    // ldmatrix per-lane byte offsets
    const uint32_t aOff = (uint32_t)((lane & 15) * SH * 2 + 16 * (lane >> 4));
    const uint32_t bOff = (uint32_t)(((lane & 7) + 8 * (lane >> 4)) * SH * 2 +
                                     16 * ((lane >> 3) & 1));

    // ---- phase 0: biases, X update/Ks, pads; async Z/aw2/ew/Z1 loads ----
    if (tid < 128) {
        sb1[tid] = (tid < R) ? ab2[tid] : 0.f;
        sb2[tid] = (tid < R) ? eb[tid] : 0.f;
    }
    if (tid < R) {
        float* xp = g_X + (size_t)b * (R * 3) + tid * 3;
        float y0, y1, y2;
        if (apply) {
            const float scn = g_scaleN[tid], sfn = g_shiftN[tid];
            const float* up = g_X1 + (size_t)b * (R * 3) + tid * 3;
            y0 = xp[0] + fmaxf(fmaf(up[0], scn, sfn), 0.f);
            y1 = xp[1] + fmaxf(fmaf(up[1], scn, sfn), 0.f);
            y2 = xp[2] + fmaxf(fmaf(up[2], scn, sfn), 0.f);
            xp[0] = y0; xp[1] = y1; xp[2] = y2;
            const float f = fmaxf(fmaf(y0, dnw[0],
                             fmaf(y1, dnw[1], fmaf(y2, dnw[2], dnb[0]))), 0.f);
            g_XZ[(size_t)b * FEAT + offN + tid] = f;
            pA[tid] = f;                       // node feature scratch
        } else {
            y0 = xp[0]; y1 = xp[1]; y2 = xp[2];
        }
        sXs[tid * 3 + 0] = y0; sXs[tid * 3 + 1] = y1; sXs[tid * 3 + 2] = y2;
#pragma unroll
        for (int o = 0; o < 3; o++)
            sKs[tid * 3 + o] = fmaf(aw1[o * 3 + 0], y0,
                                fmaf(aw1[o * 3 + 1], y1,
                                fmaf(aw1[o * 3 + 2], y2, ab1[o])));
    }
    // zero pad rows 116..127, cols 0..127: 12 rows x 16 uint4, all NREG regions
    {
        const uint4 z4u = make_uint4(0, 0, 0, 0);
        for (int idx = tid; idx < NREG * 192; idx += LT) {
            const int t = idx / 192, i2 = idx - t * 192;
            const int r = 116 + i2 / 16, c8 = (i2 & 15) * 8;
            *(uint4*)(hR1 + (size_t)t * REGH + r * SH + c8) = z4u;
        }
    }
    // zero pad cols 116..127 rows 0..115: 3 uint2 per row, all NREG regions
    {
        const uint2 z2u = make_uint2(0, 0);
        for (int idx = tid; idx < NREG * 116; idx += LT) {
            const int t = idx / 116, r = idx - t * 116;
            uint2* p = (uint2*)(hR1 + (size_t)t * REGH + r * SH + 116);
            p[0] = z2u; p[1] = z2u; p[2] = z2u;
        }
    }
    // Zh -> R1, aw2 -> R2, ew -> R5 (+ Z1h -> R4 when applying), via cp.async
    {
        const __half* Zb = g_Zh + (size_t)b * RR;
        const __half* Ub = g_Z1h + (size_t)b * RR;
        const uint32_t r1b = sptr(hR1), r2b = sptr(hR2);
        const uint32_t r4b = sptr(hR4), r5b = sptr(hR5);
        for (int idx = tid; idx < 116 * 29; idx += LT) {
            const int r = idx / 29;
            const int c = (idx - r * 29) << 2;
            const uint32_t so = (uint32_t)(r * SH + c) * 2;
            CP8(r1b + so, Zb + r * R + c);
            CP8(r2b + so, aw2h + r * R + c);
            CP8(r5b + so, ewh + r * R + c);
            if (apply) CP8(r4b + so, Ub + r * R + c);
        }
        CP_COMMIT();
    }
    __syncthreads();    // sKs/sXs/pA/pads visible; cp.async still in flight

    // ---- attention -> R3 (fp16), overlapping the async tile loads ----
    for (int n = wid; n < R; n += 16) {
        const float k0 = sKs[n * 3], k1 = sKs[n * 3 + 1], k2 = sKs[n * 3 + 2];
        float s[4];
        float mx = -3.0e38f;
#pragma unroll
        for (int it = 0; it < 4; it++) {
            const int m = it * 32 + lane;
            float v = -3.0e38f;
            if (m < R) v = k0 * sKs[m * 3] + k1 * sKs[m * 3 + 1] + k2 * sKs[m * 3 + 2];
            s[it] = v;
            mx = fmaxf(mx, v);
        }
#pragma unroll
        for (int o = 16; o; o >>= 1) mx = fmaxf(mx, __shfl_xor_sync(0xffffffffu, mx, o));
        float sum = 0.f, e[4];
#pragma unroll
        for (int it = 0; it < 4; it++) {
            const int m = it * 32 + lane;
            e[it] = (m < R) ? __expf(s[it] - mx) : 0.f;
            sum += e[it];
        }
        sum = wsum(sum);
        const float inv = 1.f / sum;
#pragma unroll
        for (int it = 0; it < 4; it++) {
            const int m = it * 32 + lane;
            if (m < R) hR3[n * SH + m] = __float2half_rn(e[it] * inv);
        }
    }
    CP_WAIT0();
    __syncthreads();    // all async copies complete

    // ---- fused Z apply + down-edge (layers 1..3) ----
    if (apply) {
        float w0[4], w1[4], w2[4];
#pragma unroll
        for (int d = 0; d < 4; d++) {
            const int e = 4 * lane + d;
            w1[d] = (e < 78) ? dew[e] : 0.f;
            w0[d] = (e < 39) ? dew[39 + e] : 0.f;
            w2[d] = (e >= 39 && e < 116) ? dew[e - 39] : 0.f;
        }
        const float debv = deb[0];
        __half* Zg = g_Zh + (size_t)b * RR;
        for (int r = wid; r < R; r += 16) {
            float4 v = make_float4(0.f, 0.f, 0.f, 0.f);
            if (lane < 29) {
                const uint2 zu = *(const uint2*)(hR1 + r * SH + 4 * lane);
                const uint2 uu = *(const uint2*)(hR4 + r * SH + 4 * lane);
                const float2 z01 = __half22float2(*(const __half2*)&zu.x);
                const float2 z23 = __half22float2(*(const __half2*)&zu.y);
                const float2 u01 = __half22float2(*(const __half2*)&uu.x);
                const float2 u23 = __half22float2(*(const __half2*)&uu.y);
                const float sc = g_scale[r], sf = g_shift[r];
                v.x = z01.x + fmaxf(fmaf(u01.x, sc, sf), 0.f);
                v.y = z01.y + fmaxf(fmaf(u01.y, sc, sf), 0.f);
                v.z = z23.x + fmaxf(fmaf(u23.x, sc, sf), 0.f);
                v.w = z23.y + fmaxf(fmaf(u23.y, sc, sf), 0.f);
                uint2 ou;
                *(__half2*)&ou.x = __floats2half2_rn(v.x, v.y);
                *(__half2*)&ou.y = __floats2half2_rn(v.z, v.w);
                *(uint2*)(hR1 + r * SH + 4 * lane) = ou;     // fp16 tile for GEMMs
                *(uint2*)(Zg + r * R + 4 * lane) = ou;       // carried state
            }
            float f0 = 0.f, f1 = 0.f, f2 = 0.f;
            const float vv[4] = {v.x, v.y, v.z, v.w};
#pragma unroll
            for (int d = 0; d < 4; d++) {
                f1 = fmaf(vv[d], w1[d], f1);
                f0 = fmaf(vv[d], w0[d], f0);
                f2 = fmaf(vv[d], w2[d], f2);
            }
            f0 = wsum(f0); f1 = wsum(f1); f2 = wsum(f2);
            if (lane == 0) {
                f0 = fmaxf(f0 + debv, 0.f);
                f1 = fmaxf(f1 + debv, 0.f);
                f2 = fmaxf(f2 + debv, 0.f);
                float* dst = g_XZ + (size_t)b * FEAT + offE + r * 3;
                dst[0] = f0; dst[1] = f1; dst[2] = f2;
                pS[r] = f0 + f1 + f2;
                pQ[r] = f0 * f0 + f1 * f1 + f2 * f2;
            }
        }
        // node dp fold (pA visible since sync #1)
        if (wid == 15) {
            float s = 0.f, q = 0.f;
            for (int n = lane; n < R; n += 32) {
                const float f = pA[n];
                s += f; q = fmaf(f, f, q);
            }
            s = wsum(s); q = wsum(q);
            if (lane == 0) { g_dpS[dpN + b] = s; g_dpQ[dpN + b] = q; }
        }
        __syncthreads();    // updated R1 + pS/pQ visible
        if (wid == 0) {
            float s = 0.f, q = 0.f;
            for (int r = lane; r < R; r += 32) { s += pS[r]; q += pQ[r]; }
            s = wsum(s); q = wsum(q);
            if (lane == 0) { g_dpS[dpE + b] = s; g_dpQ[dpE + b] = q; }
        }
    }

    float acc[2][4][4];
#pragma unroll
    for (int mt = 0; mt < 2; mt++)
#pragma unroll
        for (int nt = 0; nt < 4; nt++)
#pragma unroll
            for (int i = 0; i < 4; i++) acc[mt][nt][i] = 0.f;

    // ---- GEMM1: Mid1 = Z @ aw2^T  (R1 x R2 -> R4) ----
    mm_loop(hR1, hR2, acc, wm, wn, aOff, bOff);
    // store Mid1 + ab2 -> R4 (dead region; no sync needed before store)
#pragma unroll
    for (int mt = 0; mt < 2; mt++)
#pragma unroll
        for (int h = 0; h < 2; h++) {
            const int row = wm * 32 + mt * 16 + g + 8 * h;
#pragma unroll
            for (int nt = 0; nt < 4; nt++) {
                const int col = wn * 32 + nt * 8 + 2 * tig;
                if (col < 120)
                    *(__half2*)(hR4 + row * SH + col) =
                        __floats2half2_rn(acc[mt][nt][2 * h] + sb1[col],
                                          acc[mt][nt][2 * h + 1] + sb1[col + 1]);
            }
        }
#pragma unroll
    for (int mt = 0; mt < 2; mt++)
#pragma unroll
        for (int nt = 0; nt < 4; nt++)
#pragma unroll
            for (int i = 0; i < 4; i++) acc[mt][nt][i] = 0.f;
    __syncthreads();

    // ---- GEMM3: S2 = Mid1 @ att^T  (R4 x R3 -> R2) ----
    mm_loop(hR4, hR3, acc, wm, wn, aOff, bOff);
    // S2 -> R2 (aw2 dead) + node partials
#pragma unroll
    for (int mt = 0; mt < 2; mt++)
#pragma unroll
        for (int h = 0; h < 2; h++) {
            const int row = wm * 32 + mt * 16 + g + 8 * h;
            float a0 = 0.f, a1 = 0.f, a2 = 0.f;
#pragma unroll
            for (int nt = 0; nt < 4; nt++) {
                const int col = wn * 32 + nt * 8 + 2 * tig;
                const float v0 = acc[mt][nt][2 * h];
                const float v1 = acc[mt][nt][2 * h + 1];
                if (col < 120)
                    *(__half2*)(hR2 + row * SH + col) = __floats2half2_rn(v0, v1);
                if (row < R && col < R) {
                    a0 = fmaf(v0, sXs[col * 3 + 0], fmaf(v1, sXs[col * 3 + 3], a0));
                    a1 = fmaf(v0, sXs[col * 3 + 1], fmaf(v1, sXs[col * 3 + 4], a1));
                    a2 = fmaf(v0, sXs[col * 3 + 2], fmaf(v1, sXs[col * 3 + 5], a2));
                }
            }
            a0 += __shfl_xor_sync(0xffffffffu, a0, 1);
            a0 += __shfl_xor_sync(0xffffffffu, a0, 2);
            a1 += __shfl_xor_sync(0xffffffffu, a1, 1);
            a1 += __shfl_xor_sync(0xffffffffu, a1, 2);
            a2 += __shfl_xor_sync(0xffffffffu, a2, 1);
            a2 += __shfl_xor_sync(0xffffffffu, a2, 2);
            if (tig == 0) {
                pA[0 * 512 + wn * 128 + row] = a0;
                pA[1 * 512 + wn * 128 + row] = a1;
                pA[2 * 512 + wn * 128 + row] = a2;
            }
        }
#pragma unroll
    for (int mt = 0; mt < 2; mt++)
#pragma unroll
        for (int nt = 0; nt < 4; nt++)
#pragma unroll
            for (int i = 0; i < 4; i++) acc[mt][nt][i] = 0.f;
    __syncthreads();

    // ---- GEMM2: Et = ew @ Z^T  (R5 x R1 -> R3) ----
    mm_loop(hR5, hR1, acc, wm, wn, aOff, bOff);
    // Et -> R3 (att dead)
#pragma unroll
    for (int mt = 0; mt < 2; mt++)
#pragma unroll
        for (int h = 0; h < 2; h++) {
            const int row = wm * 32 + mt * 16 + g + 8 * h;
#pragma unroll
            for (int nt = 0; nt < 4; nt++) {
                const int col = wn * 32 + nt * 8 + 2 * tig;
                if (col < 120)
                    *(__half2*)(hR3 + row * SH + col) =
                        __floats2half2_rn(acc[mt][nt][2 * h], acc[mt][nt][2 * h + 1]);
            }
        }
#pragma unroll
    for (int mt = 0; mt < 2; mt++)
#pragma unroll
        for (int nt = 0; nt < 4; nt++)
#pragma unroll
            for (int i = 0; i < 4; i++) acc[mt][nt][i] = 0.f;
    __syncthreads();

    // ---- GEMM4: Z1 = S2 @ Et^T + eb  (R2 x R3 -> gmem) ----
    mm_loop(hR2, hR3, acc, wm, wn, aOff, bOff);

    // ---- epilogue: Z1 (fp16) + edge stats (fp32, pre-rounding) ----
    __half* Cb = g_Z1h + (size_t)b * RR;
#pragma unroll
    for (int mt = 0; mt < 2; mt++) {
#pragma unroll
        for (int h = 0; h < 2; h++) {
            const int row = wm * 32 + mt * 16 + g + 8 * h;
            float s = 0.f, q = 0.f;
#pragma unroll
            for (int nt = 0; nt < 4; nt++) {
                const int col = wn * 32 + nt * 8 + 2 * tig;
                if (col < R) {
                    const float v0 = acc[mt][nt][2 * h] + sb2[col];
                    const float v1 = acc[mt][nt][2 * h + 1] + sb2[col + 1];
                    if (row < R)
                        *(__half2*)(Cb + (size_t)row * R + col) =
                            __floats2half2_rn(v0, v1);
                    s += v0 + v1;
                    q += v0 * v0 + v1 * v1;
                }
            }
            s += __shfl_xor_sync(0xffffffffu, s, 1);
            s += __shfl_xor_sync(0xffffffffu, s, 2);
            q += __shfl_xor_sync(0xffffffffu, q, 1);
            q += __shfl_xor_sync(0xffffffffu, q, 2);
            if (tig == 0) { pS[wn * 128 + row] = s; pQ[wn * 128 + row] = q; }
        }
    }
    __syncthreads();
    if (tid < R) {
        const float s = pS[tid] + pS[128 + tid] + pS[256 + tid] + pS[384 + tid];
        const float q = pQ[tid] + pQ[128 + tid] + pQ[256 + tid] + pQ[384 + tid];
        g_ps[tid * NB + b] = s;
        g_pq[tid * NB + b] = q;
    }
    // ---- node path finish: X1 = (S2 @ X) @ nw^T + nb, node stats ----
    if (tid < R) {
        const int n = tid;
        const float a0 = pA[0 * 512 + n] + pA[0 * 512 + 128 + n] +
                         pA[0 * 512 + 256 + n] + pA[0 * 512 + 384 + n];
        const float a1 = pA[1 * 512 + n] + pA[1 * 512 + 128 + n] +
                         pA[1 * 512 + 256 + n] + pA[1 * 512 + 384 + n];
        const float a2 = pA[2 * 512 + n] + pA[2 * 512 + 128 + n] +
                         pA[2 * 512 + 256 + n] + pA[2 * 512 + 384 + n];
        float ps = 0.f, pq = 0.f;
        float* dst = g_X1 + (size_t)b * (R * 3) + n * 3;
#pragma unroll
        for (int o = 0; o < 3; o++) {
            const float v = fmaf(nw[o * 3 + 0], a0,
                            fmaf(nw[o * 3 + 1], a1,
                            fmaf(nw[o * 3 + 2], a2, nb_[o])));
            dst[o] = v;
            ps += v;
            pq = fmaf(v, v, pq);
        }
        g_psN[n * NB + b] = ps;
        g_pqN[n * NB + b] = pq;
    }
}

// ----------------------------------------------------------------------------
// Both BN channel reductions fused per channel. grid = R, block = 512.
// ----------------------------------------------------------------------------
__global__ void __launch_bounds__(512)
k_reduce_both(const float* __restrict__ geg, const float* __restrict__ geb,
              const float* __restrict__ gng, const float* __restrict__ gnb) {
    const int n = blockIdx.x;
    const int half = threadIdx.x >> 8;        // 0 = edge, 1 = node
    const int t = threadIdx.x & 255;
    const float* PS = half ? g_psN : g_ps;
    const float* PQ = half ? g_pqN : g_pq;
    float s = 0.f, q = 0.f;
#pragma unroll
    for (int it = 0; it < 2; it++) {
        const int b2 = it * 256 + t;
        const float2 vs = *(const float2*)(PS + n * NB + 2 * b2);
        const float2 vq = *(const float2*)(PQ + n * NB + 2 * b2);
        s += vs.x + vs.y;
        q += vq.x + vq.y;
    }
    __shared__ float shs[2][8], shq[2][8];
    s = wsum(s); q = wsum(q);
    const int w = t >> 5, lane = t & 31;
    if (lane == 0) { shs[half][w] = s; shq[half][w] = q; }
    __syncthreads();
    if (t == 0) {
        s = shs[half][0] + shs[half][1] + shs[half][2] + shs[half][3] +
            shs[half][4] + shs[half][5] + shs[half][6] + shs[half][7];
        q = shq[half][0] + shq[half][1] + shq[half][2] + shq[half][3] +
            shq[half][4] + shq[half][5] + shq[half][6] + shq[half][7];
        const float invcnt = half ? (1.f / (float)(3 * NB)) : (1.f / (float)(NB * R));
        const float mean = s * invcnt;
        const float var = q * invcnt - mean * mean;
        const float rstd = rsqrtf(var + EPS);
        const float gg = half ? gng[n] : geg[n];
        const float bb = half ? gnb[n] : geb[n];
        const float sc = rstd * gg;
        if (half) { g_scaleN[n] = sc; g_shiftN[n] = bb - mean * sc; }
        else      { g_scale[n] = sc;  g_shift[n] = bb - mean * sc; }
    }
}

// ----------------------------------------------------------------------------
// Standalone apply+down: only l=0 (pass-through + weight cvt tail) and l=4.
// grid = 29696 + 928 (+CVTB for l=0), block = 128.
// ----------------------------------------------------------------------------
__global__ void k_apply_down(const float* __restrict__ dew, const float* __restrict__ deb,
                             const float* __restrict__ dnw, const float* __restrict__ dnb,
                             const float* __restrict__ srcZ, const float* __restrict__ srcX,
                             const float* __restrict__ aw2f, const float* __restrict__ ewf,
                             int offE, int offN, int dpE, int dpN, int apply) {
    __shared__ float sh[8];
    if (blockIdx.x >= 30624) {
        // ---------------- weight conversion (layer 0 launch only) ----------------
        const int i = (blockIdx.x - 30624) * 256 + threadIdx.x * 2;
        const int N = LAYERS * RR;
        if (i < N) {
            g_wh[i] = __float2half_rn(aw2f[i]);
            if (i + 1 < N) g_wh[i + 1] = __float2half_rn(aw2f[i + 1]);
            else if (i + 1 < 2 * N) g_wh[i + 1] = __float2half_rn(ewf[i + 1 - N]);
        } else if (i < 2 * N) {
            g_wh[i] = __float2half_rn(ewf[i - N]);
            if (i + 1 < 2 * N) g_wh[i + 1] = __float2half_rn(ewf[i + 1 - N]);
        }
        return;
    }
    if (blockIdx.x < 29696) {
        // ---------------- edge ----------------
        const int wrp = threadIdx.x >> 5, lane = threadIdx.x & 31;
        const int rowid = blockIdx.x * 4 + wrp;
        const int b = rowid / R, n = rowid - b * R;
        float w0[4], w1[4], w2[4];
#pragma unroll
        for (int d = 0; d < 4; d++) {
            const int e = 4 * lane + d;
            w1[d] = (e < 78) ? dew[e] : 0.f;
            w0[d] = (e < 39) ? dew[39 + e] : 0.f;
            w2[d] = (e >= 39 && e < 116) ? dew[e - 39] : 0.f;
        }
        float4 v = make_float4(0.f, 0.f, 0.f, 0.f);
        __half2* zrow = (__half2*)(g_Zh + (size_t)rowid * R);
        if (lane < 29) {
            if (apply) {
                const uint2 zu = *(const uint2*)(zrow + 2 * lane);
                const uint2 uu = *(const uint2*)((const __half2*)(g_Z1h + (size_t)rowid * R) + 2 * lane);
                const float2 z01 = __half22float2(*(const __half2*)&zu.x);
                const float2 z23 = __half22float2(*(const __half2*)&zu.y);
                const float2 u01 = __half22float2(*(const __half2*)&uu.x);
                const float2 u23 = __half22float2(*(const __half2*)&uu.y);
                const float sc = g_scale[n], sf = g_shift[n];
                v.x = z01.x + fmaxf(fmaf(u01.x, sc, sf), 0.f);
                v.y = z01.y + fmaxf(fmaf(u01.y, sc, sf), 0.f);
                v.z = z23.x + fmaxf(fmaf(u23.x, sc, sf), 0.f);
                v.w = z23.y + fmaxf(fmaf(u23.y, sc, sf), 0.f);
                uint2 ou;
                *(__half2*)&ou.x = __floats2half2_rn(v.x, v.y);
                *(__half2*)&ou.y = __floats2half2_rn(v.z, v.w);
                *(uint2*)(zrow + 2 * lane) = ou;
            } else {
                v = *(const float4*)(srcZ + (size_t)rowid * R + 4 * lane);
                uint2 ou;
                *(__half2*)&ou.x = __floats2half2_rn(v.x, v.y);
                *(__half2*)&ou.y = __floats2half2_rn(v.z, v.w);
                *(uint2*)(zrow + 2 * lane) = ou;
            }
        }
        float f0 = 0.f, f1 = 0.f, f2 = 0.f;
        const float vv[4] = {v.x, v.y, v.z, v.w};
#pragma unroll
        for (int d = 0; d < 4; d++) {
            f1 = fmaf(vv[d], w1[d], f1);
            f0 = fmaf(vv[d], w0[d], f0);
            f2 = fmaf(vv[d], w2[d], f2);
        }
        f0 = wsum(f0); f1 = wsum(f1); f2 = wsum(f2);
        float s = 0.f, q = 0.f;
        if (lane == 0) {
            const float bb = deb[0];
            f0 = fmaxf(f0 + bb, 0.f);
            f1 = fmaxf(f1 + bb, 0.f);
            f2 = fmaxf(f2 + bb, 0.f);
            float* dst = g_XZ + (size_t)b * FEAT + offE + n * 3;
            dst[0] = f0; dst[1] = f1; dst[2] = f2;
            s = f0 + f1 + f2;
            q = f0 * f0 + f1 * f1 + f2 * f2;
            sh[wrp] = s; sh[4 + wrp] = q;
        }
        __syncthreads();
        if (threadIdx.x == 0) {
            g_dpS[dpE + blockIdx.x] = sh[0] + sh[1] + sh[2] + sh[3];
            g_dpQ[dpE + blockIdx.x] = sh[4] + sh[5] + sh[6] + sh[7];
        }
    } else {
        // ---------------- node ----------------
        const int bid = blockIdx.x - 29696;
        const int idx = bid * 128 + threadIdx.x;
        float* xp = g_X + (size_t)idx * 3;
        float x0, x1, x2;
        if (apply) {
            x0 = xp[0]; x1 = xp[1]; x2 = xp[2];
            const int n = idx % R;
            const float sc = g_scaleN[n], sf = g_shiftN[n];
            const float* up = g_X1 + (size_t)idx * 3;
            x0 += fmaxf(fmaf(up[0], sc, sf), 0.f);
            x1 += fmaxf(fmaf(up[1], sc, sf), 0.f);
            x2 += fmaxf(fmaf(up[2], sc, sf), 0.f);
            xp[0] = x0; xp[1] = x1; xp[2] = x2;
        } else {
            const float* sp = srcX + (size_t)idx * 3;
            x0 = sp[0]; x1 = sp[1]; x2 = sp[2];
            xp[0] = x0; xp[1] = x1; xp[2] = x2;
        }
        const float f = fmaxf(fmaf(x0, dnw[0], fmaf(x1, dnw[1], fmaf(x2, dnw[2], dnb[0]))), 0.f);
        const int b = idx / R, r = idx - (idx / R) * R;
        g_XZ[(size_t)b * FEAT + offN + r] = f;
        const float s = wsum(f);
        const float q = wsum(f * f);
        const int wr = threadIdx.x >> 5, lane = threadIdx.x & 31;
        if (lane == 0) { sh[wr] = s; sh[4 + wr] = q; }
        __syncthreads();
        if (threadIdx.x == 0) {
            g_dpS[dpN + bid] = sh[0] + sh[1] + sh[2] + sh[3];
            g_dpQ[dpN + bid] = sh[4] + sh[5] + sh[6] + sh[7];
        }
    }
}

// ----------------------------------------------------------------------------
// All 10 down-sample reductions at once. grid = 10, block = 1024.
// sgm 0..4 node l, 5..9 edge l-5.
// ----------------------------------------------------------------------------
__global__ void k_dreduce_all(const float* __restrict__ dng, const float* __restrict__ dnbe,
                              const float* __restrict__ deg, const float* __restrict__ debe) {
    const int sgm = blockIdx.x;
    const bool node = sgm < 5;
    const int l = node ? sgm : sgm - 5;
    int base, cnt;
    if (node) {
        if (l == 0)      { base = DP_N0; cnt = 928; }
        else if (l == 4) { base = DP_N4; cnt = 928; }
        else             { base = DP_NF + (l - 1) * 1024; cnt = 1024; }
    } else {
        if (l == 0)      { base = DP_E0; cnt = 29696; }
        else if (l == 4) { base = DP_E4; cnt = 29696; }
        else             { base = DP_EF + (l - 1) * 1024; cnt = 1024; }
    }
    const float invcnt = node ? (1.f / (float)(NB * R)) : (1.f / (float)(NB * R * 3));
    float s = 0.f, q = 0.f;
    for (int i = threadIdx.x; i < cnt; i += 1024) {
        s += g_dpS[base + i];
        q += g_dpQ[base + i];
    }
    __shared__ float shs[32], shq[32];
    s = wsum(s); q = wsum(q);
    const int w = threadIdx.x >> 5, lane = threadIdx.x & 31;
    if (lane == 0) { shs[w] = s; shq[w] = q; }
    __syncthreads();
    if (w == 0) {
        s = shs[lane]; q = shq[lane];
        s = wsum(s); q = wsum(q);
        if (lane == 0) {
            const float mean = s * invcnt;
            const float var = q * invcnt - mean * mean;
            const float rstd = rsqrtf(var + EPS);
            const float gg = node ? dng[l] : deg[l];
            const float bb = node ? dnbe[l] : debe[l];
            const float sc = rstd * gg;
            g_dssArr[2 * sgm]     = sc;
            g_dssArr[2 * sgm + 1] = bb - mean * sc;
        }
    }
}

// ----------------------------------------------------------------------------
// Classifier GEMM (fp16) + fused out-projection partials.
// ----------------------------------------------------------------------------
#define CSTR 24

__global__ void __launch_bounds__(256)
k_cls(const float* __restrict__ A, const float* __restrict__ Bm,
      const float* __restrict__ bias, const float* __restrict__ cw2)
{
    __shared__ __half sA[2][128 * CSTR];
    __shared__ __half sB[2][64 * CSTR];
    __shared__ float sbc[64];
    __shared__ float sc2[2][64];
    __shared__ float pOut[128][4];
    const int tid = threadIdx.x;
    const int wid = tid >> 5, lane = tid & 31;
    const int wm = wid >> 1, wn = wid & 1;
    const int g = lane >> 2, tig = lane & 3;
    const int row0 = blockIdx.y * 128, col0 = blockIdx.x * 64;

    if (tid < 64) {
        sbc[tid] = bias[col0 + tid];
        sc2[0][tid] = cw2[col0 + tid];
        sc2[1][tid] = cw2[HID + col0 + tid];
    }

    float4 pa0, pa1, pb;
    float fsc, fsh;
    const int ar0 = tid >> 2, ac0 = (tid & 3) << 2;
    const int ar1 = (tid + 256) >> 2, ac1 = ac0;
    const int br = tid >> 2, bc = (tid & 3) << 2;

    auto fetch = [&](int k0) {
        const int k = k0 + ac0;
        const int sgm = (k < 580) ? (k / 116) : (5 + (k - 580) / 348);
        fsc = g_dssArr[2 * sgm];
        fsh = g_dssArr[2 * sgm + 1];
        pa0 = *(const float4*)(A + (size_t)(row0 + ar0) * FEAT + k0 + ac0);
        pa1 = *(const float4*)(A + (size_t)(row0 + ar1) * FEAT + k0 + ac1);
        pb  = *(const float4*)(Bm + (size_t)(col0 + br) * FEAT + k0 + bc);
    };
    auto store = [&](int buf) {
        __half2* d0 = (__half2*)&sA[buf][ar0 * CSTR + ac0];
        d0[0] = __floats2half2_rn(fmaf(pa0.x, fsc, fsh), fmaf(pa0.y, fsc, fsh));
        d0[1] = __floats2half2_rn(fmaf(pa0.z, fsc, fsh), fmaf(pa0.w, fsc, fsh));
        __half2* d1 = (__half2*)&sA[buf][ar1 * CSTR + ac1];
        d1[0] = __floats2half2_rn(fmaf(pa1.x, fsc, fsh), fmaf(pa1.y, fsc, fsh));
        d1[1] = __floats2half2_rn(fmaf(pa1.z, fsc, fsh), fmaf(pa1.w, fsc, fsh));
        __half2* d2 = (__half2*)&sB[buf][br * CSTR + bc];
        d2[0] = __floats2half2_rn(pb.x, pb.y);
        d2[1] = __floats2half2_rn(pb.z, pb.w);
    };

    float acc[2][4][4];
#pragma unroll
    for (int mt = 0; mt < 2; mt++)
#pragma unroll
        for (int nt = 0; nt < 4; nt++)
#pragma unroll
            for (int i = 0; i < 4; i++) acc[mt][nt][i] = 0.f;

    const int NS = FEAT / 16;   // 145
    fetch(0);
    store(0);
    __syncthreads();
    int buf = 0;
    for (int ks = 0; ks < NS; ks++) {
        if (ks + 1 < NS) fetch((ks + 1) * 16);
        uint32_t af[2][4], bf[4][2];
#pragma unroll
        for (int mt = 0; mt < 2; mt++) {
            const __half* p0 = &sA[buf][(wm * 32 + mt * 16 + g) * CSTR + 2 * tig];
            af[mt][0] = *(const uint32_t*)(p0);
            af[mt][1] = *(const uint32_t*)(p0 + 8 * CSTR);
            af[mt][2] = *(const uint32_t*)(p0 + 8);
            af[mt][3] = *(const uint32_t*)(p0 + 8 * CSTR + 8);
        }
#pragma unroll
        for (int nt = 0; nt < 4; nt++) {
            const __half* q0 = &sB[buf][(wn * 32 + nt * 8 + g) * CSTR + 2 * tig];
            bf[nt][0] = *(const uint32_t*)(q0);
            bf[nt][1] = *(const uint32_t*)(q0 + 8);
        }
#pragma unroll
        for (int mt = 0; mt < 2; mt++)
#pragma unroll
            for (int nt = 0; nt < 4; nt++)
                mma16(acc[mt][nt], af[mt], bf[nt]);
        if (ks + 1 < NS) store(buf ^ 1);
        __syncthreads();
        buf ^= 1;
    }

    // fused epilogue: relu + dot with cw2 slice -> per-row partials
#pragma unroll
    for (int mt = 0; mt < 2; mt++)
#pragma unroll
        for (int h = 0; h < 2; h++) {
            const int rl = wm * 32 + mt * 16 + g + 8 * h;
            float p0 = 0.f, p1 = 0.f;
#pragma unroll
            for (int nt = 0; nt < 4; nt++) {
                const int col = wn * 32 + nt * 8 + 2 * tig;
                const float v0 = fmaxf(acc[mt][nt][2 * h] + sbc[col], 0.f);
                const float v1 = fmaxf(acc[mt][nt][2 * h + 1] + sbc[col + 1], 0.f);
                p0 = fmaf(v0, sc2[0][col], fmaf(v1, sc2[0][col + 1], p0));
                p1 = fmaf(v0, sc2[1][col], fmaf(v1, sc2[1][col + 1], p1));
            }
            p0 += __shfl_xor_sync(0xffffffffu, p0, 1);
            p0 += __shfl_xor_sync(0xffffffffu, p0, 2);
            p1 += __shfl_xor_sync(0xffffffffu, p1, 1);
            p1 += __shfl_xor_sync(0xffffffffu, p1, 2);
            if (tig == 0) {
                pOut[rl][wn * 2 + 0] = p0;
                pOut[rl][wn * 2 + 1] = p1;
            }
        }
    __syncthreads();
    if (tid < 128) {
        g_Hp[(size_t)(row0 + tid) * 32 + blockIdx.x * 2 + 0] = pOut[tid][0] + pOut[tid][2];
        g_Hp[(size_t)(row0 + tid) * 32 + blockIdx.x * 2 + 1] = pOut[tid][1] + pOut[tid][3];
    }
}

// Final fold: out[b][c] = sum_k g_Hp[b][2k+c] + cb2[c]. grid = 4, block = 256.
__global__ void k_out2(const float* __restrict__ cb2, float* __restrict__ out) {
    const int b = blockIdx.x * 256 + threadIdx.x;
    const float* p = g_Hp + (size_t)b * 32;
    float a0 = 0.f, a1 = 0.f;
#pragma unroll
    for (int k = 0; k < 16; k++) {
        a0 += p[2 * k];
        a1 += p[2 * k + 1];
    }
    out[b * 2 + 0] = a0 + cb2[0];
    out[b * 2 + 1] = a1 + cb2[1];
}

// ----------------------------------------------------------------------------
// Host orchestration (graph-capturable: kernel launches only)
// ----------------------------------------------------------------------------
extern "C" void kernel_launch(void* const* d_in, const int* in_sizes, int n_in,
                              void* d_out, int out_size) {
    const float* X_in  = (const float*)d_in[0];
    const float* Z_in  = (const float*)d_in[1];
    const float* aw1   = (const float*)d_in[2];
    const float* ab1   = (const float*)d_in[3];
    const float* aw2   = (const float*)d_in[4];
    const float* ab2   = (const float*)d_in[5];
    const float* nw    = (const float*)d_in[6];
    const float* nb    = (const float*)d_in[7];
    const float* ew    = (const float*)d_in[8];
    const float* eb    = (const float*)d_in[9];
    const float* gn_g  = (const float*)d_in[10];
    const float* gn_b  = (const float*)d_in[11];
    const float* ge_g  = (const float*)d_in[12];
    const float* ge_b  = (const float*)d_in[13];
    const float* dn_w  = (const float*)d_in[14];
    const float* dn_b  = (const float*)d_in[15];
    const float* dn_g  = (const float*)d_in[16];
    const float* dn_be = (const float*)d_in[17];
    const float* de_w  = (const float*)d_in[18];
    const float* de_b  = (const float*)d_in[19];
    const float* de_g  = (const float*)d_in[20];
    const float* de_be = (const float*)d_in[21];
    const float* cw1   = (const float*)d_in[22];
    const float* cb1   = (const float*)d_in[23];
    const float* cw2   = (const float*)d_in[24];
    const float* cb2   = (const float*)d_in[25];
    float* out = (float*)d_out;

    cudaFuncSetAttribute(k_layer, cudaFuncAttributeMaxDynamicSharedMemorySize, SM_TOTB);

    float* pXZ;
    __half* pWh;
    cudaGetSymbolAddress((void**)&pXZ, g_XZ);
    cudaGetSymbolAddress((void**)&pWh, g_wh);

    // layer-0 down-sample + input pass-through + fused weight fp16 conversion
    k_apply_down<<<29696 + 928 + CVTB, 128>>>(de_w, de_b, dn_w, dn_b,
                                              Z_in, X_in, aw2, ew,
                                              580, 0, DP_E0, DP_N0, 0);

    for (int i = 0; i < LAYERS; i++) {
        const int ap = (i > 0) ? 1 : 0;
        const int dpE = ap ? (DP_EF + (i - 1) * 1024) : 0;
        const int dpN = ap ? (DP_NF + (i - 1) * 1024) : 0;
        k_layer<<<NB, LT, SM_TOTB>>>(pWh + (size_t)i * RR, ab2 + i * R,
                                     aw1 + 9 * i, ab1 + 3 * i,
                                     pWh + (size_t)(LAYERS + i) * RR, eb + i * R,
                                     nw + 9 * i, nb + 3 * i,
                                     de_w + 78 * i, de_b + i,
                                     dn_w + 3 * i, dn_b + i,
                                     580 + i * 348, i * R, dpE, dpN, ap);
        k_reduce_both<<<R, 512>>>(ge_g + i * R, ge_b + i * R,
                                  gn_g + i * R, gn_b + i * R);
    }

    // final apply + down-sample for l = 4
    k_apply_down<<<29696 + 928, 128>>>(de_w + 78 * 4, de_b + 4,
                                       dn_w + 3 * 4, dn_b + 4,
                                       nullptr, nullptr, nullptr, nullptr,
                                       580 + 4 * 348, 4 * R, DP_E4, DP_N4, 1);

    k_dreduce_all<<<10, 1024>>>(dn_g, dn_be, de_g, de_be);
    k_cls<<<dim3(HID / 64, NB / 128), 256>>>(pXZ, cw1, cb1, cw2);
    k_out2<<<NB / 256, 256>>>(cb2, out);
}